// round 1
// baseline (speedup 1.0000x reference)
#include <cuda_runtime.h>
#include <math.h>
#include <stdint.h>
#include <stdio.h>

#define BB 4
#define TT 1024
#define EE 1024
#define HH 16
#define FFDIM 64
#define LN_N ((size_t)TT * EE)

// ---------------- scratch (static device globals; no allocation) -------------
__device__ float g_wq[EE * EE];
__device__ float g_wk[EE * EE];
__device__ float g_wv[EE * EE];
__device__ float g_wff[EE * EE];
__device__ float g_q[BB * TT * EE];   // layout [B, T, H*F]
__device__ float g_k[BB * TT * EE];
__device__ float g_v[BB * TT * EE];
__device__ float g_s[(size_t)BB * HH * TT * TT];  // 256 MB scores/attn
__device__ float g_zm[BB * TT * EE];  // merged-head attention out
__device__ float g_zf[BB * TT * EE];  // after fr reduction
__device__ float g_z1[BB * TT * EE];
__device__ float g_z2[BB * TT * EE];
__device__ double g_part[BB * 64 * 2];
__device__ float g_stats[BB * 2];

// ---------------- weight repacks --------------------------------------------
// q_w[h,e,f] -> W[e, h*F+f] so projection is a plain NN GEMM
__global__ void repack_qkv(const float* __restrict__ qw,
                           const float* __restrict__ kw,
                           const float* __restrict__ vw) {
    int idx = blockIdx.x * blockDim.x + threadIdx.x;
    if (idx >= EE * EE) return;
    int e = idx / EE, n = idx % EE;
    int h = n >> 6, f = n & 63;
    int src = h * (EE * FFDIM) + e * FFDIM + f;
    g_wq[idx] = qw[src];
    g_wk[idx] = kw[src];
    g_wv[idx] = vw[src];
}

// ff_w[d,e] -> W[e,d]
__global__ void repack_ff(const float* __restrict__ w) {
    int idx = blockIdx.x * blockDim.x + threadIdx.x;
    if (idx >= EE * EE) return;
    int e = idx / EE, d = idx % EE;
    g_wff[idx] = w[d * EE + e];
}

// ---------------- generic NN GEMM: C = A(MxK) * B(KxN) ----------------------
// BM=BN=64, BK=16, 256 threads, 4x4 per thread. Optional batch via grid.z.
template <bool RELU>
__global__ __launch_bounds__(256) void gemm_nn(
    const float* __restrict__ A, const float* __restrict__ Bm,
    float* __restrict__ C, int M, int N, int K,
    long sA, long sB, long sC, const float* __restrict__ bias) {
    __shared__ float As[16][64];
    __shared__ float Bs[16][68];
    A += (size_t)blockIdx.z * sA;
    Bm += (size_t)blockIdx.z * sB;
    C += (size_t)blockIdx.z * sC;
    int m0 = blockIdx.y * 64, n0 = blockIdx.x * 64;
    int tid = threadIdx.x;
    int ty = tid >> 4, tx = tid & 15;
    float acc[4][4] = {};
    for (int k0 = 0; k0 < K; k0 += 16) {
#pragma unroll
        for (int i = 0; i < 4; i++) {
            int idx = tid + i * 256;
            int r = idx >> 4, c = idx & 15;
            As[c][r] = A[(size_t)(m0 + r) * K + k0 + c];
        }
#pragma unroll
        for (int i = 0; i < 4; i++) {
            int idx = tid + i * 256;
            int kr = idx >> 6, c = idx & 63;
            Bs[kr][c] = Bm[(size_t)(k0 + kr) * N + n0 + c];
        }
        __syncthreads();
#pragma unroll
        for (int k = 0; k < 16; k++) {
            float a[4], b[4];
#pragma unroll
            for (int i = 0; i < 4; i++) a[i] = As[k][ty * 4 + i];
#pragma unroll
            for (int j = 0; j < 4; j++) b[j] = Bs[k][tx * 4 + j];
#pragma unroll
            for (int i = 0; i < 4; i++)
#pragma unroll
                for (int j = 0; j < 4; j++) acc[i][j] += a[i] * b[j];
        }
        __syncthreads();
    }
#pragma unroll
    for (int i = 0; i < 4; i++) {
        int m = m0 + ty * 4 + i;
#pragma unroll
        for (int j = 0; j < 4; j++) {
            int n = n0 + tx * 4 + j;
            float v = acc[i][j];
            if (bias) v += bias[n];
            if (RELU) v = fmaxf(v, 0.0f);
            C[(size_t)m * N + n] = v;
        }
    }
}

// ---------------- attention: scores = (q k^T) * mask / 8 --------------------
// grid (T/64 key tiles, T/64 query tiles, B*H); block 256
__global__ __launch_bounds__(256) void attn_scores() {
    int bh = blockIdx.z;
    int b = bh / HH, h = bh % HH;
    int q0 = blockIdx.y * 64, k0 = blockIdx.x * 64;
    __shared__ float qs[64][65];
    __shared__ float ks[64][65];
    int tid = threadIdx.x;
    const float* qp = g_q + (size_t)b * TT * EE + h * FFDIM;
    const float* kp = g_k + (size_t)b * TT * EE + h * FFDIM;
#pragma unroll
    for (int i = 0; i < 16; i++) {
        int idx = tid + i * 256;
        int r = idx >> 6, c = idx & 63;
        qs[r][c] = qp[(size_t)(q0 + r) * EE + c];
        ks[r][c] = kp[(size_t)(k0 + r) * EE + c];
    }
    __syncthreads();
    int ty = tid >> 4, tx = tid & 15;
    float acc[4][4] = {};
#pragma unroll 8
    for (int f = 0; f < 64; f++) {
        float a[4], bv[4];
#pragma unroll
        for (int i = 0; i < 4; i++) a[i] = qs[ty * 4 + i][f];
#pragma unroll
        for (int j = 0; j < 4; j++) bv[j] = ks[tx * 4 + j][f];
#pragma unroll
        for (int i = 0; i < 4; i++)
#pragma unroll
            for (int j = 0; j < 4; j++) acc[i][j] += a[i] * bv[j];
    }
    float* sp = g_s + (size_t)bh * TT * TT;
#pragma unroll
    for (int i = 0; i < 4; i++) {
        int qg = q0 + ty * 4 + i;
#pragma unroll
        for (int j = 0; j < 4; j++) {
            int kg = k0 + tx * 4 + j;
            // multiplicative mask, faithful to reference: 1 on lower+diag,
            // (1 - 1e9) on strict upper; then /sqrt(F)=*0.125
            float m = (kg > qg) ? (1.0f - 1.0e9f) : 1.0f;
            sp[(size_t)qg * TT + kg] = acc[i][j] * m * 0.125f;
        }
    }
}

// ---------------- softmax over last dim (rows of 1024), in place ------------
__global__ __launch_bounds__(256) void softmax_rows() {
    size_t row = blockIdx.x;
    float* p = g_s + row * TT;
    int tid = threadIdx.x;
    float v[4];
    float mx = -INFINITY;
#pragma unroll
    for (int i = 0; i < 4; i++) {
        v[i] = p[tid + i * 256];
        mx = fmaxf(mx, v[i]);
    }
    __shared__ float sm[8];
#pragma unroll
    for (int o = 16; o > 0; o >>= 1) mx = fmaxf(mx, __shfl_xor_sync(0xffffffffu, mx, o));
    if ((tid & 31) == 0) sm[tid >> 5] = mx;
    __syncthreads();
    if (tid < 8) {
        float m2 = sm[tid];
#pragma unroll
        for (int o = 4; o > 0; o >>= 1) m2 = fmaxf(m2, __shfl_xor_sync(0xffu, m2, o));
        sm[tid] = m2;
    }
    __syncthreads();
    mx = sm[0];
    float s = 0.0f;
#pragma unroll
    for (int i = 0; i < 4; i++) {
        v[i] = __expf(v[i] - mx);
        s += v[i];
    }
    __shared__ float ss[8];
#pragma unroll
    for (int o = 16; o > 0; o >>= 1) s += __shfl_xor_sync(0xffffffffu, s, o);
    if ((tid & 31) == 0) ss[tid >> 5] = s;
    __syncthreads();
    if (tid < 8) {
        float s2 = ss[tid];
#pragma unroll
        for (int o = 4; o > 0; o >>= 1) s2 += __shfl_xor_sync(0xffu, s2, o);
        ss[tid] = s2;
    }
    __syncthreads();
    float inv = 1.0f / ss[0];
#pragma unroll
    for (int i = 0; i < 4; i++) p[tid + i * 256] = v[i] * inv;
}

// ---------------- z = attn(TxT) * v(TxF), write merged heads ----------------
// grid (T/64 query tiles, B*H)
__global__ __launch_bounds__(256) void attn_av() {
    int bh = blockIdx.y;
    int b = bh / HH, h = bh % HH;
    int q0 = blockIdx.x * 64;
    const float* sp = g_s + (size_t)bh * TT * TT;
    const float* vp = g_v + (size_t)b * TT * EE + h * FFDIM;
    float* op = g_zm + (size_t)b * TT * EE + h * FFDIM;
    __shared__ float As[64][33];
    __shared__ float Bs[32][68];
    int tid = threadIdx.x;
    int ty = tid >> 4, tx = tid & 15;
    float acc[4][4] = {};
    for (int k0 = 0; k0 < TT; k0 += 32) {
#pragma unroll
        for (int i = 0; i < 8; i++) {
            int idx = tid + i * 256;
            int r = idx >> 5, c = idx & 31;
            As[r][c] = sp[(size_t)(q0 + r) * TT + k0 + c];
        }
#pragma unroll
        for (int i = 0; i < 8; i++) {
            int idx = tid + i * 256;
            int kr = idx >> 6, c = idx & 63;
            Bs[kr][c] = vp[(size_t)(k0 + kr) * EE + c];
        }
        __syncthreads();
#pragma unroll 8
        for (int k = 0; k < 32; k++) {
            float a[4], bv[4];
#pragma unroll
            for (int i = 0; i < 4; i++) a[i] = As[ty * 4 + i][k];
#pragma unroll
            for (int j = 0; j < 4; j++) bv[j] = Bs[k][tx * 4 + j];
#pragma unroll
            for (int i = 0; i < 4; i++)
#pragma unroll
                for (int j = 0; j < 4; j++) acc[i][j] += a[i] * bv[j];
        }
        __syncthreads();
    }
#pragma unroll
    for (int i = 0; i < 4; i++)
#pragma unroll
        for (int j = 0; j < 4; j++)
            op[(size_t)(q0 + ty * 4 + i) * EE + tx * 4 + j] = acc[i][j];
}

// ---------------- LayerNorm over whole [T,E] plane per batch ----------------
__global__ __launch_bounds__(256) void ln_reduce(const float* __restrict__ in1,
                                                 const float* __restrict__ in2) {
    int b = blockIdx.y;
    const float* p1 = in1 + (size_t)b * LN_N;
    const float* p2 = in2 + (size_t)b * LN_N;
    const int chunk = (int)(LN_N / 64);
    size_t base = (size_t)blockIdx.x * chunk;
    double s = 0.0, sq = 0.0;
    for (int i = threadIdx.x; i < chunk; i += 256) {
        float x = p1[base + i] + p2[base + i];
        s += x;
        sq += (double)x * x;
    }
    __shared__ double sh[256], shq[256];
    int tid = threadIdx.x;
    sh[tid] = s;
    shq[tid] = sq;
    __syncthreads();
    for (int o = 128; o > 0; o >>= 1) {
        if (tid < o) {
            sh[tid] += sh[tid + o];
            shq[tid] += shq[tid + o];
        }
        __syncthreads();
    }
    if (tid == 0) {
        g_part[(b * 64 + blockIdx.x) * 2] = sh[0];
        g_part[(b * 64 + blockIdx.x) * 2 + 1] = shq[0];
    }
}

__global__ void ln_finalize() {
    int b = blockIdx.x;
    int tid = threadIdx.x;  // 64
    __shared__ double sh[64], shq[64];
    sh[tid] = g_part[(b * 64 + tid) * 2];
    shq[tid] = g_part[(b * 64 + tid) * 2 + 1];
    __syncthreads();
    for (int o = 32; o > 0; o >>= 1) {
        if (tid < o) {
            sh[tid] += sh[tid + o];
            shq[tid] += shq[tid + o];
        }
        __syncthreads();
    }
    if (tid == 0) {
        double n = (double)LN_N;
        double mean = sh[0] / n;
        double var = shq[0] / n - mean * mean;
        g_stats[b * 2] = (float)mean;
        g_stats[b * 2 + 1] = (float)(1.0 / sqrt(var + 1e-5));
    }
}

__global__ __launch_bounds__(256) void ln_norm(const float* __restrict__ in1,
                                               const float* __restrict__ in2,
                                               const float* __restrict__ w,
                                               const float* __restrict__ bia,
                                               float* __restrict__ out) {
    size_t i = (size_t)blockIdx.x * blockDim.x + threadIdx.x;
    if (i >= (size_t)BB * LN_N) return;
    int b = (int)(i / LN_N);
    size_t te = i % LN_N;
    float mean = g_stats[b * 2];
    float rstd = g_stats[b * 2 + 1];
    float x = in1[i] + in2[i];
    out[i] = (x - mean) * rstd * w[te] + bia[te];
}

// ---------------- launch ----------------------------------------------------
extern "C" void kernel_launch(void* const* d_in, const int* in_sizes, int n_in,
                              void* d_out, int out_size) {
    const float* x = (const float*)d_in[0];
    const float* q_w = (const float*)d_in[1];
    const float* k_w = (const float*)d_in[2];
    const float* v_w = (const float*)d_in[3];
    const float* fr_w = (const float*)d_in[4];
    const float* ff_w = (const float*)d_in[5];
    const float* ff_b = (const float*)d_in[6];
    const float* ln1_w = (const float*)d_in[7];
    const float* ln1_b = (const float*)d_in[8];
    const float* ln2_w = (const float*)d_in[9];
    const float* ln2_b = (const float*)d_in[10];
    float* out = (float*)d_out;

    float *p_wq, *p_wk, *p_wv, *p_wff, *p_q, *p_k, *p_v;
    float *p_zm, *p_zf, *p_z1, *p_z2;
    cudaGetSymbolAddress((void**)&p_wq, g_wq);
    cudaGetSymbolAddress((void**)&p_wk, g_wk);
    cudaGetSymbolAddress((void**)&p_wv, g_wv);
    cudaGetSymbolAddress((void**)&p_wff, g_wff);
    cudaGetSymbolAddress((void**)&p_q, g_q);
    cudaGetSymbolAddress((void**)&p_k, g_k);
    cudaGetSymbolAddress((void**)&p_v, g_v);
    cudaGetSymbolAddress((void**)&p_zm, g_zm);
    cudaGetSymbolAddress((void**)&p_zf, g_zf);
    cudaGetSymbolAddress((void**)&p_z1, g_z1);
    cudaGetSymbolAddress((void**)&p_z2, g_z2);

    // 1) repack weights
    repack_qkv<<<(EE * EE + 255) / 256, 256>>>(q_w, k_w, v_w);
    repack_ff<<<(EE * EE + 255) / 256, 256>>>(ff_w);

    // 2) QKV projections: [4096,1024] x [1024,1024]
    dim3 gproj(EE / 64, (BB * TT) / 64, 1);
    gemm_nn<false><<<gproj, 256>>>(x, p_wq, p_q, BB * TT, EE, EE, 0, 0, 0, nullptr);
    gemm_nn<false><<<gproj, 256>>>(x, p_wk, p_k, BB * TT, EE, EE, 0, 0, 0, nullptr);
    gemm_nn<false><<<gproj, 256>>>(x, p_wv, p_v, BB * TT, EE, EE, 0, 0, 0, nullptr);

    // 3) attention
    dim3 gsc(TT / 64, TT / 64, BB * HH);
    attn_scores<<<gsc, 256>>>();
    softmax_rows<<<BB * HH * TT, 256>>>();
    dim3 gav(TT / 64, BB * HH, 1);
    attn_av<<<gav, 256>>>();

    // 4) per-batch feature reduction: zf[b] = zm[b] @ fr_w[b]
    dim3 gfr(EE / 64, TT / 64, BB);
    gemm_nn<false><<<gfr, 256>>>(p_zm, fr_w, p_zf, TT, EE, EE,
                                 (long)TT * EE, (long)EE * EE, (long)TT * EE, nullptr);

    // 5) LN1 over x + zf -> z1
    dim3 gred(64, BB, 1);
    ln_reduce<<<gred, 256>>>(x, p_zf);
    ln_finalize<<<BB, 64>>>();
    size_t total = (size_t)BB * LN_N;
    ln_norm<<<(unsigned)((total + 255) / 256), 256>>>(x, p_zf, ln1_w, ln1_b, p_z1);

    // 6) FFN: z2 = relu(z1 @ ff_w^T + ff_b)
    gemm_nn<true><<<gproj, 256>>>(p_z1, p_wff, p_z2, BB * TT, EE, EE, 0, 0, 0, ff_b);

    // 7) LN2 over z1 + z2 -> out
    ln_reduce<<<gred, 256>>>(p_z1, p_z2);
    ln_finalize<<<BB, 64>>>();
    ln_norm<<<(unsigned)((total + 255) / 256), 256>>>(p_z1, p_z2, ln2_w, ln2_b, out);
}

// round 4
// speedup vs baseline: 1.5476x; 1.5476x over previous
#include <cuda_runtime.h>
#include <math.h>
#include <stdint.h>

#define BB 4
#define TT 1024
#define EE 1024
#define HH 16
#define FFDIM 64
#define LN_N ((size_t)TT * EE)

// ---------------- scratch (static device globals; no allocation) -------------
__device__ float g_wq[EE * EE];
__device__ float g_wk[EE * EE];
__device__ float g_wv[EE * EE];
__device__ float g_wff[EE * EE];
__device__ float g_q[BB * TT * EE];   // [B, T, H*F]
__device__ float g_k[BB * TT * EE];
__device__ float g_v[BB * TT * EE];
__device__ float g_s[(size_t)BB * HH * TT * TT];  // 256 MB scores/attn
__device__ float g_zm[BB * TT * EE];
__device__ float g_zf[BB * TT * EE];
__device__ float g_z1[BB * TT * EE];
__device__ float g_z2[BB * TT * EE];
__device__ double g_part[BB * 64 * 2];
__device__ float g_stats[BB * 2];

// ---------------- helpers ----------------------------------------------------
__device__ __forceinline__ uint32_t f2tf(float x) {
    uint32_t r;
    asm("cvt.rna.tf32.f32 %0, %1;" : "=r"(r) : "f"(x));
    return r;
}

__device__ __forceinline__ void mma8(float c[4], const uint32_t a[4], const uint32_t b[2]) {
    asm volatile(
        "mma.sync.aligned.m16n8k8.row.col.f32.tf32.tf32.f32 "
        "{%0,%1,%2,%3}, {%4,%5,%6,%7}, {%8,%9}, {%0,%1,%2,%3};\n"
        : "+f"(c[0]), "+f"(c[1]), "+f"(c[2]), "+f"(c[3])
        : "r"(a[0]), "r"(a[1]), "r"(a[2]), "r"(a[3]), "r"(b[0]), "r"(b[1]));
}

// ---------------- weight repacks ---------------------------------------------
__global__ void repack_qkv(const float* __restrict__ qw,
                           const float* __restrict__ kw,
                           const float* __restrict__ vw) {
    int idx = blockIdx.x * blockDim.x + threadIdx.x;
    if (idx >= EE * EE) return;
    int e = idx / EE, n = idx % EE;
    int h = n >> 6, f = n & 63;
    int src = h * (EE * FFDIM) + e * FFDIM + f;
    g_wq[idx] = qw[src];
    g_wk[idx] = kw[src];
    g_wv[idx] = vw[src];
}

__global__ void repack_ff(const float* __restrict__ w) {
    int idx = blockIdx.x * blockDim.x + threadIdx.x;
    if (idx >= EE * EE) return;
    int e = idx / EE, d = idx % EE;
    g_wff[idx] = w[d * EE + e];
}

// ---------------- fp32 SIMT GEMM, 128x128, 8x8/thread, sequential-k fma ------
// Per-output arithmetic: acc = fma(A[m][k], B[k][n], acc) for k = 0..K-1 in
// ascending order — bit-identical to the R1 baseline that passed.
__global__ __launch_bounds__(256) void gemm_simt8(
    const float* __restrict__ A, const float* __restrict__ Bm,
    float* __restrict__ C, int M, int N, int K) {
    __shared__ float As[16][132];  // [k][m]
    __shared__ float Bs[16][128];  // [k][n]
    int m0 = blockIdx.y * 128, n0 = blockIdx.x * 128;
    int tid = threadIdx.x;
    int ty = tid >> 4, tx = tid & 15;
    float acc[8][8] = {};
    int ar = tid >> 2;            // 0..63
    int ac4 = (tid & 3) * 4;      // 0,4,8,12
    int bk = tid >> 5;            // 0..7
    int bc4 = (tid & 31) * 4;     // 0..124

    for (int k0 = 0; k0 < K; k0 += 16) {
#pragma unroll
        for (int ri = 0; ri < 2; ri++) {
            int r = ar + ri * 64;
            const float4 v = *(const float4*)&A[(size_t)(m0 + r) * K + k0 + ac4];
            As[ac4 + 0][r] = v.x;
            As[ac4 + 1][r] = v.y;
            As[ac4 + 2][r] = v.z;
            As[ac4 + 3][r] = v.w;
        }
#pragma unroll
        for (int ki = 0; ki < 2; ki++) {
            *(float4*)&Bs[bk + ki * 8][bc4] =
                *(const float4*)&Bm[(size_t)(k0 + bk + ki * 8) * N + n0 + bc4];
        }
        __syncthreads();
#pragma unroll
        for (int k = 0; k < 16; k++) {
            float a[8], b[8];
            *(float4*)&a[0] = *(const float4*)&As[k][ty * 8];
            *(float4*)&a[4] = *(const float4*)&As[k][ty * 8 + 4];
            *(float4*)&b[0] = *(const float4*)&Bs[k][tx * 8];
            *(float4*)&b[4] = *(const float4*)&Bs[k][tx * 8 + 4];
#pragma unroll
            for (int i = 0; i < 8; i++)
#pragma unroll
                for (int j = 0; j < 8; j++) acc[i][j] += a[i] * b[j];
        }
        __syncthreads();
    }
#pragma unroll
    for (int i = 0; i < 8; i++) {
        int m = m0 + ty * 8 + i;
        *(float4*)&C[(size_t)m * N + n0 + tx * 8] = *(float4*)&acc[i][0];
        *(float4*)&C[(size_t)m * N + n0 + tx * 8 + 4] = *(float4*)&acc[i][4];
    }
}

// ---------------- scores = (Q K^T) * mask / 8, fp32 SIMT, sequential-f -------
// grid (T/128 key tiles, T/128 query tiles, B*H); 8x8 per thread.
__global__ __launch_bounds__(256) void attn_scores8() {
    __shared__ float qs[16][132];  // [f][q]
    __shared__ float ks[16][132];  // [f][k]
    int bh = blockIdx.z;
    int b = bh / HH, h = bh % HH;
    int q0 = blockIdx.y * 128, k0 = blockIdx.x * 128;
    const float* qp = g_q + (size_t)b * TT * EE + h * FFDIM;
    const float* kp = g_k + (size_t)b * TT * EE + h * FFDIM;
    int tid = threadIdx.x;
    int ty = tid >> 4, tx = tid & 15;
    float acc[8][8] = {};
    int ar = tid >> 2;
    int ac4 = (tid & 3) * 4;

    for (int c0 = 0; c0 < FFDIM; c0 += 16) {
#pragma unroll
        for (int ri = 0; ri < 2; ri++) {
            int r = ar + ri * 64;
            const float4 va = *(const float4*)&qp[(size_t)(q0 + r) * EE + c0 + ac4];
            qs[ac4 + 0][r] = va.x;
            qs[ac4 + 1][r] = va.y;
            qs[ac4 + 2][r] = va.z;
            qs[ac4 + 3][r] = va.w;
            const float4 vb = *(const float4*)&kp[(size_t)(k0 + r) * EE + c0 + ac4];
            ks[ac4 + 0][r] = vb.x;
            ks[ac4 + 1][r] = vb.y;
            ks[ac4 + 2][r] = vb.z;
            ks[ac4 + 3][r] = vb.w;
        }
        __syncthreads();
#pragma unroll
        for (int f = 0; f < 16; f++) {
            float a[8], bv[8];
            *(float4*)&a[0] = *(const float4*)&qs[f][ty * 8];
            *(float4*)&a[4] = *(const float4*)&qs[f][ty * 8 + 4];
            *(float4*)&bv[0] = *(const float4*)&ks[f][tx * 8];
            *(float4*)&bv[4] = *(const float4*)&ks[f][tx * 8 + 4];
#pragma unroll
            for (int i = 0; i < 8; i++)
#pragma unroll
                for (int j = 0; j < 8; j++) acc[i][j] += a[i] * bv[j];
        }
        __syncthreads();
    }
    float* sp = g_s + (size_t)bh * TT * TT;
#pragma unroll
    for (int i = 0; i < 8; i++) {
        int qg = q0 + ty * 8 + i;
#pragma unroll
        for (int j = 0; j < 8; j++) {
            int kg = k0 + tx * 8 + j;
            // identical expression to the passing R1 kernel
            float m = (kg > qg) ? (1.0f - 1.0e9f) : 1.0f;
            sp[(size_t)qg * TT + kg] = acc[i][j] * m * 0.125f;
        }
    }
}

// ---------------- softmax over rows of 1024, in place (R1-identical) ---------
__global__ __launch_bounds__(256) void softmax_rows() {
    size_t row = blockIdx.x;
    float* p = g_s + row * TT;
    int tid = threadIdx.x;
    float v[4];
    float mx = -INFINITY;
#pragma unroll
    for (int i = 0; i < 4; i++) {
        v[i] = p[tid + i * 256];
        mx = fmaxf(mx, v[i]);
    }
    __shared__ float sm[8];
#pragma unroll
    for (int o = 16; o > 0; o >>= 1) mx = fmaxf(mx, __shfl_xor_sync(0xffffffffu, mx, o));
    if ((tid & 31) == 0) sm[tid >> 5] = mx;
    __syncthreads();
    if (tid < 8) {
        float m2 = sm[tid];
#pragma unroll
        for (int o = 4; o > 0; o >>= 1) m2 = fmaxf(m2, __shfl_xor_sync(0xffu, m2, o));
        sm[tid] = m2;
    }
    __syncthreads();
    mx = sm[0];
    float s = 0.0f;
#pragma unroll
    for (int i = 0; i < 4; i++) {
        v[i] = __expf(v[i] - mx);
        s += v[i];
    }
    __shared__ float ss[8];
#pragma unroll
    for (int o = 16; o > 0; o >>= 1) s += __shfl_xor_sync(0xffffffffu, s, o);
    if ((tid & 31) == 0) ss[tid >> 5] = s;
    __syncthreads();
    if (tid < 8) {
        float s2 = ss[tid];
#pragma unroll
        for (int o = 4; o > 0; o >>= 1) s2 += __shfl_xor_sync(0xffu, s2, o);
        ss[tid] = s2;
    }
    __syncthreads();
    float inv = 1.0f / ss[0];
#pragma unroll
    for (int i = 0; i < 4; i++) p[tid + i * 256] = v[i] * inv;
}

// ---------------- z = attn * V via tf32 MMA, 2-term (V split hi+lo) ----------
// attn weights are exactly {0,1} (one-hot rows) -> tf32 A is exact; splitting
// V recovers full fp32 V values. grid (T/128 query tiles, B*H).
__global__ __launch_bounds__(256, 2) void attn_av_mma() {
    __shared__ uint32_t As[16][136];   // [k][q] attn (exact in tf32)
    __shared__ uint32_t Bs[16][72];    // [k][f] V hi
    __shared__ uint32_t Bsl[16][72];   // [k][f] V lo
    int bh = blockIdx.y;
    int b = bh / HH, h = bh % HH;
    int m0 = blockIdx.x * 128;
    const float* sp = g_s + (size_t)bh * TT * TT;
    const float* vp = g_v + (size_t)b * TT * EE + h * FFDIM;
    float* op = g_zm + (size_t)b * TT * EE + h * FFDIM;
    int tid = threadIdx.x, lane = tid & 31, w = tid >> 5;
    int wm = w >> 1, wn = w & 1;
    int g = lane >> 2, tig = lane & 3;
    float acc[2][4][4] = {};
    int ar = tid >> 2;
    int ac4 = (tid & 3) * 4;
    int bk = tid >> 4;           // 0..15
    int bn4 = (tid & 15) * 4;    // 0..60

    for (int k0 = 0; k0 < TT; k0 += 16) {
#pragma unroll
        for (int ri = 0; ri < 2; ri++) {
            int r = ar + ri * 64;
            const float4 v = *(const float4*)&sp[(size_t)(m0 + r) * TT + k0 + ac4];
            As[ac4 + 0][r] = f2tf(v.x);
            As[ac4 + 1][r] = f2tf(v.y);
            As[ac4 + 2][r] = f2tf(v.z);
            As[ac4 + 3][r] = f2tf(v.w);
        }
        {
            const float4 v = *(const float4*)&vp[(size_t)(k0 + bk) * EE + bn4];
            uint4 t, l;
            t.x = f2tf(v.x); t.y = f2tf(v.y); t.z = f2tf(v.z); t.w = f2tf(v.w);
            l.x = f2tf(v.x - __uint_as_float(t.x));
            l.y = f2tf(v.y - __uint_as_float(t.y));
            l.z = f2tf(v.z - __uint_as_float(t.z));
            l.w = f2tf(v.w - __uint_as_float(t.w));
            *(uint4*)&Bs[bk][bn4] = t;
            *(uint4*)&Bsl[bk][bn4] = l;
        }
        __syncthreads();
#pragma unroll
        for (int kk = 0; kk < 16; kk += 8) {
            uint32_t af[2][4];
#pragma unroll
            for (int mi = 0; mi < 2; mi++) {
                int mb = wm * 32 + mi * 16 + g;
                af[mi][0] = As[kk + tig][mb];
                af[mi][1] = As[kk + tig][mb + 8];
                af[mi][2] = As[kk + tig + 4][mb];
                af[mi][3] = As[kk + tig + 4][mb + 8];
            }
#pragma unroll
            for (int ni = 0; ni < 4; ni++) {
                int nb = wn * 32 + ni * 8 + g;
                uint32_t bf[2], bfl[2];
                bf[0] = Bs[kk + tig][nb];
                bf[1] = Bs[kk + tig + 4][nb];
                bfl[0] = Bsl[kk + tig][nb];
                bfl[1] = Bsl[kk + tig + 4][nb];
#pragma unroll
                for (int mi = 0; mi < 2; mi++) {
                    mma8(acc[mi][ni], af[mi], bfl);
                    mma8(acc[mi][ni], af[mi], bf);
                }
            }
        }
        __syncthreads();
    }
#pragma unroll
    for (int mi = 0; mi < 2; mi++) {
        int m = m0 + wm * 32 + mi * 16 + g;
#pragma unroll
        for (int ni = 0; ni < 4; ni++) {
            int n = wn * 32 + ni * 8 + tig * 2;
            *(float2*)&op[(size_t)m * EE + n] = make_float2(acc[mi][ni][0], acc[mi][ni][1]);
            *(float2*)&op[(size_t)(m + 8) * EE + n] = make_float2(acc[mi][ni][2], acc[mi][ni][3]);
        }
    }
}

// ---------------- 3xTF32 tensor-core GEMM (error-tolerant paths) -------------
template <bool RELU>
__global__ __launch_bounds__(256, 2) void gemm_tf32x3(
    const float* __restrict__ A, const float* __restrict__ Bm,
    float* __restrict__ C, int M, int N, int K,
    long sA, long sB, long sC, const float* __restrict__ bias) {
    extern __shared__ uint32_t sm_[];
    uint32_t(*As)[136] = (uint32_t(*)[136])sm_;
    uint32_t(*Bs)[136] = (uint32_t(*)[136])(sm_ + 16 * 136);
    uint32_t(*Asl)[136] = (uint32_t(*)[136])(sm_ + 2 * 16 * 136);
    uint32_t(*Bsl)[136] = (uint32_t(*)[136])(sm_ + 3 * 16 * 136);
    A += (size_t)blockIdx.z * sA;
    Bm += (size_t)blockIdx.z * sB;
    C += (size_t)blockIdx.z * sC;
    int m0 = blockIdx.y * 128, n0 = blockIdx.x * 128;
    int tid = threadIdx.x, lane = tid & 31, w = tid >> 5;
    int wm = w & 1, wn = w >> 1;
    int g = lane >> 2, tig = lane & 3;
    float acc[4][4][4] = {};
    int ar = tid >> 2;
    int ac4 = (tid & 3) * 4;
    int bk = tid >> 5;
    int bn4 = (tid & 31) * 4;

    for (int k0 = 0; k0 < K; k0 += 16) {
#pragma unroll
        for (int ri = 0; ri < 2; ri++) {
            const float4 v = *(const float4*)&A[(size_t)(m0 + ar + ri * 64) * K + k0 + ac4];
            int r = ar + ri * 64;
            uint32_t h0 = f2tf(v.x), h1 = f2tf(v.y), h2 = f2tf(v.z), h3 = f2tf(v.w);
            As[ac4 + 0][r] = h0;
            As[ac4 + 1][r] = h1;
            As[ac4 + 2][r] = h2;
            As[ac4 + 3][r] = h3;
            Asl[ac4 + 0][r] = f2tf(v.x - __uint_as_float(h0));
            Asl[ac4 + 1][r] = f2tf(v.y - __uint_as_float(h1));
            Asl[ac4 + 2][r] = f2tf(v.z - __uint_as_float(h2));
            Asl[ac4 + 3][r] = f2tf(v.w - __uint_as_float(h3));
        }
#pragma unroll
        for (int ki = 0; ki < 2; ki++) {
            const float4 v = *(const float4*)&Bm[(size_t)(k0 + bk + ki * 8) * N + n0 + bn4];
            uint4 t, l;
            t.x = f2tf(v.x); t.y = f2tf(v.y); t.z = f2tf(v.z); t.w = f2tf(v.w);
            l.x = f2tf(v.x - __uint_as_float(t.x));
            l.y = f2tf(v.y - __uint_as_float(t.y));
            l.z = f2tf(v.z - __uint_as_float(t.z));
            l.w = f2tf(v.w - __uint_as_float(t.w));
            *(uint4*)&Bs[bk + ki * 8][bn4] = t;
            *(uint4*)&Bsl[bk + ki * 8][bn4] = l;
        }
        __syncthreads();
#pragma unroll
        for (int kk = 0; kk < 16; kk += 8) {
            uint32_t af[4][4], afl[4][4];
#pragma unroll
            for (int mi = 0; mi < 4; mi++) {
                int mb = wm * 64 + mi * 16 + g;
                af[mi][0] = As[kk + tig][mb];
                af[mi][1] = As[kk + tig][mb + 8];
                af[mi][2] = As[kk + tig + 4][mb];
                af[mi][3] = As[kk + tig + 4][mb + 8];
                afl[mi][0] = Asl[kk + tig][mb];
                afl[mi][1] = Asl[kk + tig][mb + 8];
                afl[mi][2] = Asl[kk + tig + 4][mb];
                afl[mi][3] = Asl[kk + tig + 4][mb + 8];
            }
#pragma unroll
            for (int ni = 0; ni < 4; ni++) {
                int nb = wn * 32 + ni * 8 + g;
                uint32_t bf[2], bfl[2];
                bf[0] = Bs[kk + tig][nb];
                bf[1] = Bs[kk + tig + 4][nb];
                bfl[0] = Bsl[kk + tig][nb];
                bfl[1] = Bsl[kk + tig + 4][nb];
#pragma unroll
                for (int mi = 0; mi < 4; mi++) {
                    mma8(acc[mi][ni], af[mi], bfl);
                    mma8(acc[mi][ni], afl[mi], bf);
                    mma8(acc[mi][ni], af[mi], bf);
                }
            }
        }
        __syncthreads();
    }
#pragma unroll
    for (int mi = 0; mi < 4; mi++) {
        int m = m0 + wm * 64 + mi * 16 + g;
#pragma unroll
        for (int ni = 0; ni < 4; ni++) {
            int n = n0 + wn * 32 + ni * 8 + tig * 2;
            float b0 = bias ? bias[n] : 0.0f;
            float b1 = bias ? bias[n + 1] : 0.0f;
            float v0 = acc[mi][ni][0] + b0, v1 = acc[mi][ni][1] + b1;
            float v2 = acc[mi][ni][2] + b0, v3 = acc[mi][ni][3] + b1;
            if (RELU) {
                v0 = fmaxf(v0, 0.0f); v1 = fmaxf(v1, 0.0f);
                v2 = fmaxf(v2, 0.0f); v3 = fmaxf(v3, 0.0f);
            }
            *(float2*)&C[(size_t)m * N + n] = make_float2(v0, v1);
            *(float2*)&C[(size_t)(m + 8) * N + n] = make_float2(v2, v3);
        }
    }
}

// ---------------- LayerNorm over whole [T,E] plane per batch -----------------
__global__ __launch_bounds__(256) void ln_reduce(const float* __restrict__ in1,
                                                 const float* __restrict__ in2) {
    int b = blockIdx.y;
    const float* p1 = in1 + (size_t)b * LN_N;
    const float* p2 = in2 + (size_t)b * LN_N;
    const int chunk = (int)(LN_N / 64);
    size_t base = (size_t)blockIdx.x * chunk;
    double s = 0.0, sq = 0.0;
    for (int i = threadIdx.x; i < chunk; i += 256) {
        float x = p1[base + i] + p2[base + i];
        s += x;
        sq += (double)x * x;
    }
    __shared__ double sh[256], shq[256];
    int tid = threadIdx.x;
    sh[tid] = s;
    shq[tid] = sq;
    __syncthreads();
    for (int o = 128; o > 0; o >>= 1) {
        if (tid < o) {
            sh[tid] += sh[tid + o];
            shq[tid] += shq[tid + o];
        }
        __syncthreads();
    }
    if (tid == 0) {
        g_part[(b * 64 + blockIdx.x) * 2] = sh[0];
        g_part[(b * 64 + blockIdx.x) * 2 + 1] = shq[0];
    }
}

__global__ void ln_finalize() {
    int b = blockIdx.x;
    int tid = threadIdx.x;  // 64
    __shared__ double sh[64], shq[64];
    sh[tid] = g_part[(b * 64 + tid) * 2];
    shq[tid] = g_part[(b * 64 + tid) * 2 + 1];
    __syncthreads();
    for (int o = 32; o > 0; o >>= 1) {
        if (tid < o) {
            sh[tid] += sh[tid + o];
            shq[tid] += shq[tid + o];
        }
        __syncthreads();
    }
    if (tid == 0) {
        double n = (double)LN_N;
        double mean = sh[0] / n;
        double var = shq[0] / n - mean * mean;
        g_stats[b * 2] = (float)mean;
        g_stats[b * 2 + 1] = (float)(1.0 / sqrt(var + 1e-5));
    }
}

__global__ __launch_bounds__(256) void ln_norm(const float* __restrict__ in1,
                                               const float* __restrict__ in2,
                                               const float* __restrict__ w,
                                               const float* __restrict__ bia,
                                               float* __restrict__ out) {
    size_t i = (size_t)blockIdx.x * blockDim.x + threadIdx.x;
    if (i >= (size_t)BB * LN_N) return;
    int b = (int)(i / LN_N);
    size_t te = i % LN_N;
    float mean = g_stats[b * 2];
    float rstd = g_stats[b * 2 + 1];
    float x = in1[i] + in2[i];
    out[i] = (x - mean) * rstd * w[te] + bia[te];
}

// ---------------- launch -----------------------------------------------------
extern "C" void kernel_launch(void* const* d_in, const int* in_sizes, int n_in,
                              void* d_out, int out_size) {
    const float* x = (const float*)d_in[0];
    const float* q_w = (const float*)d_in[1];
    const float* k_w = (const float*)d_in[2];
    const float* v_w = (const float*)d_in[3];
    const float* fr_w = (const float*)d_in[4];
    const float* ff_w = (const float*)d_in[5];
    const float* ff_b = (const float*)d_in[6];
    const float* ln1_w = (const float*)d_in[7];
    const float* ln1_b = (const float*)d_in[8];
    const float* ln2_w = (const float*)d_in[9];
    const float* ln2_b = (const float*)d_in[10];
    float* out = (float*)d_out;

    float *p_wq, *p_wk, *p_wv, *p_wff, *p_q, *p_k, *p_v;
    float *p_zm, *p_zf, *p_z1, *p_z2;
    cudaGetSymbolAddress((void**)&p_wq, g_wq);
    cudaGetSymbolAddress((void**)&p_wk, g_wk);
    cudaGetSymbolAddress((void**)&p_wv, g_wv);
    cudaGetSymbolAddress((void**)&p_wff, g_wff);
    cudaGetSymbolAddress((void**)&p_q, g_q);
    cudaGetSymbolAddress((void**)&p_k, g_k);
    cudaGetSymbolAddress((void**)&p_v, g_v);
    cudaGetSymbolAddress((void**)&p_zm, g_zm);
    cudaGetSymbolAddress((void**)&p_zf, g_zf);
    cudaGetSymbolAddress((void**)&p_z1, g_z1);
    cudaGetSymbolAddress((void**)&p_z2, g_z2);

    const size_t SM3 = 4 * 16 * 136 * sizeof(uint32_t);

    // 1) repack weights
    repack_qkv<<<(EE * EE + 255) / 256, 256>>>(q_w, k_w, v_w);
    repack_ff<<<(EE * EE + 255) / 256, 256>>>(ff_w);

    // 2) Q,K: exact fp32 sequential-k (argmax-critical); V: 3xTF32
    dim3 gs8(EE / 128, (BB * TT) / 128, 1);
    gemm_simt8<<<gs8, 256>>>(x, p_wq, p_q, BB * TT, EE, EE);
    gemm_simt8<<<gs8, 256>>>(x, p_wk, p_k, BB * TT, EE, EE);
    gemm_tf32x3<false><<<gs8, 256, SM3>>>(x, p_wv, p_v, BB * TT, EE, EE, 0, 0, 0, nullptr);

    // 3) attention
    dim3 gsc(TT / 128, TT / 128, BB * HH);
    attn_scores8<<<gsc, 256>>>();
    softmax_rows<<<BB * HH * TT, 256>>>();
    dim3 gav(TT / 128, BB * HH, 1);
    attn_av_mma<<<gav, 256>>>();

    // 4) per-batch feature reduction (3xTF32)
    dim3 gfr(EE / 128, TT / 128, BB);
    gemm_tf32x3<false><<<gfr, 256, SM3>>>(p_zm, fr_w, p_zf, TT, EE, EE,
                                          (long)TT * EE, (long)EE * EE, (long)TT * EE,
                                          nullptr);

    // 5) LN1 over x + zf -> z1
    dim3 gred(64, BB, 1);
    ln_reduce<<<gred, 256>>>(x, p_zf);
    ln_finalize<<<BB, 64>>>();
    size_t total = (size_t)BB * LN_N;
    ln_norm<<<(unsigned)((total + 255) / 256), 256>>>(x, p_zf, ln1_w, ln1_b, p_z1);

    // 6) FFN: z2 = relu(z1 @ ff_w^T + ff_b) (3xTF32)
    gemm_tf32x3<true><<<gs8, 256, SM3>>>(p_z1, p_wff, p_z2, BB * TT, EE, EE, 0, 0, 0, ff_b);

    // 7) LN2 over z1 + z2 -> out
    ln_reduce<<<gred, 256>>>(p_z1, p_z2);
    ln_finalize<<<BB, 64>>>();
    ln_norm<<<(unsigned)((total + 255) / 256), 256>>>(p_z1, p_z2, ln2_w, ln2_b, out);
}

// round 6
// speedup vs baseline: 1.6904x; 1.0923x over previous
#include <cuda_runtime.h>
#include <math.h>
#include <stdint.h>

#define BB 4
#define TT 1024
#define EE 1024
#define HH 16
#define FFDIM 64
#define LN_N ((size_t)TT * EE)

// ---------------- scratch (static device globals; no allocation) -------------
__device__ float g_wq[EE * EE];
__device__ float g_wk[EE * EE];
__device__ float g_wv[EE * EE];
__device__ float g_wff[EE * EE];
__device__ float g_q[BB * TT * EE];   // [B, T, H*F]
__device__ float g_k[BB * TT * EE];
__device__ float g_v[BB * TT * EE];
__device__ float g_zm[BB * TT * EE];
__device__ float g_zf[BB * TT * EE];
__device__ float g_z1[BB * TT * EE];
__device__ float g_z2[BB * TT * EE];
__device__ double g_part[BB * 64 * 2];
__device__ float g_stats[BB * 2];

// ---------------- helpers ----------------------------------------------------
__device__ __forceinline__ uint32_t f2tf(float x) {
    uint32_t r;
    asm("cvt.rna.tf32.f32 %0, %1;" : "=r"(r) : "f"(x));
    return r;
}

__device__ __forceinline__ void mma8(float c[4], const uint32_t a[4], const uint32_t b[2]) {
    asm volatile(
        "mma.sync.aligned.m16n8k8.row.col.f32.tf32.tf32.f32 "
        "{%0,%1,%2,%3}, {%4,%5,%6,%7}, {%8,%9}, {%0,%1,%2,%3};\n"
        : "+f"(c[0]), "+f"(c[1]), "+f"(c[2]), "+f"(c[3])
        : "r"(a[0]), "r"(a[1]), "r"(a[2]), "r"(a[3]), "r"(b[0]), "r"(b[1]));
}

// ---------------- weight repacks ---------------------------------------------
__global__ void repack_qkv(const float* __restrict__ qw,
                           const float* __restrict__ kw,
                           const float* __restrict__ vw) {
    int idx = blockIdx.x * blockDim.x + threadIdx.x;
    if (idx >= EE * EE) return;
    int e = idx / EE, n = idx % EE;
    int h = n >> 6, f = n & 63;
    int src = h * (EE * FFDIM) + e * FFDIM + f;
    g_wq[idx] = qw[src];
    g_wk[idx] = kw[src];
    g_wv[idx] = vw[src];
}

__global__ void repack_ff(const float* __restrict__ w) {
    int idx = blockIdx.x * blockDim.x + threadIdx.x;
    if (idx >= EE * EE) return;
    int e = idx / EE, d = idx % EE;
    g_wff[idx] = w[d * EE + e];
}

// ---------------- fp32 SIMT GEMM, 128x128, 8x8/thread, double-buffered -------
// Per-output fma order: ascending k — bit-identical to the R4 kernel that passed.
__global__ __launch_bounds__(256) void gemm_simt8_db(
    const float* __restrict__ A, const float* __restrict__ Bm,
    float* __restrict__ C, int M, int N, int K) {
    __shared__ float As[2][16][132];  // [stage][k][m]
    __shared__ float Bs[2][16][128];  // [stage][k][n]
    int m0 = blockIdx.y * 128, n0 = blockIdx.x * 128;
    int tid = threadIdx.x;
    int ty = tid >> 4, tx = tid & 15;
    float acc[8][8] = {};
    int ar = tid >> 2;            // 0..63
    int ac4 = (tid & 3) * 4;      // 0,4,8,12
    int bk = tid >> 5;            // 0..7
    int bc4 = (tid & 31) * 4;     // 0..124

    float4 ra0, ra1, rb0, rb1;
    // prologue: tile 0 -> regs -> smem[0]
    ra0 = *(const float4*)&A[(size_t)(m0 + ar) * K + ac4];
    ra1 = *(const float4*)&A[(size_t)(m0 + ar + 64) * K + ac4];
    rb0 = *(const float4*)&Bm[(size_t)bk * N + n0 + bc4];
    rb1 = *(const float4*)&Bm[(size_t)(bk + 8) * N + n0 + bc4];
    As[0][ac4 + 0][ar] = ra0.x; As[0][ac4 + 1][ar] = ra0.y;
    As[0][ac4 + 2][ar] = ra0.z; As[0][ac4 + 3][ar] = ra0.w;
    As[0][ac4 + 0][ar + 64] = ra1.x; As[0][ac4 + 1][ar + 64] = ra1.y;
    As[0][ac4 + 2][ar + 64] = ra1.z; As[0][ac4 + 3][ar + 64] = ra1.w;
    *(float4*)&Bs[0][bk][bc4] = rb0;
    *(float4*)&Bs[0][bk + 8][bc4] = rb1;
    __syncthreads();

    int nt = K / 16;
    for (int t = 0; t < nt; t++) {
        int s = t & 1;
        if (t + 1 < nt) {
            int k0 = (t + 1) * 16;
            ra0 = *(const float4*)&A[(size_t)(m0 + ar) * K + k0 + ac4];
            ra1 = *(const float4*)&A[(size_t)(m0 + ar + 64) * K + k0 + ac4];
            rb0 = *(const float4*)&Bm[(size_t)(k0 + bk) * N + n0 + bc4];
            rb1 = *(const float4*)&Bm[(size_t)(k0 + bk + 8) * N + n0 + bc4];
        }
#pragma unroll
        for (int k = 0; k < 16; k++) {
            float a[8], b[8];
            *(float4*)&a[0] = *(const float4*)&As[s][k][ty * 8];
            *(float4*)&a[4] = *(const float4*)&As[s][k][ty * 8 + 4];
            *(float4*)&b[0] = *(const float4*)&Bs[s][k][tx * 8];
            *(float4*)&b[4] = *(const float4*)&Bs[s][k][tx * 8 + 4];
#pragma unroll
            for (int i = 0; i < 8; i++)
#pragma unroll
                for (int j = 0; j < 8; j++) acc[i][j] += a[i] * b[j];
        }
        if (t + 1 < nt) {
            int s2 = s ^ 1;
            As[s2][ac4 + 0][ar] = ra0.x; As[s2][ac4 + 1][ar] = ra0.y;
            As[s2][ac4 + 2][ar] = ra0.z; As[s2][ac4 + 3][ar] = ra0.w;
            As[s2][ac4 + 0][ar + 64] = ra1.x; As[s2][ac4 + 1][ar + 64] = ra1.y;
            As[s2][ac4 + 2][ar + 64] = ra1.z; As[s2][ac4 + 3][ar + 64] = ra1.w;
            *(float4*)&Bs[s2][bk][bc4] = rb0;
            *(float4*)&Bs[s2][bk + 8][bc4] = rb1;
        }
        __syncthreads();
    }
#pragma unroll
    for (int i = 0; i < 8; i++) {
        int m = m0 + ty * 8 + i;
        *(float4*)&C[(size_t)m * N + n0 + tx * 8] = *(float4*)&acc[i][0];
        *(float4*)&C[(size_t)m * N + n0 + tx * 8 + 4] = *(float4*)&acc[i][4];
    }
}

// ---------------- fused attention: scores (exact fp32) + softmax + PV --------
// One block per (q-tile of 128, b*h). Scores computed with the identical
// ascending-f fp32 fma chain and mask expression as the passing R4 kernel, so
// argmaxes are bit-identical. Online softmax (rows are one-hot); PV on tensor
// cores (P tf32 exact for {0,1}; V hi+lo split — same as R4's attn_av_mma).
struct __align__(16) AttnSmem {
    float qs[64][132];     // [f][q]
    float ks[64][132];     // [f][k]
    float vs[128][72];     // [k][f]
    uint32_t Ps[128][132]; // [q][k] tf32
    float sm_m[128];
    float sm_l[128];
    float sm_sc[128];
};

__global__ __launch_bounds__(256) void attn_fused() {
    extern __shared__ char smraw[];
    AttnSmem* S = (AttnSmem*)smraw;
    int bh = blockIdx.y;
    int b = bh / HH, h = bh % HH;
    int q0 = blockIdx.x * 128;
    const float* qp = g_q + (size_t)b * TT * EE + h * FFDIM;
    const float* kp = g_k + (size_t)b * TT * EE + h * FFDIM;
    const float* vp = g_v + (size_t)b * TT * EE + h * FFDIM;
    float* op = g_zm + (size_t)b * TT * EE + h * FFDIM;

    int tid = threadIdx.x;
    int ty = tid >> 4, tx = tid & 15;
    int lane = tid & 31, w = tid >> 5;
    int wm = w >> 1, wn = w & 1;
    int g = lane >> 2, tig = lane & 3;
    int ar = tid >> 2;
    int ac4 = (tid & 3) * 4;

    // load Q tile (once)
#pragma unroll
    for (int c0 = 0; c0 < 64; c0 += 16) {
#pragma unroll
        for (int ri = 0; ri < 2; ri++) {
            int r = ar + ri * 64;
            const float4 va = *(const float4*)&qp[(size_t)(q0 + r) * EE + c0 + ac4];
            S->qs[c0 + ac4 + 0][r] = va.x;
            S->qs[c0 + ac4 + 1][r] = va.y;
            S->qs[c0 + ac4 + 2][r] = va.z;
            S->qs[c0 + ac4 + 3][r] = va.w;
        }
    }
    if (tid < 128) {
        S->sm_m[tid] = -INFINITY;
        S->sm_l[tid] = 0.0f;
    }
    float acc[2][4][4] = {};
    __syncthreads();

    for (int k0 = 0; k0 < TT; k0 += 128) {
        // load K tile (transposed) + V tile
#pragma unroll
        for (int c0 = 0; c0 < 64; c0 += 16) {
#pragma unroll
            for (int ri = 0; ri < 2; ri++) {
                int r = ar + ri * 64;
                const float4 vb = *(const float4*)&kp[(size_t)(k0 + r) * EE + c0 + ac4];
                S->ks[c0 + ac4 + 0][r] = vb.x;
                S->ks[c0 + ac4 + 1][r] = vb.y;
                S->ks[c0 + ac4 + 2][r] = vb.z;
                S->ks[c0 + ac4 + 3][r] = vb.w;
            }
        }
        {
            int vr = tid >> 1;
            int vh = (tid & 1) * 32;
#pragma unroll
            for (int j = 0; j < 8; j++) {
                *(float4*)&S->vs[vr][vh + j * 4] =
                    *(const float4*)&vp[(size_t)(k0 + vr) * EE + vh + j * 4];
            }
        }
        __syncthreads();

        // S tile: 8x8 per thread, ascending f (identical to R4 scores kernel)
        float s[8][8] = {};
#pragma unroll
        for (int f = 0; f < 64; f++) {
            float a[8], bv[8];
            *(float4*)&a[0] = *(const float4*)&S->qs[f][ty * 8];
            *(float4*)&a[4] = *(const float4*)&S->qs[f][ty * 8 + 4];
            *(float4*)&bv[0] = *(const float4*)&S->ks[f][tx * 8];
            *(float4*)&bv[4] = *(const float4*)&S->ks[f][tx * 8 + 4];
#pragma unroll
            for (int i = 0; i < 8; i++)
#pragma unroll
                for (int j = 0; j < 8; j++) s[i][j] += a[i] * bv[j];
        }
        // mask + scale (identical expression to R4)
#pragma unroll
        for (int i = 0; i < 8; i++) {
            int qg = q0 + ty * 8 + i;
#pragma unroll
            for (int j = 0; j < 8; j++) {
                int kg = k0 + tx * 8 + j;
                float m = (kg > qg) ? (1.0f - 1.0e9f) : 1.0f;
                s[i][j] = s[i][j] * m * 0.125f;
            }
        }
        // tile row max (reduce over tx lanes within warp)
        float tm[8];
#pragma unroll
        for (int i = 0; i < 8; i++) {
            float v = s[i][0];
#pragma unroll
            for (int j = 1; j < 8; j++) v = fmaxf(v, s[i][j]);
#pragma unroll
            for (int o = 8; o > 0; o >>= 1) v = fmaxf(v, __shfl_xor_sync(0xffffffffu, v, o));
            tm[i] = v;
        }
        if (tx == 0) {
#pragma unroll
            for (int i = 0; i < 8; i++) {
                int row = ty * 8 + i;
                float mo = S->sm_m[row];
                float mn = fmaxf(mo, tm[i]);
                S->sm_sc[row] = __expf(mo - mn);
                S->sm_m[row] = mn;
            }
        }
        __syncthreads();

        // P = exp(s - m_new), write tf32 to smem, row sums
#pragma unroll
        for (int i = 0; i < 8; i++) {
            int row = ty * 8 + i;
            float mn = S->sm_m[row];
            float rs = 0.0f;
            uint32_t pr[8];
#pragma unroll
            for (int j = 0; j < 8; j++) {
                float p = __expf(s[i][j] - mn);
                rs += p;
                pr[j] = f2tf(p);
            }
            *(uint4*)&S->Ps[row][tx * 8] = make_uint4(pr[0], pr[1], pr[2], pr[3]);
            *(uint4*)&S->Ps[row][tx * 8 + 4] = make_uint4(pr[4], pr[5], pr[6], pr[7]);
#pragma unroll
            for (int o = 8; o > 0; o >>= 1) rs += __shfl_xor_sync(0xffffffffu, rs, o);
            if (tx == 0) S->sm_l[row] = S->sm_l[row] * S->sm_sc[row] + rs;
        }
        __syncthreads();

        // rescale O accumulators, then PV mma
#pragma unroll
        for (int mi = 0; mi < 2; mi++) {
            int row = wm * 32 + mi * 16 + g;
            float s0 = S->sm_sc[row], s1 = S->sm_sc[row + 8];
#pragma unroll
            for (int ni = 0; ni < 4; ni++) {
                acc[mi][ni][0] *= s0; acc[mi][ni][1] *= s0;
                acc[mi][ni][2] *= s1; acc[mi][ni][3] *= s1;
            }
        }
#pragma unroll
        for (int kk = 0; kk < 128; kk += 8) {
            uint32_t af[2][4];
#pragma unroll
            for (int mi = 0; mi < 2; mi++) {
                int mb = wm * 32 + mi * 16 + g;
                af[mi][0] = S->Ps[mb][kk + tig];
                af[mi][1] = S->Ps[mb + 8][kk + tig];
                af[mi][2] = S->Ps[mb][kk + tig + 4];
                af[mi][3] = S->Ps[mb + 8][kk + tig + 4];
            }
#pragma unroll
            for (int ni = 0; ni < 4; ni++) {
                int nb = wn * 32 + ni * 8 + g;
                float v0 = S->vs[kk + tig][nb];
                float v1 = S->vs[kk + tig + 4][nb];
                uint32_t bf[2], bfl[2];
                bf[0] = f2tf(v0);
                bf[1] = f2tf(v1);
                bfl[0] = f2tf(v0 - __uint_as_float(bf[0]));
                bfl[1] = f2tf(v1 - __uint_as_float(bf[1]));
#pragma unroll
                for (int mi = 0; mi < 2; mi++) {
                    mma8(acc[mi][ni], af[mi], bfl);
                    mma8(acc[mi][ni], af[mi], bf);
                }
            }
        }
        __syncthreads();
    }
    // epilogue: O /= l, write merged heads
#pragma unroll
    for (int mi = 0; mi < 2; mi++) {
        int row = wm * 32 + mi * 16 + g;
        float i0 = 1.0f / S->sm_l[row];
        float i1 = 1.0f / S->sm_l[row + 8];
        int m = q0 + row;
#pragma unroll
        for (int ni = 0; ni < 4; ni++) {
            int n = wn * 32 + ni * 8 + tig * 2;
            *(float2*)&op[(size_t)m * EE + n] =
                make_float2(acc[mi][ni][0] * i0, acc[mi][ni][1] * i0);
            *(float2*)&op[(size_t)(m + 8) * EE + n] =
                make_float2(acc[mi][ni][2] * i1, acc[mi][ni][3] * i1);
        }
    }
}

// ---------------- 3xTF32 tensor-core GEMM (error-tolerant paths) -------------
template <bool RELU>
__global__ __launch_bounds__(256, 2) void gemm_tf32x3(
    const float* __restrict__ A, const float* __restrict__ Bm,
    float* __restrict__ C, int M, int N, int K,
    long sA, long sB, long sC, const float* __restrict__ bias) {
    extern __shared__ uint32_t sm_[];
    uint32_t(*As)[136] = (uint32_t(*)[136])sm_;
    uint32_t(*Bs)[136] = (uint32_t(*)[136])(sm_ + 16 * 136);
    uint32_t(*Asl)[136] = (uint32_t(*)[136])(sm_ + 2 * 16 * 136);
    uint32_t(*Bsl)[136] = (uint32_t(*)[136])(sm_ + 3 * 16 * 136);
    A += (size_t)blockIdx.z * sA;
    Bm += (size_t)blockIdx.z * sB;
    C += (size_t)blockIdx.z * sC;
    int m0 = blockIdx.y * 128, n0 = blockIdx.x * 128;
    int tid = threadIdx.x, lane = tid & 31, w = tid >> 5;
    int wm = w & 1, wn = w >> 1;
    int g = lane >> 2, tig = lane & 3;
    float acc[4][4][4] = {};
    int ar = tid >> 2;
    int ac4 = (tid & 3) * 4;
    int bk = tid >> 5;
    int bn4 = (tid & 31) * 4;

    for (int k0 = 0; k0 < K; k0 += 16) {
#pragma unroll
        for (int ri = 0; ri < 2; ri++) {
            const float4 v = *(const float4*)&A[(size_t)(m0 + ar + ri * 64) * K + k0 + ac4];
            int r = ar + ri * 64;
            uint32_t h0 = f2tf(v.x), h1 = f2tf(v.y), h2 = f2tf(v.z), h3 = f2tf(v.w);
            As[ac4 + 0][r] = h0;
            As[ac4 + 1][r] = h1;
            As[ac4 + 2][r] = h2;
            As[ac4 + 3][r] = h3;
            Asl[ac4 + 0][r] = f2tf(v.x - __uint_as_float(h0));
            Asl[ac4 + 1][r] = f2tf(v.y - __uint_as_float(h1));
            Asl[ac4 + 2][r] = f2tf(v.z - __uint_as_float(h2));
            Asl[ac4 + 3][r] = f2tf(v.w - __uint_as_float(h3));
        }
#pragma unroll
        for (int ki = 0; ki < 2; ki++) {
            const float4 v = *(const float4*)&Bm[(size_t)(k0 + bk + ki * 8) * N + n0 + bn4];
            uint4 t, l;
            t.x = f2tf(v.x); t.y = f2tf(v.y); t.z = f2tf(v.z); t.w = f2tf(v.w);
            l.x = f2tf(v.x - __uint_as_float(t.x));
            l.y = f2tf(v.y - __uint_as_float(t.y));
            l.z = f2tf(v.z - __uint_as_float(t.z));
            l.w = f2tf(v.w - __uint_as_float(t.w));
            *(uint4*)&Bs[bk + ki * 8][bn4] = t;
            *(uint4*)&Bsl[bk + ki * 8][bn4] = l;
        }
        __syncthreads();
#pragma unroll
        for (int kk = 0; kk < 16; kk += 8) {
            uint32_t af[4][4], afl[4][4];
#pragma unroll
            for (int mi = 0; mi < 4; mi++) {
                int mb = wm * 64 + mi * 16 + g;
                af[mi][0] = As[kk + tig][mb];
                af[mi][1] = As[kk + tig][mb + 8];
                af[mi][2] = As[kk + tig + 4][mb];
                af[mi][3] = As[kk + tig + 4][mb + 8];
                afl[mi][0] = Asl[kk + tig][mb];
                afl[mi][1] = Asl[kk + tig][mb + 8];
                afl[mi][2] = Asl[kk + tig + 4][mb];
                afl[mi][3] = Asl[kk + tig + 4][mb + 8];
            }
#pragma unroll
            for (int ni = 0; ni < 4; ni++) {
                int nb = wn * 32 + ni * 8 + g;
                uint32_t bf[2], bfl[2];
                bf[0] = Bs[kk + tig][nb];
                bf[1] = Bs[kk + tig + 4][nb];
                bfl[0] = Bsl[kk + tig][nb];
                bfl[1] = Bsl[kk + tig + 4][nb];
#pragma unroll
                for (int mi = 0; mi < 4; mi++) {
                    mma8(acc[mi][ni], af[mi], bfl);
                    mma8(acc[mi][ni], afl[mi], bf);
                    mma8(acc[mi][ni], af[mi], bf);
                }
            }
        }
        __syncthreads();
    }
#pragma unroll
    for (int mi = 0; mi < 4; mi++) {
        int m = m0 + wm * 64 + mi * 16 + g;
#pragma unroll
        for (int ni = 0; ni < 4; ni++) {
            int n = n0 + wn * 32 + ni * 8 + tig * 2;
            float b0 = bias ? bias[n] : 0.0f;
            float b1 = bias ? bias[n + 1] : 0.0f;
            float v0 = acc[mi][ni][0] + b0, v1 = acc[mi][ni][1] + b1;
            float v2 = acc[mi][ni][2] + b0, v3 = acc[mi][ni][3] + b1;
            if (RELU) {
                v0 = fmaxf(v0, 0.0f); v1 = fmaxf(v1, 0.0f);
                v2 = fmaxf(v2, 0.0f); v3 = fmaxf(v3, 0.0f);
            }
            *(float2*)&C[(size_t)m * N + n] = make_float2(v0, v1);
            *(float2*)&C[(size_t)(m + 8) * N + n] = make_float2(v2, v3);
        }
    }
}

// ---------------- LayerNorm over whole [T,E] plane per batch -----------------
__global__ __launch_bounds__(256) void ln_reduce(const float* __restrict__ in1,
                                                 const float* __restrict__ in2) {
    int b = blockIdx.y;
    const float* p1 = in1 + (size_t)b * LN_N;
    const float* p2 = in2 + (size_t)b * LN_N;
    const int chunk = (int)(LN_N / 64);
    size_t base = (size_t)blockIdx.x * chunk;
    double s = 0.0, sq = 0.0;
    for (int i = threadIdx.x; i < chunk; i += 256) {
        float x = p1[base + i] + p2[base + i];
        s += x;
        sq += (double)x * x;
    }
    __shared__ double sh[256], shq[256];
    int tid = threadIdx.x;
    sh[tid] = s;
    shq[tid] = sq;
    __syncthreads();
    for (int o = 128; o > 0; o >>= 1) {
        if (tid < o) {
            sh[tid] += sh[tid + o];
            shq[tid] += shq[tid + o];
        }
        __syncthreads();
    }
    if (tid == 0) {
        g_part[(b * 64 + blockIdx.x) * 2] = sh[0];
        g_part[(b * 64 + blockIdx.x) * 2 + 1] = shq[0];
    }
}

__global__ void ln_finalize() {
    int b = blockIdx.x;
    int tid = threadIdx.x;  // 64
    __shared__ double sh[64], shq[64];
    sh[tid] = g_part[(b * 64 + tid) * 2];
    shq[tid] = g_part[(b * 64 + tid) * 2 + 1];
    __syncthreads();
    for (int o = 32; o > 0; o >>= 1) {
        if (tid < o) {
            sh[tid] += sh[tid + o];
            shq[tid] += shq[tid + o];
        }
        __syncthreads();
    }
    if (tid == 0) {
        double n = (double)LN_N;
        double mean = sh[0] / n;
        double var = shq[0] / n - mean * mean;
        g_stats[b * 2] = (float)mean;
        g_stats[b * 2 + 1] = (float)(1.0 / sqrt(var + 1e-5));
    }
}

__global__ __launch_bounds__(256) void ln_norm(const float* __restrict__ in1,
                                               const float* __restrict__ in2,
                                               const float* __restrict__ w,
                                               const float* __restrict__ bia,
                                               float* __restrict__ out) {
    size_t i = (size_t)blockIdx.x * blockDim.x + threadIdx.x;
    if (i >= (size_t)BB * LN_N) return;
    int b = (int)(i / LN_N);
    size_t te = i % LN_N;
    float mean = g_stats[b * 2];
    float rstd = g_stats[b * 2 + 1];
    float x = in1[i] + in2[i];
    out[i] = (x - mean) * rstd * w[te] + bia[te];
}

// ---------------- launch -----------------------------------------------------
extern "C" void kernel_launch(void* const* d_in, const int* in_sizes, int n_in,
                              void* d_out, int out_size) {
    const float* x = (const float*)d_in[0];
    const float* q_w = (const float*)d_in[1];
    const float* k_w = (const float*)d_in[2];
    const float* v_w = (const float*)d_in[3];
    const float* fr_w = (const float*)d_in[4];
    const float* ff_w = (const float*)d_in[5];
    const float* ff_b = (const float*)d_in[6];
    const float* ln1_w = (const float*)d_in[7];
    const float* ln1_b = (const float*)d_in[8];
    const float* ln2_w = (const float*)d_in[9];
    const float* ln2_b = (const float*)d_in[10];
    float* out = (float*)d_out;

    float *p_wq, *p_wk, *p_wv, *p_wff, *p_q, *p_k, *p_v;
    float *p_zm, *p_zf, *p_z1, *p_z2;
    cudaGetSymbolAddress((void**)&p_wq, g_wq);
    cudaGetSymbolAddress((void**)&p_wk, g_wk);
    cudaGetSymbolAddress((void**)&p_wv, g_wv);
    cudaGetSymbolAddress((void**)&p_wff, g_wff);
    cudaGetSymbolAddress((void**)&p_q, g_q);
    cudaGetSymbolAddress((void**)&p_k, g_k);
    cudaGetSymbolAddress((void**)&p_v, g_v);
    cudaGetSymbolAddress((void**)&p_zm, g_zm);
    cudaGetSymbolAddress((void**)&p_zf, g_zf);
    cudaGetSymbolAddress((void**)&p_z1, g_z1);
    cudaGetSymbolAddress((void**)&p_z2, g_z2);

    const size_t SM3 = 4 * 16 * 136 * sizeof(uint32_t);
    const size_t SMA = sizeof(AttnSmem);
    cudaFuncSetAttribute(attn_fused, cudaFuncAttributeMaxDynamicSharedMemorySize, (int)SMA);

    // 1) repack weights
    repack_qkv<<<(EE * EE + 255) / 256, 256>>>(q_w, k_w, v_w);
    repack_ff<<<(EE * EE + 255) / 256, 256>>>(ff_w);

    // 2) Q,K: exact fp32 sequential-k (argmax-critical), double-buffered; V: 3xTF32
    dim3 gs8(EE / 128, (BB * TT) / 128, 1);
    gemm_simt8_db<<<gs8, 256>>>(x, p_wq, p_q, BB * TT, EE, EE);
    gemm_simt8_db<<<gs8, 256>>>(x, p_wk, p_k, BB * TT, EE, EE);
    gemm_tf32x3<false><<<gs8, 256, SM3>>>(x, p_wv, p_v, BB * TT, EE, EE, 0, 0, 0, nullptr);

    // 3) fused attention (scores + mask + softmax + PV)
    dim3 gat(TT / 128, BB * HH, 1);
    attn_fused<<<gat, 256, SMA>>>();

    // 4) per-batch feature reduction (3xTF32)
    dim3 gfr(EE / 128, TT / 128, BB);
    gemm_tf32x3<false><<<gfr, 256, SM3>>>(p_zm, fr_w, p_zf, TT, EE, EE,
                                          (long)TT * EE, (long)EE * EE, (long)TT * EE,
                                          nullptr);

    // 5) LN1 over x + zf -> z1
    dim3 gred(64, BB, 1);
    ln_reduce<<<gred, 256>>>(x, p_zf);
    ln_finalize<<<BB, 64>>>();
    size_t total = (size_t)BB * LN_N;
    ln_norm<<<(unsigned)((total + 255) / 256), 256>>>(x, p_zf, ln1_w, ln1_b, p_z1);

    // 6) FFN: z2 = relu(z1 @ ff_w^T + ff_b) (3xTF32)
    gemm_tf32x3<true><<<gs8, 256, SM3>>>(p_z1, p_wff, p_z2, BB * TT, EE, EE, 0, 0, 0, ff_b);

    // 7) LN2 over z1 + z2 -> out
    ln_reduce<<<gred, 256>>>(p_z1, p_z2);
    ln_finalize<<<BB, 64>>>();
    ln_norm<<<(unsigned)((total + 255) / 256), 256>>>(p_z1, p_z2, ln2_w, ln2_b, out);
}

// round 7
// speedup vs baseline: 1.7156x; 1.0149x over previous
#include <cuda_runtime.h>
#include <math.h>
#include <stdint.h>

#define BB 4
#define TT 1024
#define EE 1024
#define HH 16
#define FFDIM 64
#define LN_N ((size_t)TT * EE)

// ---------------- scratch (static device globals; no allocation) -------------
__device__ float g_wq[EE * EE];
__device__ float g_wk[EE * EE];
__device__ float g_wv[EE * EE];
__device__ float g_wff[EE * EE];
__device__ float g_q[BB * TT * EE];   // [B, T, H*F]
__device__ float g_k[BB * TT * EE];
__device__ float g_v[BB * TT * EE];
__device__ float g_zm[BB * TT * EE];
__device__ float g_zf[BB * TT * EE];
__device__ float g_z1[BB * TT * EE];
__device__ float g_z2[BB * TT * EE];
__device__ double g_part[BB * 64 * 2];
__device__ float g_stats[BB * 2];

// ---------------- helpers ----------------------------------------------------
__device__ __forceinline__ uint32_t f2tf(float x) {
    uint32_t r;
    asm("cvt.rna.tf32.f32 %0, %1;" : "=r"(r) : "f"(x));
    return r;
}

__device__ __forceinline__ void mma8(float c[4], const uint32_t a[4], const uint32_t b[2]) {
    asm volatile(
        "mma.sync.aligned.m16n8k8.row.col.f32.tf32.tf32.f32 "
        "{%0,%1,%2,%3}, {%4,%5,%6,%7}, {%8,%9}, {%0,%1,%2,%3};\n"
        : "+f"(c[0]), "+f"(c[1]), "+f"(c[2]), "+f"(c[3])
        : "r"(a[0]), "r"(a[1]), "r"(a[2]), "r"(a[3]), "r"(b[0]), "r"(b[1]));
}

__device__ __forceinline__ uint32_t smem_u32(const void* p) {
    return (uint32_t)__cvta_generic_to_shared(p);
}
__device__ __forceinline__ void cpasync16(uint32_t dst, const void* src) {
    asm volatile("cp.async.ca.shared.global [%0], [%1], 16;\n" ::"r"(dst), "l"(src));
}

// ---------------- weight repacks ---------------------------------------------
__global__ void repack_qkv(const float* __restrict__ qw,
                           const float* __restrict__ kw,
                           const float* __restrict__ vw) {
    int idx = blockIdx.x * blockDim.x + threadIdx.x;
    if (idx >= EE * EE) return;
    int e = idx / EE, n = idx % EE;
    int h = n >> 6, f = n & 63;
    int src = h * (EE * FFDIM) + e * FFDIM + f;
    g_wq[idx] = qw[src];
    g_wk[idx] = kw[src];
    g_wv[idx] = vw[src];
}

__global__ void repack_ff(const float* __restrict__ w) {
    int idx = blockIdx.x * blockDim.x + threadIdx.x;
    if (idx >= EE * EE) return;
    int e = idx / EE, d = idx % EE;
    g_wff[idx] = w[d * EE + e];
}

// ---------------- fp32 SIMT GEMM for Q and K, double-buffered ----------------
// grid.z selects (B0,C0) or (B1,C1). B prefetch via cp.async (no data regs),
// A prefetch via 8 registers. Per-output fma chain: ascending k, fp32 —
// bit-identical to the R4/R5 kernels that passed.
__global__ __launch_bounds__(256, 2) void gemm_qk(
    const float* __restrict__ A, const float* __restrict__ B0,
    const float* __restrict__ B1, float* __restrict__ C0, float* __restrict__ C1,
    int M, int N, int K) {
    const float* Bm = blockIdx.z ? B1 : B0;
    float* C = blockIdx.z ? C1 : C0;
    __shared__ float As[2][16][132];  // [stage][k][m]
    __shared__ float Bs[2][16][128];  // [stage][k][n]
    int m0 = blockIdx.y * 128, n0 = blockIdx.x * 128;
    int tid = threadIdx.x;
    int ty = tid >> 4, tx = tid & 15;
    float acc[8][8] = {};
    int ar = tid >> 2;            // 0..63
    int ac4 = (tid & 3) * 4;      // 0,4,8,12
    int bk = tid >> 5;            // 0..7
    int bc4 = (tid & 31) * 4;     // 0..124

    uint32_t bd0[2], bd1[2];
    bd0[0] = smem_u32(&Bs[0][bk][bc4]);
    bd0[1] = smem_u32(&Bs[1][bk][bc4]);
    bd1[0] = smem_u32(&Bs[0][bk + 8][bc4]);
    bd1[1] = smem_u32(&Bs[1][bk + 8][bc4]);

    // prologue: tile 0
    cpasync16(bd0[0], &Bm[(size_t)bk * N + n0 + bc4]);
    cpasync16(bd1[0], &Bm[(size_t)(bk + 8) * N + n0 + bc4]);
    asm volatile("cp.async.commit_group;\n");
    float4 ra0 = *(const float4*)&A[(size_t)(m0 + ar) * K + ac4];
    float4 ra1 = *(const float4*)&A[(size_t)(m0 + ar + 64) * K + ac4];
    As[0][ac4 + 0][ar] = ra0.x; As[0][ac4 + 1][ar] = ra0.y;
    As[0][ac4 + 2][ar] = ra0.z; As[0][ac4 + 3][ar] = ra0.w;
    As[0][ac4 + 0][ar + 64] = ra1.x; As[0][ac4 + 1][ar + 64] = ra1.y;
    As[0][ac4 + 2][ar + 64] = ra1.z; As[0][ac4 + 3][ar + 64] = ra1.w;
    asm volatile("cp.async.wait_group 0;\n");
    __syncthreads();

    int nt = K / 16;
    for (int t = 0; t < nt; t++) {
        int s = t & 1;
        if (t + 1 < nt) {
            int k0 = (t + 1) * 16;
            cpasync16(bd0[s ^ 1], &Bm[(size_t)(k0 + bk) * N + n0 + bc4]);
            cpasync16(bd1[s ^ 1], &Bm[(size_t)(k0 + bk + 8) * N + n0 + bc4]);
            asm volatile("cp.async.commit_group;\n");
            ra0 = *(const float4*)&A[(size_t)(m0 + ar) * K + k0 + ac4];
            ra1 = *(const float4*)&A[(size_t)(m0 + ar + 64) * K + k0 + ac4];
        }
#pragma unroll
        for (int k = 0; k < 16; k++) {
            float a[8], b[8];
            *(float4*)&a[0] = *(const float4*)&As[s][k][ty * 8];
            *(float4*)&a[4] = *(const float4*)&As[s][k][ty * 8 + 4];
            *(float4*)&b[0] = *(const float4*)&Bs[s][k][tx * 8];
            *(float4*)&b[4] = *(const float4*)&Bs[s][k][tx * 8 + 4];
#pragma unroll
            for (int i = 0; i < 8; i++)
#pragma unroll
                for (int j = 0; j < 8; j++) acc[i][j] += a[i] * b[j];
        }
        if (t + 1 < nt) {
            int s2 = s ^ 1;
            As[s2][ac4 + 0][ar] = ra0.x; As[s2][ac4 + 1][ar] = ra0.y;
            As[s2][ac4 + 2][ar] = ra0.z; As[s2][ac4 + 3][ar] = ra0.w;
            As[s2][ac4 + 0][ar + 64] = ra1.x; As[s2][ac4 + 1][ar + 64] = ra1.y;
            As[s2][ac4 + 2][ar + 64] = ra1.z; As[s2][ac4 + 3][ar + 64] = ra1.w;
            asm volatile("cp.async.wait_group 0;\n");
        }
        __syncthreads();
    }
#pragma unroll
    for (int i = 0; i < 8; i++) {
        int m = m0 + ty * 8 + i;
        *(float4*)&C[(size_t)m * N + n0 + tx * 8] = *(float4*)&acc[i][0];
        *(float4*)&C[(size_t)m * N + n0 + tx * 8 + 4] = *(float4*)&acc[i][4];
    }
}

// ---------------- fused attention: scores (exact fp32) + softmax + PV --------
struct __align__(16) AttnSmem {
    float qs[64][132];      // [f][q]
    float ks[64][132];      // [f][k]
    uint32_t vhi[128][72];  // [k][f] tf32 hi
    uint32_t vlo[128][72];  // [k][f] tf32 lo
    uint32_t Ps[128][132];  // [q][k] tf32
    float sm_m[128];
    float sm_l[128];
    float sm_sc[128];
};

__global__ __launch_bounds__(256) void attn_fused() {
    extern __shared__ char smraw[];
    AttnSmem* S = (AttnSmem*)smraw;
    int bh = blockIdx.y;
    int b = bh / HH, h = bh % HH;
    int q0 = blockIdx.x * 128;
    const float* qp = g_q + (size_t)b * TT * EE + h * FFDIM;
    const float* kp = g_k + (size_t)b * TT * EE + h * FFDIM;
    const float* vp = g_v + (size_t)b * TT * EE + h * FFDIM;
    float* op = g_zm + (size_t)b * TT * EE + h * FFDIM;

    int tid = threadIdx.x;
    int ty = tid >> 4, tx = tid & 15;
    int lane = tid & 31, w = tid >> 5;
    int wm = w >> 1, wn = w & 1;
    int g = lane >> 2, tig = lane & 3;
    int ar = tid >> 2;
    int ac4 = (tid & 3) * 4;
    unsigned hm = (lane & 16) ? 0xffff0000u : 0x0000ffffu;  // half-warp mask

    // load Q tile (once)
#pragma unroll
    for (int c0 = 0; c0 < 64; c0 += 16) {
#pragma unroll
        for (int ri = 0; ri < 2; ri++) {
            int r = ar + ri * 64;
            const float4 va = *(const float4*)&qp[(size_t)(q0 + r) * EE + c0 + ac4];
            S->qs[c0 + ac4 + 0][r] = va.x;
            S->qs[c0 + ac4 + 1][r] = va.y;
            S->qs[c0 + ac4 + 2][r] = va.z;
            S->qs[c0 + ac4 + 3][r] = va.w;
        }
    }
    if (tid < 128) {
        S->sm_m[tid] = -INFINITY;
        S->sm_l[tid] = 0.0f;
    }
    float acc[2][4][4] = {};
    __syncthreads();

    for (int k0 = 0; k0 < TT; k0 += 128) {
        // load K tile (transposed) + V tile (pre-split tf32 hi/lo)
#pragma unroll
        for (int c0 = 0; c0 < 64; c0 += 16) {
#pragma unroll
            for (int ri = 0; ri < 2; ri++) {
                int r = ar + ri * 64;
                const float4 vb = *(const float4*)&kp[(size_t)(k0 + r) * EE + c0 + ac4];
                S->ks[c0 + ac4 + 0][r] = vb.x;
                S->ks[c0 + ac4 + 1][r] = vb.y;
                S->ks[c0 + ac4 + 2][r] = vb.z;
                S->ks[c0 + ac4 + 3][r] = vb.w;
            }
        }
        {
            int vr = tid >> 1;
            int vh = (tid & 1) * 32;
#pragma unroll
            for (int j = 0; j < 8; j++) {
                const float4 v = *(const float4*)&vp[(size_t)(k0 + vr) * EE + vh + j * 4];
                uint4 t, l;
                t.x = f2tf(v.x); t.y = f2tf(v.y); t.z = f2tf(v.z); t.w = f2tf(v.w);
                l.x = f2tf(v.x - __uint_as_float(t.x));
                l.y = f2tf(v.y - __uint_as_float(t.y));
                l.z = f2tf(v.z - __uint_as_float(t.z));
                l.w = f2tf(v.w - __uint_as_float(t.w));
                *(uint4*)&S->vhi[vr][vh + j * 4] = t;
                *(uint4*)&S->vlo[vr][vh + j * 4] = l;
            }
        }
        __syncthreads();

        // S tile: 8x8 per thread, ascending f (identical fp32 chain)
        float s[8][8] = {};
#pragma unroll
        for (int f = 0; f < 64; f++) {
            float a[8], bv[8];
            *(float4*)&a[0] = *(const float4*)&S->qs[f][ty * 8];
            *(float4*)&a[4] = *(const float4*)&S->qs[f][ty * 8 + 4];
            *(float4*)&bv[0] = *(const float4*)&S->ks[f][tx * 8];
            *(float4*)&bv[4] = *(const float4*)&S->ks[f][tx * 8 + 4];
#pragma unroll
            for (int i = 0; i < 8; i++)
#pragma unroll
                for (int j = 0; j < 8; j++) s[i][j] += a[i] * bv[j];
        }
        // mask + scale (identical expression)
#pragma unroll
        for (int i = 0; i < 8; i++) {
            int qg = q0 + ty * 8 + i;
#pragma unroll
            for (int j = 0; j < 8; j++) {
                int kg = k0 + tx * 8 + j;
                float m = (kg > qg) ? (1.0f - 1.0e9f) : 1.0f;
                s[i][j] = s[i][j] * m * 0.125f;
            }
        }
        // tile row max (reduce over 16 lanes)
        float tm[8];
#pragma unroll
        for (int i = 0; i < 8; i++) {
            float v = s[i][0];
#pragma unroll
            for (int j = 1; j < 8; j++) v = fmaxf(v, s[i][j]);
#pragma unroll
            for (int o = 8; o > 0; o >>= 1) v = fmaxf(v, __shfl_xor_sync(0xffffffffu, v, o));
            tm[i] = v;
        }
        if (tx == 0) {
#pragma unroll
            for (int i = 0; i < 8; i++) {
                int row = ty * 8 + i;
                float mo = S->sm_m[row];
                float mn = fmaxf(mo, tm[i]);
                S->sm_sc[row] = __expf(mo - mn);
                S->sm_m[row] = mn;
            }
        }
        __syncthreads();

        // P = exp(s - m_new); per-row skip when every exp underflows to 0.0f
        // (tm - mn <= -104 < ln(2^-149) makes the skip bit-exact)
#pragma unroll
        for (int i = 0; i < 8; i++) {
            int row = ty * 8 + i;
            float mn = S->sm_m[row];
            if (tm[i] - mn > -104.0f) {
                float rs = 0.0f;
                uint32_t pr[8];
#pragma unroll
                for (int j = 0; j < 8; j++) {
                    float p = __expf(s[i][j] - mn);
                    rs += p;
                    pr[j] = f2tf(p);
                }
                *(uint4*)&S->Ps[row][tx * 8] = make_uint4(pr[0], pr[1], pr[2], pr[3]);
                *(uint4*)&S->Ps[row][tx * 8 + 4] = make_uint4(pr[4], pr[5], pr[6], pr[7]);
#pragma unroll
                for (int o = 8; o > 0; o >>= 1) rs += __shfl_xor_sync(hm, rs, o);
                if (tx == 0) S->sm_l[row] = S->sm_l[row] * S->sm_sc[row] + rs;
            } else {
                uint4 z = make_uint4(0, 0, 0, 0);
                *(uint4*)&S->Ps[row][tx * 8] = z;
                *(uint4*)&S->Ps[row][tx * 8 + 4] = z;
                // sc == 1 and rs == 0 here, so sm_l is unchanged
            }
        }
        __syncthreads();

        // rescale O accumulators, then PV mma
#pragma unroll
        for (int mi = 0; mi < 2; mi++) {
            int row = wm * 32 + mi * 16 + g;
            float s0 = S->sm_sc[row], s1 = S->sm_sc[row + 8];
#pragma unroll
            for (int ni = 0; ni < 4; ni++) {
                acc[mi][ni][0] *= s0; acc[mi][ni][1] *= s0;
                acc[mi][ni][2] *= s1; acc[mi][ni][3] *= s1;
            }
        }
#pragma unroll
        for (int kk = 0; kk < 128; kk += 8) {
            uint32_t af[2][4];
#pragma unroll
            for (int mi = 0; mi < 2; mi++) {
                int mb = wm * 32 + mi * 16 + g;
                af[mi][0] = S->Ps[mb][kk + tig];
                af[mi][1] = S->Ps[mb + 8][kk + tig];
                af[mi][2] = S->Ps[mb][kk + tig + 4];
                af[mi][3] = S->Ps[mb + 8][kk + tig + 4];
            }
#pragma unroll
            for (int ni = 0; ni < 4; ni++) {
                int nb = wn * 32 + ni * 8 + g;
                uint32_t bf[2], bfl[2];
                bf[0] = S->vhi[kk + tig][nb];
                bf[1] = S->vhi[kk + tig + 4][nb];
                bfl[0] = S->vlo[kk + tig][nb];
                bfl[1] = S->vlo[kk + tig + 4][nb];
#pragma unroll
                for (int mi = 0; mi < 2; mi++) {
                    mma8(acc[mi][ni], af[mi], bfl);
                    mma8(acc[mi][ni], af[mi], bf);
                }
            }
        }
        __syncthreads();
    }
    // epilogue: O /= l, write merged heads
#pragma unroll
    for (int mi = 0; mi < 2; mi++) {
        int row = wm * 32 + mi * 16 + g;
        float i0 = 1.0f / S->sm_l[row];
        float i1 = 1.0f / S->sm_l[row + 8];
        int m = q0 + row;
#pragma unroll
        for (int ni = 0; ni < 4; ni++) {
            int n = wn * 32 + ni * 8 + tig * 2;
            *(float2*)&op[(size_t)m * EE + n] =
                make_float2(acc[mi][ni][0] * i0, acc[mi][ni][1] * i0);
            *(float2*)&op[(size_t)(m + 8) * EE + n] =
                make_float2(acc[mi][ni][2] * i1, acc[mi][ni][3] * i1);
        }
    }
}

// ---------------- 3xTF32 tensor-core GEMM (error-tolerant paths) -------------
template <bool RELU>
__global__ __launch_bounds__(256, 2) void gemm_tf32x3(
    const float* __restrict__ A, const float* __restrict__ Bm,
    float* __restrict__ C, int M, int N, int K,
    long sA, long sB, long sC, const float* __restrict__ bias) {
    extern __shared__ uint32_t sm_[];
    uint32_t(*As)[136] = (uint32_t(*)[136])sm_;
    uint32_t(*Bs)[136] = (uint32_t(*)[136])(sm_ + 16 * 136);
    uint32_t(*Asl)[136] = (uint32_t(*)[136])(sm_ + 2 * 16 * 136);
    uint32_t(*Bsl)[136] = (uint32_t(*)[136])(sm_ + 3 * 16 * 136);
    A += (size_t)blockIdx.z * sA;
    Bm += (size_t)blockIdx.z * sB;
    C += (size_t)blockIdx.z * sC;
    int m0 = blockIdx.y * 128, n0 = blockIdx.x * 128;
    int tid = threadIdx.x, lane = tid & 31, w = tid >> 5;
    int wm = w & 1, wn = w >> 1;
    int g = lane >> 2, tig = lane & 3;
    float acc[4][4][4] = {};
    int ar = tid >> 2;
    int ac4 = (tid & 3) * 4;
    int bk = tid >> 5;
    int bn4 = (tid & 31) * 4;

    for (int k0 = 0; k0 < K; k0 += 16) {
#pragma unroll
        for (int ri = 0; ri < 2; ri++) {
            const float4 v = *(const float4*)&A[(size_t)(m0 + ar + ri * 64) * K + k0 + ac4];
            int r = ar + ri * 64;
            uint32_t h0 = f2tf(v.x), h1 = f2tf(v.y), h2 = f2tf(v.z), h3 = f2tf(v.w);
            As[ac4 + 0][r] = h0;
            As[ac4 + 1][r] = h1;
            As[ac4 + 2][r] = h2;
            As[ac4 + 3][r] = h3;
            Asl[ac4 + 0][r] = f2tf(v.x - __uint_as_float(h0));
            Asl[ac4 + 1][r] = f2tf(v.y - __uint_as_float(h1));
            Asl[ac4 + 2][r] = f2tf(v.z - __uint_as_float(h2));
            Asl[ac4 + 3][r] = f2tf(v.w - __uint_as_float(h3));
        }
#pragma unroll
        for (int ki = 0; ki < 2; ki++) {
            const float4 v = *(const float4*)&Bm[(size_t)(k0 + bk + ki * 8) * N + n0 + bn4];
            uint4 t, l;
            t.x = f2tf(v.x); t.y = f2tf(v.y); t.z = f2tf(v.z); t.w = f2tf(v.w);
            l.x = f2tf(v.x - __uint_as_float(t.x));
            l.y = f2tf(v.y - __uint_as_float(t.y));
            l.z = f2tf(v.z - __uint_as_float(t.z));
            l.w = f2tf(v.w - __uint_as_float(t.w));
            *(uint4*)&Bs[bk + ki * 8][bn4] = t;
            *(uint4*)&Bsl[bk + ki * 8][bn4] = l;
        }
        __syncthreads();
#pragma unroll
        for (int kk = 0; kk < 16; kk += 8) {
            uint32_t af[4][4], afl[4][4];
#pragma unroll
            for (int mi = 0; mi < 4; mi++) {
                int mb = wm * 64 + mi * 16 + g;
                af[mi][0] = As[kk + tig][mb];
                af[mi][1] = As[kk + tig][mb + 8];
                af[mi][2] = As[kk + tig + 4][mb];
                af[mi][3] = As[kk + tig + 4][mb + 8];
                afl[mi][0] = Asl[kk + tig][mb];
                afl[mi][1] = Asl[kk + tig][mb + 8];
                afl[mi][2] = Asl[kk + tig + 4][mb];
                afl[mi][3] = Asl[kk + tig + 4][mb + 8];
            }
#pragma unroll
            for (int ni = 0; ni < 4; ni++) {
                int nb = wn * 32 + ni * 8 + g;
                uint32_t bf[2], bfl[2];
                bf[0] = Bs[kk + tig][nb];
                bf[1] = Bs[kk + tig + 4][nb];
                bfl[0] = Bsl[kk + tig][nb];
                bfl[1] = Bsl[kk + tig + 4][nb];
#pragma unroll
                for (int mi = 0; mi < 4; mi++) {
                    mma8(acc[mi][ni], af[mi], bfl);
                    mma8(acc[mi][ni], afl[mi], bf);
                    mma8(acc[mi][ni], af[mi], bf);
                }
            }
        }
        __syncthreads();
    }
#pragma unroll
    for (int mi = 0; mi < 4; mi++) {
        int m = m0 + wm * 64 + mi * 16 + g;
#pragma unroll
        for (int ni = 0; ni < 4; ni++) {
            int n = n0 + wn * 32 + ni * 8 + tig * 2;
            float b0 = bias ? bias[n] : 0.0f;
            float b1 = bias ? bias[n + 1] : 0.0f;
            float v0 = acc[mi][ni][0] + b0, v1 = acc[mi][ni][1] + b1;
            float v2 = acc[mi][ni][2] + b0, v3 = acc[mi][ni][3] + b1;
            if (RELU) {
                v0 = fmaxf(v0, 0.0f); v1 = fmaxf(v1, 0.0f);
                v2 = fmaxf(v2, 0.0f); v3 = fmaxf(v3, 0.0f);
            }
            *(float2*)&C[(size_t)m * N + n] = make_float2(v0, v1);
            *(float2*)&C[(size_t)(m + 8) * N + n] = make_float2(v2, v3);
        }
    }
}

// ---------------- LayerNorm over whole [T,E] plane per batch -----------------
__global__ __launch_bounds__(256) void ln_reduce(const float* __restrict__ in1,
                                                 const float* __restrict__ in2) {
    int b = blockIdx.y;
    const float* p1 = in1 + (size_t)b * LN_N;
    const float* p2 = in2 + (size_t)b * LN_N;
    const int chunk = (int)(LN_N / 64);
    size_t base = (size_t)blockIdx.x * chunk;
    double s = 0.0, sq = 0.0;
    for (int i = threadIdx.x; i < chunk; i += 256) {
        float x = p1[base + i] + p2[base + i];
        s += x;
        sq += (double)x * x;
    }
    __shared__ double sh[256], shq[256];
    int tid = threadIdx.x;
    sh[tid] = s;
    shq[tid] = sq;
    __syncthreads();
    for (int o = 128; o > 0; o >>= 1) {
        if (tid < o) {
            sh[tid] += sh[tid + o];
            shq[tid] += shq[tid + o];
        }
        __syncthreads();
    }
    if (tid == 0) {
        g_part[(b * 64 + blockIdx.x) * 2] = sh[0];
        g_part[(b * 64 + blockIdx.x) * 2 + 1] = shq[0];
    }
}

__global__ void ln_finalize() {
    int b = blockIdx.x;
    int tid = threadIdx.x;  // 64
    __shared__ double sh[64], shq[64];
    sh[tid] = g_part[(b * 64 + tid) * 2];
    shq[tid] = g_part[(b * 64 + tid) * 2 + 1];
    __syncthreads();
    for (int o = 32; o > 0; o >>= 1) {
        if (tid < o) {
            sh[tid] += sh[tid + o];
            shq[tid] += shq[tid + o];
        }
        __syncthreads();
    }
    if (tid == 0) {
        double n = (double)LN_N;
        double mean = sh[0] / n;
        double var = shq[0] / n - mean * mean;
        g_stats[b * 2] = (float)mean;
        g_stats[b * 2 + 1] = (float)(1.0 / sqrt(var + 1e-5));
    }
}

__global__ __launch_bounds__(256) void ln_norm(const float* __restrict__ in1,
                                               const float* __restrict__ in2,
                                               const float* __restrict__ w,
                                               const float* __restrict__ bia,
                                               float* __restrict__ out) {
    size_t i = (size_t)blockIdx.x * blockDim.x + threadIdx.x;
    if (i >= (size_t)BB * LN_N) return;
    int b = (int)(i / LN_N);
    size_t te = i % LN_N;
    float mean = g_stats[b * 2];
    float rstd = g_stats[b * 2 + 1];
    float x = in1[i] + in2[i];
    out[i] = (x - mean) * rstd * w[te] + bia[te];
}

// ---------------- launch -----------------------------------------------------
extern "C" void kernel_launch(void* const* d_in, const int* in_sizes, int n_in,
                              void* d_out, int out_size) {
    const float* x = (const float*)d_in[0];
    const float* q_w = (const float*)d_in[1];
    const float* k_w = (const float*)d_in[2];
    const float* v_w = (const float*)d_in[3];
    const float* fr_w = (const float*)d_in[4];
    const float* ff_w = (const float*)d_in[5];
    const float* ff_b = (const float*)d_in[6];
    const float* ln1_w = (const float*)d_in[7];
    const float* ln1_b = (const float*)d_in[8];
    const float* ln2_w = (const float*)d_in[9];
    const float* ln2_b = (const float*)d_in[10];
    float* out = (float*)d_out;

    float *p_wq, *p_wk, *p_wv, *p_wff, *p_q, *p_k, *p_v;
    float *p_zm, *p_zf, *p_z1, *p_z2;
    cudaGetSymbolAddress((void**)&p_wq, g_wq);
    cudaGetSymbolAddress((void**)&p_wk, g_wk);
    cudaGetSymbolAddress((void**)&p_wv, g_wv);
    cudaGetSymbolAddress((void**)&p_wff, g_wff);
    cudaGetSymbolAddress((void**)&p_q, g_q);
    cudaGetSymbolAddress((void**)&p_k, g_k);
    cudaGetSymbolAddress((void**)&p_v, g_v);
    cudaGetSymbolAddress((void**)&p_zm, g_zm);
    cudaGetSymbolAddress((void**)&p_zf, g_zf);
    cudaGetSymbolAddress((void**)&p_z1, g_z1);
    cudaGetSymbolAddress((void**)&p_z2, g_z2);

    const size_t SM3 = 4 * 16 * 136 * sizeof(uint32_t);
    const size_t SMA = sizeof(AttnSmem);
    cudaFuncSetAttribute(attn_fused, cudaFuncAttributeMaxDynamicSharedMemorySize, (int)SMA);

    // 1) repack weights
    repack_qkv<<<(EE * EE + 255) / 256, 256>>>(q_w, k_w, v_w);
    repack_ff<<<(EE * EE + 255) / 256, 256>>>(ff_w);

    // 2) Q,K in one launch: exact fp32 sequential-k, cp.async double-buffered;
    //    V: 3xTF32
    dim3 gqk(EE / 128, (BB * TT) / 128, 2);
    gemm_qk<<<gqk, 256>>>(x, p_wq, p_wk, p_q, p_k, BB * TT, EE, EE);
    dim3 gs8(EE / 128, (BB * TT) / 128, 1);
    gemm_tf32x3<false><<<gs8, 256, SM3>>>(x, p_wv, p_v, BB * TT, EE, EE, 0, 0, 0, nullptr);

    // 3) fused attention (scores + mask + softmax + PV)
    dim3 gat(TT / 128, BB * HH, 1);
    attn_fused<<<gat, 256, SMA>>>();

    // 4) per-batch feature reduction (3xTF32)
    dim3 gfr(EE / 128, TT / 128, BB);
    gemm_tf32x3<false><<<gfr, 256, SM3>>>(p_zm, fr_w, p_zf, TT, EE, EE,
                                          (long)TT * EE, (long)EE * EE, (long)TT * EE,
                                          nullptr);

    // 5) LN1 over x + zf -> z1
    dim3 gred(64, BB, 1);
    ln_reduce<<<gred, 256>>>(x, p_zf);
    ln_finalize<<<BB, 64>>>();
    size_t total = (size_t)BB * LN_N;
    ln_norm<<<(unsigned)((total + 255) / 256), 256>>>(x, p_zf, ln1_w, ln1_b, p_z1);

    // 6) FFN: z2 = relu(z1 @ ff_w^T + ff_b) (3xTF32)
    gemm_tf32x3<true><<<gs8, 256, SM3>>>(p_z1, p_wff, p_z2, BB * TT, EE, EE, 0, 0, 0, ff_b);

    // 7) LN2 over z1 + z2 -> out
    ln_reduce<<<gred, 256>>>(p_z1, p_z2);
    ln_finalize<<<BB, 64>>>();
    ln_norm<<<(unsigned)((total + 255) / 256), 256>>>(p_z1, p_z2, ln2_w, ln2_b, out);
}

// round 8
// speedup vs baseline: 1.7376x; 1.0128x over previous
#include <cuda_runtime.h>
#include <math.h>
#include <stdint.h>

#define BB 4
#define TT 1024
#define EE 1024
#define HH 16
#define FFDIM 64
#define LN_N ((size_t)TT * EE)

// ---------------- scratch (static device globals; no allocation) -------------
__device__ float g_wq[EE * EE];
__device__ float g_wk[EE * EE];
__device__ float g_q[BB * TT * EE];   // [B, T, H*F]
__device__ float g_k[BB * TT * EE];
__device__ float g_v[BB * TT * EE];
__device__ float g_zm[BB * TT * EE];
__device__ float g_zf[BB * TT * EE];
__device__ float g_z1[BB * TT * EE];
__device__ float g_z2[BB * TT * EE];
__device__ double g_part[BB * 64 * 2];
__device__ float g_stats[BB * 2];
// tf32 hi/lo splits
__device__ uint32_t g_wvhi[EE * EE];
__device__ uint32_t g_wvlo[EE * EE];
__device__ uint32_t g_wffhi[EE * EE];
__device__ uint32_t g_wfflo[EE * EE];
__device__ uint32_t g_frhi[BB * EE * EE];
__device__ uint32_t g_frlo[BB * EE * EE];
__device__ uint32_t g_athi[BB * TT * EE];  // transposed activation hi [K][M]
__device__ uint32_t g_atlo[BB * TT * EE];

// ---------------- helpers ----------------------------------------------------
__device__ __forceinline__ uint32_t f2tf(float x) {
    uint32_t r;
    asm("cvt.rna.tf32.f32 %0, %1;" : "=r"(r) : "f"(x));
    return r;
}

__device__ __forceinline__ void mma8(float c[4], const uint32_t a[4], const uint32_t b[2]) {
    asm volatile(
        "mma.sync.aligned.m16n8k8.row.col.f32.tf32.tf32.f32 "
        "{%0,%1,%2,%3}, {%4,%5,%6,%7}, {%8,%9}, {%0,%1,%2,%3};\n"
        : "+f"(c[0]), "+f"(c[1]), "+f"(c[2]), "+f"(c[3])
        : "r"(a[0]), "r"(a[1]), "r"(a[2]), "r"(a[3]), "r"(b[0]), "r"(b[1]));
}

__device__ __forceinline__ uint32_t smem_u32(const void* p) {
    return (uint32_t)__cvta_generic_to_shared(p);
}
__device__ __forceinline__ void cpasync16(uint32_t dst, const void* src) {
    asm volatile("cp.async.ca.shared.global [%0], [%1], 16;\n" ::"r"(dst), "l"(src));
}

// ---------------- weight repacks + splits ------------------------------------
__global__ void repack_qkv(const float* __restrict__ qw,
                           const float* __restrict__ kw,
                           const float* __restrict__ vw) {
    int idx = blockIdx.x * blockDim.x + threadIdx.x;
    if (idx >= EE * EE) return;
    int e = idx / EE, n = idx % EE;
    int h = n >> 6, f = n & 63;
    int src = h * (EE * FFDIM) + e * FFDIM + f;
    g_wq[idx] = qw[src];
    g_wk[idx] = kw[src];
    float v = vw[src];
    uint32_t hbits = f2tf(v);
    g_wvhi[idx] = hbits;
    g_wvlo[idx] = f2tf(v - __uint_as_float(hbits));
}

__global__ void repack_ff(const float* __restrict__ w) {
    int idx = blockIdx.x * blockDim.x + threadIdx.x;
    if (idx >= EE * EE) return;
    int e = idx / EE, d = idx % EE;
    float v = w[d * EE + e];
    uint32_t hbits = f2tf(v);
    g_wffhi[idx] = hbits;
    g_wfflo[idx] = f2tf(v - __uint_as_float(hbits));
}

__global__ void split_fr(const float* __restrict__ w) {
    int idx = blockIdx.x * blockDim.x + threadIdx.x;
    if (idx >= BB * EE * EE) return;
    float v = w[idx];
    uint32_t hbits = f2tf(v);
    g_frhi[idx] = hbits;
    g_frlo[idx] = f2tf(v - __uint_as_float(hbits));
}

// ---------------- tiled transpose + split: [nb][M][K] -> hi/lo [nb][K][M] ----
__global__ __launch_bounds__(256) void transpose_split(
    const float* __restrict__ in, uint32_t* __restrict__ ohi,
    uint32_t* __restrict__ olo, int M, int K) {
    __shared__ float t[32][33];
    size_t bo = (size_t)blockIdx.z * M * K;
    in += bo; ohi += bo; olo += bo;
    int m0 = blockIdx.y * 32, k0 = blockIdx.x * 32;
    int tx = threadIdx.x & 31, ty = threadIdx.x >> 5;
#pragma unroll
    for (int i = ty; i < 32; i += 8) t[i][tx] = in[(size_t)(m0 + i) * K + k0 + tx];
    __syncthreads();
#pragma unroll
    for (int i = ty; i < 32; i += 8) {
        float v = t[tx][i];
        uint32_t hbits = f2tf(v);
        size_t o = (size_t)(k0 + i) * M + m0 + tx;
        ohi[o] = hbits;
        olo[o] = f2tf(v - __uint_as_float(hbits));
    }
}

// ---------------- fp32 SIMT GEMM for Q and K, double-buffered ----------------
// Per-output fma chain: ascending k, fp32 — bit-identical to passing kernels.
__global__ __launch_bounds__(256, 2) void gemm_qk(
    const float* __restrict__ A, const float* __restrict__ B0,
    const float* __restrict__ B1, float* __restrict__ C0, float* __restrict__ C1,
    int M, int N, int K) {
    const float* Bm = blockIdx.z ? B1 : B0;
    float* C = blockIdx.z ? C1 : C0;
    __shared__ float As[2][16][132];
    __shared__ float Bs[2][16][128];
    int m0 = blockIdx.y * 128, n0 = blockIdx.x * 128;
    int tid = threadIdx.x;
    int ty = tid >> 4, tx = tid & 15;
    float acc[8][8] = {};
    int ar = tid >> 2;
    int ac4 = (tid & 3) * 4;
    int bk = tid >> 5;
    int bc4 = (tid & 31) * 4;

    uint32_t bd0[2], bd1[2];
    bd0[0] = smem_u32(&Bs[0][bk][bc4]);
    bd0[1] = smem_u32(&Bs[1][bk][bc4]);
    bd1[0] = smem_u32(&Bs[0][bk + 8][bc4]);
    bd1[1] = smem_u32(&Bs[1][bk + 8][bc4]);

    cpasync16(bd0[0], &Bm[(size_t)bk * N + n0 + bc4]);
    cpasync16(bd1[0], &Bm[(size_t)(bk + 8) * N + n0 + bc4]);
    asm volatile("cp.async.commit_group;\n");
    float4 ra0 = *(const float4*)&A[(size_t)(m0 + ar) * K + ac4];
    float4 ra1 = *(const float4*)&A[(size_t)(m0 + ar + 64) * K + ac4];
    As[0][ac4 + 0][ar] = ra0.x; As[0][ac4 + 1][ar] = ra0.y;
    As[0][ac4 + 2][ar] = ra0.z; As[0][ac4 + 3][ar] = ra0.w;
    As[0][ac4 + 0][ar + 64] = ra1.x; As[0][ac4 + 1][ar + 64] = ra1.y;
    As[0][ac4 + 2][ar + 64] = ra1.z; As[0][ac4 + 3][ar + 64] = ra1.w;
    asm volatile("cp.async.wait_group 0;\n");
    __syncthreads();

    int nt = K / 16;
    for (int t = 0; t < nt; t++) {
        int s = t & 1;
        if (t + 1 < nt) {
            int k0 = (t + 1) * 16;
            cpasync16(bd0[s ^ 1], &Bm[(size_t)(k0 + bk) * N + n0 + bc4]);
            cpasync16(bd1[s ^ 1], &Bm[(size_t)(k0 + bk + 8) * N + n0 + bc4]);
            asm volatile("cp.async.commit_group;\n");
            ra0 = *(const float4*)&A[(size_t)(m0 + ar) * K + k0 + ac4];
            ra1 = *(const float4*)&A[(size_t)(m0 + ar + 64) * K + k0 + ac4];
        }
#pragma unroll
        for (int k = 0; k < 16; k++) {
            float a[8], b[8];
            *(float4*)&a[0] = *(const float4*)&As[s][k][ty * 8];
            *(float4*)&a[4] = *(const float4*)&As[s][k][ty * 8 + 4];
            *(float4*)&b[0] = *(const float4*)&Bs[s][k][tx * 8];
            *(float4*)&b[4] = *(const float4*)&Bs[s][k][tx * 8 + 4];
#pragma unroll
            for (int i = 0; i < 8; i++)
#pragma unroll
                for (int j = 0; j < 8; j++) acc[i][j] += a[i] * b[j];
        }
        if (t + 1 < nt) {
            int s2 = s ^ 1;
            As[s2][ac4 + 0][ar] = ra0.x; As[s2][ac4 + 1][ar] = ra0.y;
            As[s2][ac4 + 2][ar] = ra0.z; As[s2][ac4 + 3][ar] = ra0.w;
            As[s2][ac4 + 0][ar + 64] = ra1.x; As[s2][ac4 + 1][ar + 64] = ra1.y;
            As[s2][ac4 + 2][ar + 64] = ra1.z; As[s2][ac4 + 3][ar + 64] = ra1.w;
            asm volatile("cp.async.wait_group 0;\n");
        }
        __syncthreads();
    }
#pragma unroll
    for (int i = 0; i < 8; i++) {
        int m = m0 + ty * 8 + i;
        *(float4*)&C[(size_t)m * N + n0 + tx * 8] = *(float4*)&acc[i][0];
        *(float4*)&C[(size_t)m * N + n0 + tx * 8 + 4] = *(float4*)&acc[i][4];
    }
}

// ---------------- pure-MMA 3xTF32 GEMM with presplit operands ----------------
// A: hi/lo [K][M] (pre-transposed), B: hi/lo [K][N]. Fully cp.async
// double-buffered, zero conversion instructions inside the kernel.
// smem layout: [stage][stream(Ahi,Alo,Bhi,Blo)][16][136] uint32
#define PRE_STAGE_U32 (4 * 16 * 136)
template <bool RELU>
__global__ __launch_bounds__(256, 2) void gemm_pre(
    const uint32_t* __restrict__ Ahi, const uint32_t* __restrict__ Alo,
    const uint32_t* __restrict__ Bhi, const uint32_t* __restrict__ Blo,
    float* __restrict__ C, int M, int N, int K,
    long sA, long sB, long sC, const float* __restrict__ bias) {
    extern __shared__ uint32_t smp[];
    Ahi += (size_t)blockIdx.z * sA;
    Alo += (size_t)blockIdx.z * sA;
    Bhi += (size_t)blockIdx.z * sB;
    Blo += (size_t)blockIdx.z * sB;
    C += (size_t)blockIdx.z * sC;
    int m0 = blockIdx.y * 128, n0 = blockIdx.x * 128;
    int tid = threadIdx.x, lane = tid & 31, w = tid >> 5;
    int wm = w & 1, wn = w >> 1;
    int g = lane >> 2, tig = lane & 3;
    float acc[4][4][4] = {};

    int crow = tid >> 4;            // 0..15
    int col0 = (tid & 15) * 4;      // 0..60
    uint32_t sbase = smem_u32(smp);
    // byte offsets for this thread's 8 chunks within a stage
    uint32_t offA0 = ((0 * 16 + crow) * 136 + col0) * 4;
    uint32_t offB0 = ((2 * 16 + crow) * 136 + col0) * 4;
    const uint32_t STAGE_B = PRE_STAGE_U32 * 4;
    const uint32_t STREAM_B = 16 * 136 * 4;

    // prologue: tile 0 into stage 0
    {
        const uint32_t* ga = &Ahi[(size_t)crow * M + m0 + col0];
        const uint32_t* gal = &Alo[(size_t)crow * M + m0 + col0];
        const uint32_t* gb = &Bhi[(size_t)crow * N + n0 + col0];
        const uint32_t* gbl = &Blo[(size_t)crow * N + n0 + col0];
        cpasync16(sbase + offA0, ga);
        cpasync16(sbase + offA0 + 256, ga + 64);
        cpasync16(sbase + offA0 + STREAM_B, gal);
        cpasync16(sbase + offA0 + STREAM_B + 256, gal + 64);
        cpasync16(sbase + offB0, gb);
        cpasync16(sbase + offB0 + 256, gb + 64);
        cpasync16(sbase + offB0 + STREAM_B, gbl);
        cpasync16(sbase + offB0 + STREAM_B + 256, gbl + 64);
        asm volatile("cp.async.commit_group;\n");
        asm volatile("cp.async.wait_group 0;\n");
    }
    __syncthreads();

    int nt = K / 16;
    for (int t = 0; t < nt; t++) {
        int s = t & 1;
        if (t + 1 < nt) {
            int k0 = (t + 1) * 16;
            uint32_t dst = sbase + (s ^ 1) * STAGE_B;
            const uint32_t* ga = &Ahi[(size_t)(k0 + crow) * M + m0 + col0];
            const uint32_t* gal = &Alo[(size_t)(k0 + crow) * M + m0 + col0];
            const uint32_t* gb = &Bhi[(size_t)(k0 + crow) * N + n0 + col0];
            const uint32_t* gbl = &Blo[(size_t)(k0 + crow) * N + n0 + col0];
            cpasync16(dst + offA0, ga);
            cpasync16(dst + offA0 + 256, ga + 64);
            cpasync16(dst + offA0 + STREAM_B, gal);
            cpasync16(dst + offA0 + STREAM_B + 256, gal + 64);
            cpasync16(dst + offB0, gb);
            cpasync16(dst + offB0 + 256, gb + 64);
            cpasync16(dst + offB0 + STREAM_B, gbl);
            cpasync16(dst + offB0 + STREAM_B + 256, gbl + 64);
            asm volatile("cp.async.commit_group;\n");
        }
        const uint32_t* As = smp + s * PRE_STAGE_U32;
        const uint32_t* Asl = As + 16 * 136;
        const uint32_t* Bs = Asl + 16 * 136;
        const uint32_t* Bsl = Bs + 16 * 136;
#pragma unroll
        for (int kk = 0; kk < 16; kk += 8) {
            uint32_t af[4][4], afl[4][4];
#pragma unroll
            for (int mi = 0; mi < 4; mi++) {
                int mb = wm * 64 + mi * 16 + g;
                af[mi][0] = As[(kk + tig) * 136 + mb];
                af[mi][1] = As[(kk + tig) * 136 + mb + 8];
                af[mi][2] = As[(kk + tig + 4) * 136 + mb];
                af[mi][3] = As[(kk + tig + 4) * 136 + mb + 8];
                afl[mi][0] = Asl[(kk + tig) * 136 + mb];
                afl[mi][1] = Asl[(kk + tig) * 136 + mb + 8];
                afl[mi][2] = Asl[(kk + tig + 4) * 136 + mb];
                afl[mi][3] = Asl[(kk + tig + 4) * 136 + mb + 8];
            }
#pragma unroll
            for (int ni = 0; ni < 4; ni++) {
                int nb = wn * 32 + ni * 8 + g;
                uint32_t bf[2], bfl[2];
                bf[0] = Bs[(kk + tig) * 136 + nb];
                bf[1] = Bs[(kk + tig + 4) * 136 + nb];
                bfl[0] = Bsl[(kk + tig) * 136 + nb];
                bfl[1] = Bsl[(kk + tig + 4) * 136 + nb];
#pragma unroll
                for (int mi = 0; mi < 4; mi++) {
                    mma8(acc[mi][ni], af[mi], bfl);
                    mma8(acc[mi][ni], afl[mi], bf);
                    mma8(acc[mi][ni], af[mi], bf);
                }
            }
        }
        if (t + 1 < nt) asm volatile("cp.async.wait_group 0;\n");
        __syncthreads();
    }
#pragma unroll
    for (int mi = 0; mi < 4; mi++) {
        int m = m0 + wm * 64 + mi * 16 + g;
#pragma unroll
        for (int ni = 0; ni < 4; ni++) {
            int n = n0 + wn * 32 + ni * 8 + tig * 2;
            float b0 = bias ? bias[n] : 0.0f;
            float b1 = bias ? bias[n + 1] : 0.0f;
            float v0 = acc[mi][ni][0] + b0, v1 = acc[mi][ni][1] + b1;
            float v2 = acc[mi][ni][2] + b0, v3 = acc[mi][ni][3] + b1;
            if (RELU) {
                v0 = fmaxf(v0, 0.0f); v1 = fmaxf(v1, 0.0f);
                v2 = fmaxf(v2, 0.0f); v3 = fmaxf(v3, 0.0f);
            }
            *(float2*)&C[(size_t)m * N + n] = make_float2(v0, v1);
            *(float2*)&C[(size_t)(m + 8) * N + n] = make_float2(v2, v3);
        }
    }
}

// ---------------- fused attention: scores (exact fp32) + softmax + PV --------
struct __align__(16) AttnSmem {
    float qs[64][132];
    float ks[64][132];
    uint32_t vhi[128][72];
    uint32_t vlo[128][72];
    uint32_t Ps[128][132];
    float sm_m[128];
    float sm_l[128];
    float sm_sc[128];
};

__global__ __launch_bounds__(256) void attn_fused() {
    extern __shared__ char smraw[];
    AttnSmem* S = (AttnSmem*)smraw;
    int bh = blockIdx.y;
    int b = bh / HH, h = bh % HH;
    int q0 = blockIdx.x * 128;
    const float* qp = g_q + (size_t)b * TT * EE + h * FFDIM;
    const float* kp = g_k + (size_t)b * TT * EE + h * FFDIM;
    const float* vp = g_v + (size_t)b * TT * EE + h * FFDIM;
    float* op = g_zm + (size_t)b * TT * EE + h * FFDIM;

    int tid = threadIdx.x;
    int ty = tid >> 4, tx = tid & 15;
    int lane = tid & 31, w = tid >> 5;
    int wm = w >> 1, wn = w & 1;
    int g = lane >> 2, tig = lane & 3;
    int ar = tid >> 2;
    int ac4 = (tid & 3) * 4;
    unsigned hm = (lane & 16) ? 0xffff0000u : 0x0000ffffu;

#pragma unroll
    for (int c0 = 0; c0 < 64; c0 += 16) {
#pragma unroll
        for (int ri = 0; ri < 2; ri++) {
            int r = ar + ri * 64;
            const float4 va = *(const float4*)&qp[(size_t)(q0 + r) * EE + c0 + ac4];
            S->qs[c0 + ac4 + 0][r] = va.x;
            S->qs[c0 + ac4 + 1][r] = va.y;
            S->qs[c0 + ac4 + 2][r] = va.z;
            S->qs[c0 + ac4 + 3][r] = va.w;
        }
    }
    if (tid < 128) {
        S->sm_m[tid] = -INFINITY;
        S->sm_l[tid] = 0.0f;
    }
    float acc[2][4][4] = {};
    __syncthreads();

    for (int k0 = 0; k0 < TT; k0 += 128) {
#pragma unroll
        for (int c0 = 0; c0 < 64; c0 += 16) {
#pragma unroll
            for (int ri = 0; ri < 2; ri++) {
                int r = ar + ri * 64;
                const float4 vb = *(const float4*)&kp[(size_t)(k0 + r) * EE + c0 + ac4];
                S->ks[c0 + ac4 + 0][r] = vb.x;
                S->ks[c0 + ac4 + 1][r] = vb.y;
                S->ks[c0 + ac4 + 2][r] = vb.z;
                S->ks[c0 + ac4 + 3][r] = vb.w;
            }
        }
        {
            int vr = tid >> 1;
            int vh = (tid & 1) * 32;
#pragma unroll
            for (int j = 0; j < 8; j++) {
                const float4 v = *(const float4*)&vp[(size_t)(k0 + vr) * EE + vh + j * 4];
                uint4 t, l;
                t.x = f2tf(v.x); t.y = f2tf(v.y); t.z = f2tf(v.z); t.w = f2tf(v.w);
                l.x = f2tf(v.x - __uint_as_float(t.x));
                l.y = f2tf(v.y - __uint_as_float(t.y));
                l.z = f2tf(v.z - __uint_as_float(t.z));
                l.w = f2tf(v.w - __uint_as_float(t.w));
                *(uint4*)&S->vhi[vr][vh + j * 4] = t;
                *(uint4*)&S->vlo[vr][vh + j * 4] = l;
            }
        }
        __syncthreads();

        float s[8][8] = {};
#pragma unroll
        for (int f = 0; f < 64; f++) {
            float a[8], bv[8];
            *(float4*)&a[0] = *(const float4*)&S->qs[f][ty * 8];
            *(float4*)&a[4] = *(const float4*)&S->qs[f][ty * 8 + 4];
            *(float4*)&bv[0] = *(const float4*)&S->ks[f][tx * 8];
            *(float4*)&bv[4] = *(const float4*)&S->ks[f][tx * 8 + 4];
#pragma unroll
            for (int i = 0; i < 8; i++)
#pragma unroll
                for (int j = 0; j < 8; j++) s[i][j] += a[i] * bv[j];
        }
#pragma unroll
        for (int i = 0; i < 8; i++) {
            int qg = q0 + ty * 8 + i;
#pragma unroll
            for (int j = 0; j < 8; j++) {
                int kg = k0 + tx * 8 + j;
                float m = (kg > qg) ? (1.0f - 1.0e9f) : 1.0f;
                s[i][j] = s[i][j] * m * 0.125f;
            }
        }
        float tm[8];
#pragma unroll
        for (int i = 0; i < 8; i++) {
            float v = s[i][0];
#pragma unroll
            for (int j = 1; j < 8; j++) v = fmaxf(v, s[i][j]);
#pragma unroll
            for (int o = 8; o > 0; o >>= 1) v = fmaxf(v, __shfl_xor_sync(0xffffffffu, v, o));
            tm[i] = v;
        }
        if (tx == 0) {
#pragma unroll
            for (int i = 0; i < 8; i++) {
                int row = ty * 8 + i;
                float mo = S->sm_m[row];
                float mn = fmaxf(mo, tm[i]);
                S->sm_sc[row] = __expf(mo - mn);
                S->sm_m[row] = mn;
            }
        }
        __syncthreads();

#pragma unroll
        for (int i = 0; i < 8; i++) {
            int row = ty * 8 + i;
            float mn = S->sm_m[row];
            if (tm[i] - mn > -104.0f) {
                float rs = 0.0f;
                uint32_t pr[8];
#pragma unroll
                for (int j = 0; j < 8; j++) {
                    float p = __expf(s[i][j] - mn);
                    rs += p;
                    pr[j] = f2tf(p);
                }
                *(uint4*)&S->Ps[row][tx * 8] = make_uint4(pr[0], pr[1], pr[2], pr[3]);
                *(uint4*)&S->Ps[row][tx * 8 + 4] = make_uint4(pr[4], pr[5], pr[6], pr[7]);
#pragma unroll
                for (int o = 8; o > 0; o >>= 1) rs += __shfl_xor_sync(hm, rs, o);
                if (tx == 0) S->sm_l[row] = S->sm_l[row] * S->sm_sc[row] + rs;
            } else {
                uint4 z = make_uint4(0, 0, 0, 0);
                *(uint4*)&S->Ps[row][tx * 8] = z;
                *(uint4*)&S->Ps[row][tx * 8 + 4] = z;
            }
        }
        __syncthreads();

#pragma unroll
        for (int mi = 0; mi < 2; mi++) {
            int row = wm * 32 + mi * 16 + g;
            float s0 = S->sm_sc[row], s1 = S->sm_sc[row + 8];
#pragma unroll
            for (int ni = 0; ni < 4; ni++) {
                acc[mi][ni][0] *= s0; acc[mi][ni][1] *= s0;
                acc[mi][ni][2] *= s1; acc[mi][ni][3] *= s1;
            }
        }
#pragma unroll
        for (int kk = 0; kk < 128; kk += 8) {
            uint32_t af[2][4];
#pragma unroll
            for (int mi = 0; mi < 2; mi++) {
                int mb = wm * 32 + mi * 16 + g;
                af[mi][0] = S->Ps[mb][kk + tig];
                af[mi][1] = S->Ps[mb + 8][kk + tig];
                af[mi][2] = S->Ps[mb][kk + tig + 4];
                af[mi][3] = S->Ps[mb + 8][kk + tig + 4];
            }
#pragma unroll
            for (int ni = 0; ni < 4; ni++) {
                int nb = wn * 32 + ni * 8 + g;
                uint32_t bf[2], bfl[2];
                bf[0] = S->vhi[kk + tig][nb];
                bf[1] = S->vhi[kk + tig + 4][nb];
                bfl[0] = S->vlo[kk + tig][nb];
                bfl[1] = S->vlo[kk + tig + 4][nb];
#pragma unroll
                for (int mi = 0; mi < 2; mi++) {
                    mma8(acc[mi][ni], af[mi], bfl);
                    mma8(acc[mi][ni], af[mi], bf);
                }
            }
        }
        __syncthreads();
    }
#pragma unroll
    for (int mi = 0; mi < 2; mi++) {
        int row = wm * 32 + mi * 16 + g;
        float i0 = 1.0f / S->sm_l[row];
        float i1 = 1.0f / S->sm_l[row + 8];
        int m = q0 + row;
#pragma unroll
        for (int ni = 0; ni < 4; ni++) {
            int n = wn * 32 + ni * 8 + tig * 2;
            *(float2*)&op[(size_t)m * EE + n] =
                make_float2(acc[mi][ni][0] * i0, acc[mi][ni][1] * i0);
            *(float2*)&op[(size_t)(m + 8) * EE + n] =
                make_float2(acc[mi][ni][2] * i1, acc[mi][ni][3] * i1);
        }
    }
}

// ---------------- LayerNorm over whole [T,E] plane per batch -----------------
__global__ __launch_bounds__(256) void ln_reduce(const float* __restrict__ in1,
                                                 const float* __restrict__ in2) {
    int b = blockIdx.y;
    const float* p1 = in1 + (size_t)b * LN_N;
    const float* p2 = in2 + (size_t)b * LN_N;
    const int chunk = (int)(LN_N / 64);
    size_t base = (size_t)blockIdx.x * chunk;
    double s = 0.0, sq = 0.0;
    for (int i = threadIdx.x; i < chunk; i += 256) {
        float x = p1[base + i] + p2[base + i];
        s += x;
        sq += (double)x * x;
    }
    __shared__ double sh[256], shq[256];
    int tid = threadIdx.x;
    sh[tid] = s;
    shq[tid] = sq;
    __syncthreads();
    for (int o = 128; o > 0; o >>= 1) {
        if (tid < o) {
            sh[tid] += sh[tid + o];
            shq[tid] += shq[tid + o];
        }
        __syncthreads();
    }
    if (tid == 0) {
        g_part[(b * 64 + blockIdx.x) * 2] = sh[0];
        g_part[(b * 64 + blockIdx.x) * 2 + 1] = shq[0];
    }
}

__global__ void ln_finalize() {
    int b = blockIdx.x;
    int tid = threadIdx.x;
    __shared__ double sh[64], shq[64];
    sh[tid] = g_part[(b * 64 + tid) * 2];
    shq[tid] = g_part[(b * 64 + tid) * 2 + 1];
    __syncthreads();
    for (int o = 32; o > 0; o >>= 1) {
        if (tid < o) {
            sh[tid] += sh[tid + o];
            shq[tid] += shq[tid + o];
        }
        __syncthreads();
    }
    if (tid == 0) {
        double n = (double)LN_N;
        double mean = sh[0] / n;
        double var = shq[0] / n - mean * mean;
        g_stats[b * 2] = (float)mean;
        g_stats[b * 2 + 1] = (float)(1.0 / sqrt(var + 1e-5));
    }
}

__global__ __launch_bounds__(256) void ln_norm(const float* __restrict__ in1,
                                               const float* __restrict__ in2,
                                               const float* __restrict__ w,
                                               const float* __restrict__ bia,
                                               float* __restrict__ out) {
    size_t i = (size_t)blockIdx.x * blockDim.x + threadIdx.x;
    if (i >= (size_t)BB * LN_N) return;
    int b = (int)(i / LN_N);
    size_t te = i % LN_N;
    float mean = g_stats[b * 2];
    float rstd = g_stats[b * 2 + 1];
    float x = in1[i] + in2[i];
    out[i] = (x - mean) * rstd * w[te] + bia[te];
}

// ---------------- launch -----------------------------------------------------
extern "C" void kernel_launch(void* const* d_in, const int* in_sizes, int n_in,
                              void* d_out, int out_size) {
    const float* x = (const float*)d_in[0];
    const float* q_w = (const float*)d_in[1];
    const float* k_w = (const float*)d_in[2];
    const float* v_w = (const float*)d_in[3];
    const float* fr_w = (const float*)d_in[4];
    const float* ff_w = (const float*)d_in[5];
    const float* ff_b = (const float*)d_in[6];
    const float* ln1_w = (const float*)d_in[7];
    const float* ln1_b = (const float*)d_in[8];
    const float* ln2_w = (const float*)d_in[9];
    const float* ln2_b = (const float*)d_in[10];
    float* out = (float*)d_out;

    float *p_wq, *p_wk, *p_q, *p_k, *p_v, *p_zm, *p_zf, *p_z1, *p_z2;
    uint32_t *p_wvhi, *p_wvlo, *p_wffhi, *p_wfflo, *p_frhi, *p_frlo, *p_athi, *p_atlo;
    cudaGetSymbolAddress((void**)&p_wq, g_wq);
    cudaGetSymbolAddress((void**)&p_wk, g_wk);
    cudaGetSymbolAddress((void**)&p_q, g_q);
    cudaGetSymbolAddress((void**)&p_k, g_k);
    cudaGetSymbolAddress((void**)&p_v, g_v);
    cudaGetSymbolAddress((void**)&p_zm, g_zm);
    cudaGetSymbolAddress((void**)&p_zf, g_zf);
    cudaGetSymbolAddress((void**)&p_z1, g_z1);
    cudaGetSymbolAddress((void**)&p_z2, g_z2);
    cudaGetSymbolAddress((void**)&p_wvhi, g_wvhi);
    cudaGetSymbolAddress((void**)&p_wvlo, g_wvlo);
    cudaGetSymbolAddress((void**)&p_wffhi, g_wffhi);
    cudaGetSymbolAddress((void**)&p_wfflo, g_wfflo);
    cudaGetSymbolAddress((void**)&p_frhi, g_frhi);
    cudaGetSymbolAddress((void**)&p_frlo, g_frlo);
    cudaGetSymbolAddress((void**)&p_athi, g_athi);
    cudaGetSymbolAddress((void**)&p_atlo, g_atlo);

    const size_t SMP = 2 * PRE_STAGE_U32 * sizeof(uint32_t);  // 69632 B
    const size_t SMA = sizeof(AttnSmem);
    cudaFuncSetAttribute(attn_fused, cudaFuncAttributeMaxDynamicSharedMemorySize, (int)SMA);
    cudaFuncSetAttribute(gemm_pre<false>, cudaFuncAttributeMaxDynamicSharedMemorySize, (int)SMP);
    cudaFuncSetAttribute(gemm_pre<true>, cudaFuncAttributeMaxDynamicSharedMemorySize, (int)SMP);

    // 1) weight repacks + splits
    repack_qkv<<<(EE * EE + 255) / 256, 256>>>(q_w, k_w, v_w);
    repack_ff<<<(EE * EE + 255) / 256, 256>>>(ff_w);
    split_fr<<<(BB * EE * EE + 255) / 256, 256>>>(fr_w);

    // 2) Q,K: exact fp32 sequential-k (one launch, grid.z=2)
    dim3 gqk(EE / 128, (BB * TT) / 128, 2);
    gemm_qk<<<gqk, 256>>>(x, p_wq, p_wk, p_q, p_k, BB * TT, EE, EE);

    // 3) V = x @ wv (3xTF32, presplit): transpose+split x, then pure MMA GEMM
    dim3 gtx(EE / 32, (BB * TT) / 32, 1);
    transpose_split<<<gtx, 256>>>(x, p_athi, p_atlo, BB * TT, EE);
    dim3 gv(EE / 128, (BB * TT) / 128, 1);
    gemm_pre<false><<<gv, 256, SMP>>>(p_athi, p_atlo, p_wvhi, p_wvlo, p_v,
                                      BB * TT, EE, EE, 0, 0, 0, nullptr);

    // 4) fused attention
    dim3 gat(TT / 128, BB * HH, 1);
    attn_fused<<<gat, 256, SMA>>>();

    // 5) zf[b] = zm[b] @ fr[b] (3xTF32, presplit, batched)
    dim3 gtz(EE / 32, TT / 32, BB);
    transpose_split<<<gtz, 256>>>(p_zm, p_athi, p_atlo, TT, EE);
    dim3 gfr(EE / 128, TT / 128, BB);
    gemm_pre<false><<<gfr, 256, SMP>>>(p_athi, p_atlo, p_frhi, p_frlo, p_zf,
                                       TT, EE, EE, (long)TT * EE, (long)EE * EE,
                                       (long)TT * EE, nullptr);

    // 6) LN1 over x + zf -> z1
    dim3 gred(64, BB, 1);
    ln_reduce<<<gred, 256>>>(x, p_zf);
    ln_finalize<<<BB, 64>>>();
    size_t total = (size_t)BB * LN_N;
    ln_norm<<<(unsigned)((total + 255) / 256), 256>>>(x, p_zf, ln1_w, ln1_b, p_z1);

    // 7) FFN: z2 = relu(z1 @ ff_w^T + ff_b)
    transpose_split<<<gtx, 256>>>(p_z1, p_athi, p_atlo, BB * TT, EE);
    gemm_pre<true><<<gv, 256, SMP>>>(p_athi, p_atlo, p_wffhi, p_wfflo, p_z2,
                                     BB * TT, EE, EE, 0, 0, 0, ff_b);

    // 8) LN2 over z1 + z2 -> out
    ln_reduce<<<gred, 256>>>(p_z1, p_z2);
    ln_finalize<<<BB, 64>>>();
    ln_norm<<<(unsigned)((total + 255) / 256), 256>>>(p_z1, p_z2, ln2_w, ln2_b, out);
}

// round 9
// speedup vs baseline: 1.9217x; 1.1059x over previous
#include <cuda_runtime.h>
#include <math.h>
#include <stdint.h>

#define BB 4
#define TT 1024
#define EE 1024
#define HH 16
#define FFDIM 64
#define LN_N ((size_t)TT * EE)

// ---------------- scratch (static device globals; no allocation) -------------
__device__ float g_wq[EE * EE];
__device__ float g_wk[EE * EE];
__device__ float g_q[BB * TT * EE];   // [B, T, H*F]
__device__ float g_k[BB * TT * EE];
__device__ float g_v[BB * TT * EE];
__device__ float g_zm[BB * TT * EE];
__device__ float g_zf[BB * TT * EE];
__device__ float g_z1[BB * TT * EE];
__device__ float g_z2[BB * TT * EE];
__device__ double g_part[BB * 64 * 2];
__device__ float g_stats[BB * 2];
// tf32 hi/lo splits
__device__ uint32_t g_wvhi[EE * EE];
__device__ uint32_t g_wvlo[EE * EE];
__device__ uint32_t g_wffhi[EE * EE];
__device__ uint32_t g_wfflo[EE * EE];
__device__ uint32_t g_frhi[BB * EE * EE];
__device__ uint32_t g_frlo[BB * EE * EE];
__device__ uint32_t g_athi[BB * TT * EE];  // transposed activation hi [K][M]
__device__ uint32_t g_atlo[BB * TT * EE];

// ---------------- helpers ----------------------------------------------------
__device__ __forceinline__ uint32_t f2tf(float x) {
    uint32_t r;
    asm("cvt.rna.tf32.f32 %0, %1;" : "=r"(r) : "f"(x));
    return r;
}

__device__ __forceinline__ void mma8(float c[4], const uint32_t a[4], const uint32_t b[2]) {
    asm volatile(
        "mma.sync.aligned.m16n8k8.row.col.f32.tf32.tf32.f32 "
        "{%0,%1,%2,%3}, {%4,%5,%6,%7}, {%8,%9}, {%0,%1,%2,%3};\n"
        : "+f"(c[0]), "+f"(c[1]), "+f"(c[2]), "+f"(c[3])
        : "r"(a[0]), "r"(a[1]), "r"(a[2]), "r"(a[3]), "r"(b[0]), "r"(b[1]));
}

__device__ __forceinline__ uint32_t smem_u32(const void* p) {
    return (uint32_t)__cvta_generic_to_shared(p);
}
__device__ __forceinline__ void cpasync16(uint32_t dst, const void* src) {
    asm volatile("cp.async.ca.shared.global [%0], [%1], 16;\n" ::"r"(dst), "l"(src));
}

// ---------------- weight repacks + splits ------------------------------------
__global__ void repack_qkv(const float* __restrict__ qw,
                           const float* __restrict__ kw,
                           const float* __restrict__ vw) {
    int idx = blockIdx.x * blockDim.x + threadIdx.x;
    if (idx >= EE * EE) return;
    int e = idx / EE, n = idx % EE;
    int h = n >> 6, f = n & 63;
    int src = h * (EE * FFDIM) + e * FFDIM + f;
    g_wq[idx] = qw[src];
    g_wk[idx] = kw[src];
    float v = vw[src];
    uint32_t hbits = f2tf(v);
    g_wvhi[idx] = hbits;
    g_wvlo[idx] = f2tf(v - __uint_as_float(hbits));
}

__global__ void repack_ff(const float* __restrict__ w) {
    int idx = blockIdx.x * blockDim.x + threadIdx.x;
    if (idx >= EE * EE) return;
    int e = idx / EE, d = idx % EE;
    float v = w[d * EE + e];
    uint32_t hbits = f2tf(v);
    g_wffhi[idx] = hbits;
    g_wfflo[idx] = f2tf(v - __uint_as_float(hbits));
}

__global__ void split_fr(const float* __restrict__ w) {
    int idx = blockIdx.x * blockDim.x + threadIdx.x;
    if (idx >= BB * EE * EE) return;
    float v = w[idx];
    uint32_t hbits = f2tf(v);
    g_frhi[idx] = hbits;
    g_frlo[idx] = f2tf(v - __uint_as_float(hbits));
}

// ---------------- tiled transpose + split: [nb][M][K] -> hi/lo [nb][K][M] ----
__global__ __launch_bounds__(256) void transpose_split(
    const float* __restrict__ in, uint32_t* __restrict__ ohi,
    uint32_t* __restrict__ olo, int M, int K) {
    __shared__ float t[32][33];
    size_t bo = (size_t)blockIdx.z * M * K;
    in += bo; ohi += bo; olo += bo;
    int m0 = blockIdx.y * 32, k0 = blockIdx.x * 32;
    int tx = threadIdx.x & 31, ty = threadIdx.x >> 5;
#pragma unroll
    for (int i = ty; i < 32; i += 8) t[i][tx] = in[(size_t)(m0 + i) * K + k0 + tx];
    __syncthreads();
#pragma unroll
    for (int i = ty; i < 32; i += 8) {
        float v = t[tx][i];
        uint32_t hbits = f2tf(v);
        size_t o = (size_t)(k0 + i) * M + m0 + tx;
        ohi[o] = hbits;
        olo[o] = f2tf(v - __uint_as_float(hbits));
    }
}

// ---------------- fp32 SIMT GEMM for Q and K, double-buffered ----------------
// Per-output fma chain: ascending k, fp32 — bit-identical to passing kernels.
__global__ __launch_bounds__(256, 2) void gemm_qk(
    const float* __restrict__ A, const float* __restrict__ B0,
    const float* __restrict__ B1, float* __restrict__ C0, float* __restrict__ C1,
    int M, int N, int K) {
    const float* Bm = blockIdx.z ? B1 : B0;
    float* C = blockIdx.z ? C1 : C0;
    __shared__ float As[2][16][132];
    __shared__ float Bs[2][16][128];
    int m0 = blockIdx.y * 128, n0 = blockIdx.x * 128;
    int tid = threadIdx.x;
    int ty = tid >> 4, tx = tid & 15;
    float acc[8][8] = {};
    int ar = tid >> 2;
    int ac4 = (tid & 3) * 4;
    int bk = tid >> 5;
    int bc4 = (tid & 31) * 4;

    uint32_t bd0[2], bd1[2];
    bd0[0] = smem_u32(&Bs[0][bk][bc4]);
    bd0[1] = smem_u32(&Bs[1][bk][bc4]);
    bd1[0] = smem_u32(&Bs[0][bk + 8][bc4]);
    bd1[1] = smem_u32(&Bs[1][bk + 8][bc4]);

    cpasync16(bd0[0], &Bm[(size_t)bk * N + n0 + bc4]);
    cpasync16(bd1[0], &Bm[(size_t)(bk + 8) * N + n0 + bc4]);
    asm volatile("cp.async.commit_group;\n");
    float4 ra0 = *(const float4*)&A[(size_t)(m0 + ar) * K + ac4];
    float4 ra1 = *(const float4*)&A[(size_t)(m0 + ar + 64) * K + ac4];
    As[0][ac4 + 0][ar] = ra0.x; As[0][ac4 + 1][ar] = ra0.y;
    As[0][ac4 + 2][ar] = ra0.z; As[0][ac4 + 3][ar] = ra0.w;
    As[0][ac4 + 0][ar + 64] = ra1.x; As[0][ac4 + 1][ar + 64] = ra1.y;
    As[0][ac4 + 2][ar + 64] = ra1.z; As[0][ac4 + 3][ar + 64] = ra1.w;
    asm volatile("cp.async.wait_group 0;\n");
    __syncthreads();

    int nt = K / 16;
    for (int t = 0; t < nt; t++) {
        int s = t & 1;
        if (t + 1 < nt) {
            int k0 = (t + 1) * 16;
            cpasync16(bd0[s ^ 1], &Bm[(size_t)(k0 + bk) * N + n0 + bc4]);
            cpasync16(bd1[s ^ 1], &Bm[(size_t)(k0 + bk + 8) * N + n0 + bc4]);
            asm volatile("cp.async.commit_group;\n");
            ra0 = *(const float4*)&A[(size_t)(m0 + ar) * K + k0 + ac4];
            ra1 = *(const float4*)&A[(size_t)(m0 + ar + 64) * K + k0 + ac4];
        }
#pragma unroll
        for (int k = 0; k < 16; k++) {
            float a[8], b[8];
            *(float4*)&a[0] = *(const float4*)&As[s][k][ty * 8];
            *(float4*)&a[4] = *(const float4*)&As[s][k][ty * 8 + 4];
            *(float4*)&b[0] = *(const float4*)&Bs[s][k][tx * 8];
            *(float4*)&b[4] = *(const float4*)&Bs[s][k][tx * 8 + 4];
#pragma unroll
            for (int i = 0; i < 8; i++)
#pragma unroll
                for (int j = 0; j < 8; j++) acc[i][j] += a[i] * b[j];
        }
        if (t + 1 < nt) {
            int s2 = s ^ 1;
            As[s2][ac4 + 0][ar] = ra0.x; As[s2][ac4 + 1][ar] = ra0.y;
            As[s2][ac4 + 2][ar] = ra0.z; As[s2][ac4 + 3][ar] = ra0.w;
            As[s2][ac4 + 0][ar + 64] = ra1.x; As[s2][ac4 + 1][ar + 64] = ra1.y;
            As[s2][ac4 + 2][ar + 64] = ra1.z; As[s2][ac4 + 3][ar + 64] = ra1.w;
            asm volatile("cp.async.wait_group 0;\n");
        }
        __syncthreads();
    }
#pragma unroll
    for (int i = 0; i < 8; i++) {
        int m = m0 + ty * 8 + i;
        *(float4*)&C[(size_t)m * N + n0 + tx * 8] = *(float4*)&acc[i][0];
        *(float4*)&C[(size_t)m * N + n0 + tx * 8 + 4] = *(float4*)&acc[i][4];
    }
}

// ---------------- pure-MMA 3xTF32 GEMM with presplit operands ----------------
#define PRE_STAGE_U32 (4 * 16 * 136)
template <bool RELU>
__global__ __launch_bounds__(256, 2) void gemm_pre(
    const uint32_t* __restrict__ Ahi, const uint32_t* __restrict__ Alo,
    const uint32_t* __restrict__ Bhi, const uint32_t* __restrict__ Blo,
    float* __restrict__ C, int M, int N, int K,
    long sA, long sB, long sC, const float* __restrict__ bias) {
    extern __shared__ uint32_t smp[];
    Ahi += (size_t)blockIdx.z * sA;
    Alo += (size_t)blockIdx.z * sA;
    Bhi += (size_t)blockIdx.z * sB;
    Blo += (size_t)blockIdx.z * sB;
    C += (size_t)blockIdx.z * sC;
    int m0 = blockIdx.y * 128, n0 = blockIdx.x * 128;
    int tid = threadIdx.x, lane = tid & 31, w = tid >> 5;
    int wm = w & 1, wn = w >> 1;
    int g = lane >> 2, tig = lane & 3;
    float acc[4][4][4] = {};

    int crow = tid >> 4;
    int col0 = (tid & 15) * 4;
    uint32_t sbase = smem_u32(smp);
    uint32_t offA0 = ((0 * 16 + crow) * 136 + col0) * 4;
    uint32_t offB0 = ((2 * 16 + crow) * 136 + col0) * 4;
    const uint32_t STAGE_B = PRE_STAGE_U32 * 4;
    const uint32_t STREAM_B = 16 * 136 * 4;

    {
        const uint32_t* ga = &Ahi[(size_t)crow * M + m0 + col0];
        const uint32_t* gal = &Alo[(size_t)crow * M + m0 + col0];
        const uint32_t* gb = &Bhi[(size_t)crow * N + n0 + col0];
        const uint32_t* gbl = &Blo[(size_t)crow * N + n0 + col0];
        cpasync16(sbase + offA0, ga);
        cpasync16(sbase + offA0 + 256, ga + 64);
        cpasync16(sbase + offA0 + STREAM_B, gal);
        cpasync16(sbase + offA0 + STREAM_B + 256, gal + 64);
        cpasync16(sbase + offB0, gb);
        cpasync16(sbase + offB0 + 256, gb + 64);
        cpasync16(sbase + offB0 + STREAM_B, gbl);
        cpasync16(sbase + offB0 + STREAM_B + 256, gbl + 64);
        asm volatile("cp.async.commit_group;\n");
        asm volatile("cp.async.wait_group 0;\n");
    }
    __syncthreads();

    int nt = K / 16;
    for (int t = 0; t < nt; t++) {
        int s = t & 1;
        if (t + 1 < nt) {
            int k0 = (t + 1) * 16;
            uint32_t dst = sbase + (s ^ 1) * STAGE_B;
            const uint32_t* ga = &Ahi[(size_t)(k0 + crow) * M + m0 + col0];
            const uint32_t* gal = &Alo[(size_t)(k0 + crow) * M + m0 + col0];
            const uint32_t* gb = &Bhi[(size_t)(k0 + crow) * N + n0 + col0];
            const uint32_t* gbl = &Blo[(size_t)(k0 + crow) * N + n0 + col0];
            cpasync16(dst + offA0, ga);
            cpasync16(dst + offA0 + 256, ga + 64);
            cpasync16(dst + offA0 + STREAM_B, gal);
            cpasync16(dst + offA0 + STREAM_B + 256, gal + 64);
            cpasync16(dst + offB0, gb);
            cpasync16(dst + offB0 + 256, gb + 64);
            cpasync16(dst + offB0 + STREAM_B, gbl);
            cpasync16(dst + offB0 + STREAM_B + 256, gbl + 64);
            asm volatile("cp.async.commit_group;\n");
        }
        const uint32_t* As = smp + s * PRE_STAGE_U32;
        const uint32_t* Asl = As + 16 * 136;
        const uint32_t* Bs = Asl + 16 * 136;
        const uint32_t* Bsl = Bs + 16 * 136;
#pragma unroll
        for (int kk = 0; kk < 16; kk += 8) {
            uint32_t af[4][4], afl[4][4];
#pragma unroll
            for (int mi = 0; mi < 4; mi++) {
                int mb = wm * 64 + mi * 16 + g;
                af[mi][0] = As[(kk + tig) * 136 + mb];
                af[mi][1] = As[(kk + tig) * 136 + mb + 8];
                af[mi][2] = As[(kk + tig + 4) * 136 + mb];
                af[mi][3] = As[(kk + tig + 4) * 136 + mb + 8];
                afl[mi][0] = Asl[(kk + tig) * 136 + mb];
                afl[mi][1] = Asl[(kk + tig) * 136 + mb + 8];
                afl[mi][2] = Asl[(kk + tig + 4) * 136 + mb];
                afl[mi][3] = Asl[(kk + tig + 4) * 136 + mb + 8];
            }
#pragma unroll
            for (int ni = 0; ni < 4; ni++) {
                int nb = wn * 32 + ni * 8 + g;
                uint32_t bf[2], bfl[2];
                bf[0] = Bs[(kk + tig) * 136 + nb];
                bf[1] = Bs[(kk + tig + 4) * 136 + nb];
                bfl[0] = Bsl[(kk + tig) * 136 + nb];
                bfl[1] = Bsl[(kk + tig + 4) * 136 + nb];
#pragma unroll
                for (int mi = 0; mi < 4; mi++) {
                    mma8(acc[mi][ni], af[mi], bfl);
                    mma8(acc[mi][ni], afl[mi], bf);
                    mma8(acc[mi][ni], af[mi], bf);
                }
            }
        }
        if (t + 1 < nt) asm volatile("cp.async.wait_group 0;\n");
        __syncthreads();
    }
#pragma unroll
    for (int mi = 0; mi < 4; mi++) {
        int m = m0 + wm * 64 + mi * 16 + g;
#pragma unroll
        for (int ni = 0; ni < 4; ni++) {
            int n = n0 + wn * 32 + ni * 8 + tig * 2;
            float b0 = bias ? bias[n] : 0.0f;
            float b1 = bias ? bias[n + 1] : 0.0f;
            float v0 = acc[mi][ni][0] + b0, v1 = acc[mi][ni][1] + b1;
            float v2 = acc[mi][ni][2] + b0, v3 = acc[mi][ni][3] + b1;
            if (RELU) {
                v0 = fmaxf(v0, 0.0f); v1 = fmaxf(v1, 0.0f);
                v2 = fmaxf(v2, 0.0f); v3 = fmaxf(v3, 0.0f);
            }
            *(float2*)&C[(size_t)m * N + n] = make_float2(v0, v1);
            *(float2*)&C[(size_t)(m + 8) * N + n] = make_float2(v2, v3);
        }
    }
}

// ---------------- fused attention, BQ=128 BK=64, 2 blocks/SM -----------------
// ks tile aliases the Ps buffer (ks dead once scores are in registers; Ps
// written only after the intervening __syncthreads). Scores chain: ascending-f
// fp32 fma + identical mask expression -> argmax bits unchanged.
struct __align__(16) AttnSmem {
    float qs[64][132];      // [f][q]                      33792 B
    uint32_t Ps[128][68];   // [q][k]; rows 0-63 alias ks  34816 B
    uint32_t vhi[64][72];   // [k][f] tf32 hi              18432 B
    uint32_t vlo[64][72];   //                             18432 B
    float sm_m[128];
    float sm_l[128];
    float sm_sc[128];       //                              1536 B
};                          // total                      106 KB -> 2 blocks/SM

__global__ __launch_bounds__(256, 2) void attn_fused() {
    extern __shared__ char smraw[];
    AttnSmem* S = (AttnSmem*)smraw;
    float(*ks)[68] = (float(*)[68])S->Ps;  // [f][k] during scores
    int bh = blockIdx.y;
    int b = bh / HH, h = bh % HH;
    int q0 = blockIdx.x * 128;
    const float* qp = g_q + (size_t)b * TT * EE + h * FFDIM;
    const float* kp = g_k + (size_t)b * TT * EE + h * FFDIM;
    const float* vp = g_v + (size_t)b * TT * EE + h * FFDIM;
    float* op = g_zm + (size_t)b * TT * EE + h * FFDIM;

    int tid = threadIdx.x;
    int ty = tid >> 4, tx = tid & 15;
    int lane = tid & 31, w = tid >> 5;
    int wm = w >> 1, wn = w & 1;
    int g = lane >> 2, tig = lane & 3;
    int ar = tid >> 2;            // 0..63
    int ac4 = (tid & 3) * 4;

    // load Q tile (once): 128 q-rows x 64 f
#pragma unroll
    for (int c0 = 0; c0 < 64; c0 += 16) {
#pragma unroll
        for (int ri = 0; ri < 2; ri++) {
            int r = ar + ri * 64;
            const float4 va = *(const float4*)&qp[(size_t)(q0 + r) * EE + c0 + ac4];
            S->qs[c0 + ac4 + 0][r] = va.x;
            S->qs[c0 + ac4 + 1][r] = va.y;
            S->qs[c0 + ac4 + 2][r] = va.z;
            S->qs[c0 + ac4 + 3][r] = va.w;
        }
    }
    if (tid < 128) {
        S->sm_m[tid] = -INFINITY;
        S->sm_l[tid] = 0.0f;
    }
    float acc[2][4][4] = {};
    __syncthreads();

    for (int k0 = 0; k0 < TT; k0 += 64) {
        // load K tile (64 keys x 64 f, transposed into [f][k]) + V tile
#pragma unroll
        for (int c0 = 0; c0 < 64; c0 += 16) {
            const float4 vb = *(const float4*)&kp[(size_t)(k0 + ar) * EE + c0 + ac4];
            ks[c0 + ac4 + 0][ar] = vb.x;
            ks[c0 + ac4 + 1][ar] = vb.y;
            ks[c0 + ac4 + 2][ar] = vb.z;
            ks[c0 + ac4 + 3][ar] = vb.w;
        }
        {
            int vr = tid >> 2;            // 0..63
            int vc = (tid & 3) * 16;      // 0,16,32,48
#pragma unroll
            for (int j = 0; j < 4; j++) {
                const float4 v = *(const float4*)&vp[(size_t)(k0 + vr) * EE + vc + j * 4];
                uint4 t, l;
                t.x = f2tf(v.x); t.y = f2tf(v.y); t.z = f2tf(v.z); t.w = f2tf(v.w);
                l.x = f2tf(v.x - __uint_as_float(t.x));
                l.y = f2tf(v.y - __uint_as_float(t.y));
                l.z = f2tf(v.z - __uint_as_float(t.z));
                l.w = f2tf(v.w - __uint_as_float(t.w));
                *(uint4*)&S->vhi[vr][vc + j * 4] = t;
                *(uint4*)&S->vlo[vr][vc + j * 4] = l;
            }
        }
        __syncthreads();

        // S tile: 8 rows x 4 cols per thread, ascending f (identical fp32 chain)
        float s[8][4] = {};
#pragma unroll
        for (int f = 0; f < 64; f++) {
            float a[8], bv[4];
            *(float4*)&a[0] = *(const float4*)&S->qs[f][ty * 8];
            *(float4*)&a[4] = *(const float4*)&S->qs[f][ty * 8 + 4];
            *(float4*)&bv[0] = *(const float4*)&ks[f][tx * 4];
#pragma unroll
            for (int i = 0; i < 8; i++)
#pragma unroll
                for (int j = 0; j < 4; j++) s[i][j] += a[i] * bv[j];
        }
        // mask + scale (identical expression)
#pragma unroll
        for (int i = 0; i < 8; i++) {
            int qg = q0 + ty * 8 + i;
#pragma unroll
            for (int j = 0; j < 4; j++) {
                int kg = k0 + tx * 4 + j;
                float m = (kg > qg) ? (1.0f - 1.0e9f) : 1.0f;
                s[i][j] = s[i][j] * m * 0.125f;
            }
        }
        // tile row max (4 local + 16-lane half-warp tree; exact max)
        float tm[8];
#pragma unroll
        for (int i = 0; i < 8; i++) {
            float v = fmaxf(fmaxf(s[i][0], s[i][1]), fmaxf(s[i][2], s[i][3]));
#pragma unroll
            for (int o = 8; o > 0; o >>= 1) v = fmaxf(v, __shfl_xor_sync(0xffffffffu, v, o));
            tm[i] = v;
        }
        if (tx == 0) {
#pragma unroll
            for (int i = 0; i < 8; i++) {
                int row = ty * 8 + i;
                float mo = S->sm_m[row];
                float mn = fmaxf(mo, tm[i]);
                S->sm_sc[row] = __expf(mo - mn);
                S->sm_m[row] = mn;
            }
        }
        __syncthreads();  // guards last ks read before Ps overwrite + sm_m publish

        // P = exp(s - m_new); bit-exact underflow skip at -104
        unsigned hm = (lane & 16) ? 0xffff0000u : 0x0000ffffu;
#pragma unroll
        for (int i = 0; i < 8; i++) {
            int row = ty * 8 + i;
            float mn = S->sm_m[row];
            if (tm[i] - mn > -104.0f) {
                float p0 = __expf(s[i][0] - mn);
                float p1 = __expf(s[i][1] - mn);
                float p2 = __expf(s[i][2] - mn);
                float p3 = __expf(s[i][3] - mn);
                float rs = p0 + p1 + p2 + p3;
                *(uint4*)&S->Ps[row][tx * 4] =
                    make_uint4(f2tf(p0), f2tf(p1), f2tf(p2), f2tf(p3));
#pragma unroll
                for (int o = 8; o > 0; o >>= 1) rs += __shfl_xor_sync(hm, rs, o);
                if (tx == 0) S->sm_l[row] = S->sm_l[row] * S->sm_sc[row] + rs;
            } else {
                *(uint4*)&S->Ps[row][tx * 4] = make_uint4(0, 0, 0, 0);
            }
        }
        __syncthreads();

        // rescale O accumulators, then PV mma (K=64)
#pragma unroll
        for (int mi = 0; mi < 2; mi++) {
            int row = wm * 32 + mi * 16 + g;
            float s0 = S->sm_sc[row], s1 = S->sm_sc[row + 8];
#pragma unroll
            for (int ni = 0; ni < 4; ni++) {
                acc[mi][ni][0] *= s0; acc[mi][ni][1] *= s0;
                acc[mi][ni][2] *= s1; acc[mi][ni][3] *= s1;
            }
        }
#pragma unroll
        for (int kk = 0; kk < 64; kk += 8) {
            uint32_t af[2][4];
#pragma unroll
            for (int mi = 0; mi < 2; mi++) {
                int mb = wm * 32 + mi * 16 + g;
                af[mi][0] = S->Ps[mb][kk + tig];
                af[mi][1] = S->Ps[mb + 8][kk + tig];
                af[mi][2] = S->Ps[mb][kk + tig + 4];
                af[mi][3] = S->Ps[mb + 8][kk + tig + 4];
            }
#pragma unroll
            for (int ni = 0; ni < 4; ni++) {
                int nb = wn * 32 + ni * 8 + g;
                uint32_t bf[2], bfl[2];
                bf[0] = S->vhi[kk + tig][nb];
                bf[1] = S->vhi[kk + tig + 4][nb];
                bfl[0] = S->vlo[kk + tig][nb];
                bfl[1] = S->vlo[kk + tig + 4][nb];
#pragma unroll
                for (int mi = 0; mi < 2; mi++) {
                    mma8(acc[mi][ni], af[mi], bfl);
                    mma8(acc[mi][ni], af[mi], bf);
                }
            }
        }
        __syncthreads();
    }
    // epilogue: O /= l, write merged heads
#pragma unroll
    for (int mi = 0; mi < 2; mi++) {
        int row = wm * 32 + mi * 16 + g;
        float i0 = 1.0f / S->sm_l[row];
        float i1 = 1.0f / S->sm_l[row + 8];
        int m = q0 + row;
#pragma unroll
        for (int ni = 0; ni < 4; ni++) {
            int n = wn * 32 + ni * 8 + tig * 2;
            *(float2*)&op[(size_t)m * EE + n] =
                make_float2(acc[mi][ni][0] * i0, acc[mi][ni][1] * i0);
            *(float2*)&op[(size_t)(m + 8) * EE + n] =
                make_float2(acc[mi][ni][2] * i1, acc[mi][ni][3] * i1);
        }
    }
}

// ---------------- LayerNorm over whole [T,E] plane per batch -----------------
__global__ __launch_bounds__(256) void ln_reduce(const float* __restrict__ in1,
                                                 const float* __restrict__ in2) {
    int b = blockIdx.y;
    const float* p1 = in1 + (size_t)b * LN_N;
    const float* p2 = in2 + (size_t)b * LN_N;
    const int chunk = (int)(LN_N / 64);  // 16384
    size_t base = (size_t)blockIdx.x * chunk;
    double s = 0.0, sq = 0.0;
    for (int i = threadIdx.x * 4; i < chunk; i += 256 * 4) {
        float4 a = *(const float4*)&p1[base + i];
        float4 c = *(const float4*)&p2[base + i];
        float x0 = a.x + c.x, x1 = a.y + c.y, x2 = a.z + c.z, x3 = a.w + c.w;
        s += (double)x0 + (double)x1 + (double)x2 + (double)x3;
        sq += (double)x0 * x0 + (double)x1 * x1 + (double)x2 * x2 + (double)x3 * x3;
    }
    __shared__ double sh[256], shq[256];
    int tid = threadIdx.x;
    sh[tid] = s;
    shq[tid] = sq;
    __syncthreads();
    for (int o = 128; o > 0; o >>= 1) {
        if (tid < o) {
            sh[tid] += sh[tid + o];
            shq[tid] += shq[tid + o];
        }
        __syncthreads();
    }
    if (tid == 0) {
        g_part[(b * 64 + blockIdx.x) * 2] = sh[0];
        g_part[(b * 64 + blockIdx.x) * 2 + 1] = shq[0];
    }
}

__global__ void ln_finalize() {
    int b = blockIdx.x;
    int tid = threadIdx.x;
    __shared__ double sh[64], shq[64];
    sh[tid] = g_part[(b * 64 + tid) * 2];
    shq[tid] = g_part[(b * 64 + tid) * 2 + 1];
    __syncthreads();
    for (int o = 32; o > 0; o >>= 1) {
        if (tid < o) {
            sh[tid] += sh[tid + o];
            shq[tid] += shq[tid + o];
        }
        __syncthreads();
    }
    if (tid == 0) {
        double n = (double)LN_N;
        double mean = sh[0] / n;
        double var = shq[0] / n - mean * mean;
        g_stats[b * 2] = (float)mean;
        g_stats[b * 2 + 1] = (float)(1.0 / sqrt(var + 1e-5));
    }
}

__global__ __launch_bounds__(256) void ln_norm(const float* __restrict__ in1,
                                               const float* __restrict__ in2,
                                               const float* __restrict__ w,
                                               const float* __restrict__ bia,
                                               float* __restrict__ out) {
    size_t i = ((size_t)blockIdx.x * blockDim.x + threadIdx.x) * 4;
    if (i >= (size_t)BB * LN_N) return;
    int b = (int)(i / LN_N);
    size_t te = i % LN_N;
    float mean = g_stats[b * 2];
    float rstd = g_stats[b * 2 + 1];
    float4 a = *(const float4*)&in1[i];
    float4 c = *(const float4*)&in2[i];
    float4 ww = *(const float4*)&w[te];
    float4 bb = *(const float4*)&bia[te];
    float4 o;
    o.x = (a.x + c.x - mean) * rstd * ww.x + bb.x;
    o.y = (a.y + c.y - mean) * rstd * ww.y + bb.y;
    o.z = (a.z + c.z - mean) * rstd * ww.z + bb.z;
    o.w = (a.w + c.w - mean) * rstd * ww.w + bb.w;
    *(float4*)&out[i] = o;
}

// ---------------- launch -----------------------------------------------------
extern "C" void kernel_launch(void* const* d_in, const int* in_sizes, int n_in,
                              void* d_out, int out_size) {
    const float* x = (const float*)d_in[0];
    const float* q_w = (const float*)d_in[1];
    const float* k_w = (const float*)d_in[2];
    const float* v_w = (const float*)d_in[3];
    const float* fr_w = (const float*)d_in[4];
    const float* ff_w = (const float*)d_in[5];
    const float* ff_b = (const float*)d_in[6];
    const float* ln1_w = (const float*)d_in[7];
    const float* ln1_b = (const float*)d_in[8];
    const float* ln2_w = (const float*)d_in[9];
    const float* ln2_b = (const float*)d_in[10];
    float* out = (float*)d_out;

    float *p_wq, *p_wk, *p_q, *p_k, *p_v, *p_zm, *p_zf, *p_z1, *p_z2;
    uint32_t *p_wvhi, *p_wvlo, *p_wffhi, *p_wfflo, *p_frhi, *p_frlo, *p_athi, *p_atlo;
    cudaGetSymbolAddress((void**)&p_wq, g_wq);
    cudaGetSymbolAddress((void**)&p_wk, g_wk);
    cudaGetSymbolAddress((void**)&p_q, g_q);
    cudaGetSymbolAddress((void**)&p_k, g_k);
    cudaGetSymbolAddress((void**)&p_v, g_v);
    cudaGetSymbolAddress((void**)&p_zm, g_zm);
    cudaGetSymbolAddress((void**)&p_zf, g_zf);
    cudaGetSymbolAddress((void**)&p_z1, g_z1);
    cudaGetSymbolAddress((void**)&p_z2, g_z2);
    cudaGetSymbolAddress((void**)&p_wvhi, g_wvhi);
    cudaGetSymbolAddress((void**)&p_wvlo, g_wvlo);
    cudaGetSymbolAddress((void**)&p_wffhi, g_wffhi);
    cudaGetSymbolAddress((void**)&p_wfflo, g_wfflo);
    cudaGetSymbolAddress((void**)&p_frhi, g_frhi);
    cudaGetSymbolAddress((void**)&p_frlo, g_frlo);
    cudaGetSymbolAddress((void**)&p_athi, g_athi);
    cudaGetSymbolAddress((void**)&p_atlo, g_atlo);

    const size_t SMP = 2 * PRE_STAGE_U32 * sizeof(uint32_t);
    const size_t SMA = sizeof(AttnSmem);
    cudaFuncSetAttribute(attn_fused, cudaFuncAttributeMaxDynamicSharedMemorySize, (int)SMA);
    cudaFuncSetAttribute(gemm_pre<false>, cudaFuncAttributeMaxDynamicSharedMemorySize, (int)SMP);
    cudaFuncSetAttribute(gemm_pre<true>, cudaFuncAttributeMaxDynamicSharedMemorySize, (int)SMP);

    // 1) weight repacks + splits
    repack_qkv<<<(EE * EE + 255) / 256, 256>>>(q_w, k_w, v_w);
    repack_ff<<<(EE * EE + 255) / 256, 256>>>(ff_w);
    split_fr<<<(BB * EE * EE + 255) / 256, 256>>>(fr_w);

    // 2) Q,K: exact fp32 sequential-k (one launch, grid.z=2)
    dim3 gqk(EE / 128, (BB * TT) / 128, 2);
    gemm_qk<<<gqk, 256>>>(x, p_wq, p_wk, p_q, p_k, BB * TT, EE, EE);

    // 3) V = x @ wv (3xTF32, presplit)
    dim3 gtx(EE / 32, (BB * TT) / 32, 1);
    transpose_split<<<gtx, 256>>>(x, p_athi, p_atlo, BB * TT, EE);
    dim3 gv(EE / 128, (BB * TT) / 128, 1);
    gemm_pre<false><<<gv, 256, SMP>>>(p_athi, p_atlo, p_wvhi, p_wvlo, p_v,
                                      BB * TT, EE, EE, 0, 0, 0, nullptr);

    // 4) fused attention
    dim3 gat(TT / 128, BB * HH, 1);
    attn_fused<<<gat, 256, SMA>>>();

    // 5) zf[b] = zm[b] @ fr[b]
    dim3 gtz(EE / 32, TT / 32, BB);
    transpose_split<<<gtz, 256>>>(p_zm, p_athi, p_atlo, TT, EE);
    dim3 gfr(EE / 128, TT / 128, BB);
    gemm_pre<false><<<gfr, 256, SMP>>>(p_athi, p_atlo, p_frhi, p_frlo, p_zf,
                                       TT, EE, EE, (long)TT * EE, (long)EE * EE,
                                       (long)TT * EE, nullptr);

    // 6) LN1 over x + zf -> z1
    dim3 gred(64, BB, 1);
    ln_reduce<<<gred, 256>>>(x, p_zf);
    ln_finalize<<<BB, 64>>>();
    size_t total = (size_t)BB * LN_N;
    ln_norm<<<(unsigned)((total / 4 + 255) / 256), 256>>>(x, p_zf, ln1_w, ln1_b, p_z1);

    // 7) FFN: z2 = relu(z1 @ ff_w^T + ff_b)
    transpose_split<<<gtx, 256>>>(p_z1, p_athi, p_atlo, BB * TT, EE);
    gemm_pre<true><<<gv, 256, SMP>>>(p_athi, p_atlo, p_wffhi, p_wfflo, p_z2,
                                     BB * TT, EE, EE, 0, 0, 0, ff_b);

    // 8) LN2 over z1 + z2 -> out
    ln_reduce<<<gred, 256>>>(p_z1, p_z2);
    ln_finalize<<<BB, 64>>>();
    ln_norm<<<(unsigned)((total / 4 + 255) / 256), 256>>>(p_z1, p_z2, ln2_w, ln2_b, out);
}

// round 10
// speedup vs baseline: 2.4132x; 1.2558x over previous
#include <cuda_runtime.h>
#include <math.h>
#include <stdint.h>

#define BB 4
#define TT 1024
#define EE 1024
#define HH 16
#define FFDIM 64
#define LN_N ((size_t)TT * EE)

// ---------------- scratch (static device globals; no allocation) -------------
__device__ float g_wq[EE * EE];
__device__ float g_wk[EE * EE];
__device__ float g_q[BB * TT * EE];   // [B, T, H*F]
__device__ float g_k[BB * TT * EE];
__device__ float g_v[BB * TT * EE];
__device__ float g_zm[BB * TT * EE];
__device__ float g_zf[BB * TT * EE];
__device__ float g_z1[BB * TT * EE];
__device__ float g_z2[BB * TT * EE];
__device__ double g_part[BB * 64 * 2];
__device__ float g_stats[BB * 2];
// tf32 operands (1x path)
__device__ uint32_t g_wvhi[EE * EE];
__device__ uint32_t g_wffhi[EE * EE];
__device__ uint32_t g_frhi[BB * EE * EE];
__device__ uint32_t g_athi[BB * TT * EE];  // transposed activation [K][M]

// ---------------- helpers ----------------------------------------------------
__device__ __forceinline__ uint32_t f2tf(float x) {
    uint32_t r;
    asm("cvt.rna.tf32.f32 %0, %1;" : "=r"(r) : "f"(x));
    return r;
}

__device__ __forceinline__ void mma8(float c[4], const uint32_t a[4], const uint32_t b[2]) {
    asm volatile(
        "mma.sync.aligned.m16n8k8.row.col.f32.tf32.tf32.f32 "
        "{%0,%1,%2,%3}, {%4,%5,%6,%7}, {%8,%9}, {%0,%1,%2,%3};\n"
        : "+f"(c[0]), "+f"(c[1]), "+f"(c[2]), "+f"(c[3])
        : "r"(a[0]), "r"(a[1]), "r"(a[2]), "r"(a[3]), "r"(b[0]), "r"(b[1]));
}

__device__ __forceinline__ uint32_t smem_u32(const void* p) {
    return (uint32_t)__cvta_generic_to_shared(p);
}
__device__ __forceinline__ void cpasync16(uint32_t dst, const void* src) {
    asm volatile("cp.async.ca.shared.global [%0], [%1], 16;\n" ::"r"(dst), "l"(src));
}

// ---------------- weight repacks ---------------------------------------------
__global__ void repack_qkv(const float* __restrict__ qw,
                           const float* __restrict__ kw,
                           const float* __restrict__ vw) {
    int idx = blockIdx.x * blockDim.x + threadIdx.x;
    if (idx >= EE * EE) return;
    int e = idx / EE, n = idx % EE;
    int h = n >> 6, f = n & 63;
    int src = h * (EE * FFDIM) + e * FFDIM + f;
    g_wq[idx] = qw[src];
    g_wk[idx] = kw[src];
    g_wvhi[idx] = f2tf(vw[src]);
}

__global__ void repack_ff(const float* __restrict__ w) {
    int idx = blockIdx.x * blockDim.x + threadIdx.x;
    if (idx >= EE * EE) return;
    int e = idx / EE, d = idx % EE;
    g_wffhi[idx] = f2tf(w[d * EE + e]);
}

__global__ void split_fr(const float* __restrict__ w) {
    int idx = blockIdx.x * blockDim.x + threadIdx.x;
    if (idx >= BB * EE * EE) return;
    g_frhi[idx] = f2tf(w[idx]);
}

// ---------------- tiled transpose + tf32: [nb][M][K] -> [nb][K][M] -----------
__global__ __launch_bounds__(256) void transpose_tf(
    const float* __restrict__ in, uint32_t* __restrict__ ohi, int M, int K) {
    __shared__ float t[32][33];
    size_t bo = (size_t)blockIdx.z * M * K;
    in += bo; ohi += bo;
    int m0 = blockIdx.y * 32, k0 = blockIdx.x * 32;
    int tx = threadIdx.x & 31, ty = threadIdx.x >> 5;
#pragma unroll
    for (int i = ty; i < 32; i += 8) t[i][tx] = in[(size_t)(m0 + i) * K + k0 + tx];
    __syncthreads();
#pragma unroll
    for (int i = ty; i < 32; i += 8) {
        ohi[(size_t)(k0 + i) * M + m0 + tx] = f2tf(t[tx][i]);
    }
}

// ---------------- fp32 SIMT GEMM for Q and K, double-buffered ----------------
// Per-output fma chain: ascending k, fp32 — bit-identical to passing kernels.
// FROZEN: do not alter the arithmetic realization.
__global__ __launch_bounds__(256, 2) void gemm_qk(
    const float* __restrict__ A, const float* __restrict__ B0,
    const float* __restrict__ B1, float* __restrict__ C0, float* __restrict__ C1,
    int M, int N, int K) {
    const float* Bm = blockIdx.z ? B1 : B0;
    float* C = blockIdx.z ? C1 : C0;
    __shared__ float As[2][16][132];
    __shared__ float Bs[2][16][128];
    int m0 = blockIdx.y * 128, n0 = blockIdx.x * 128;
    int tid = threadIdx.x;
    int ty = tid >> 4, tx = tid & 15;
    float acc[8][8] = {};
    int ar = tid >> 2;
    int ac4 = (tid & 3) * 4;
    int bk = tid >> 5;
    int bc4 = (tid & 31) * 4;

    uint32_t bd0[2], bd1[2];
    bd0[0] = smem_u32(&Bs[0][bk][bc4]);
    bd0[1] = smem_u32(&Bs[1][bk][bc4]);
    bd1[0] = smem_u32(&Bs[0][bk + 8][bc4]);
    bd1[1] = smem_u32(&Bs[1][bk + 8][bc4]);

    cpasync16(bd0[0], &Bm[(size_t)bk * N + n0 + bc4]);
    cpasync16(bd1[0], &Bm[(size_t)(bk + 8) * N + n0 + bc4]);
    asm volatile("cp.async.commit_group;\n");
    float4 ra0 = *(const float4*)&A[(size_t)(m0 + ar) * K + ac4];
    float4 ra1 = *(const float4*)&A[(size_t)(m0 + ar + 64) * K + ac4];
    As[0][ac4 + 0][ar] = ra0.x; As[0][ac4 + 1][ar] = ra0.y;
    As[0][ac4 + 2][ar] = ra0.z; As[0][ac4 + 3][ar] = ra0.w;
    As[0][ac4 + 0][ar + 64] = ra1.x; As[0][ac4 + 1][ar + 64] = ra1.y;
    As[0][ac4 + 2][ar + 64] = ra1.z; As[0][ac4 + 3][ar + 64] = ra1.w;
    asm volatile("cp.async.wait_group 0;\n");
    __syncthreads();

    int nt = K / 16;
    for (int t = 0; t < nt; t++) {
        int s = t & 1;
        if (t + 1 < nt) {
            int k0 = (t + 1) * 16;
            cpasync16(bd0[s ^ 1], &Bm[(size_t)(k0 + bk) * N + n0 + bc4]);
            cpasync16(bd1[s ^ 1], &Bm[(size_t)(k0 + bk + 8) * N + n0 + bc4]);
            asm volatile("cp.async.commit_group;\n");
            ra0 = *(const float4*)&A[(size_t)(m0 + ar) * K + k0 + ac4];
            ra1 = *(const float4*)&A[(size_t)(m0 + ar + 64) * K + k0 + ac4];
        }
#pragma unroll
        for (int k = 0; k < 16; k++) {
            float a[8], b[8];
            *(float4*)&a[0] = *(const float4*)&As[s][k][ty * 8];
            *(float4*)&a[4] = *(const float4*)&As[s][k][ty * 8 + 4];
            *(float4*)&b[0] = *(const float4*)&Bs[s][k][tx * 8];
            *(float4*)&b[4] = *(const float4*)&Bs[s][k][tx * 8 + 4];
#pragma unroll
            for (int i = 0; i < 8; i++)
#pragma unroll
                for (int j = 0; j < 8; j++) acc[i][j] += a[i] * b[j];
        }
        if (t + 1 < nt) {
            int s2 = s ^ 1;
            As[s2][ac4 + 0][ar] = ra0.x; As[s2][ac4 + 1][ar] = ra0.y;
            As[s2][ac4 + 2][ar] = ra0.z; As[s2][ac4 + 3][ar] = ra0.w;
            As[s2][ac4 + 0][ar + 64] = ra1.x; As[s2][ac4 + 1][ar + 64] = ra1.y;
            As[s2][ac4 + 2][ar + 64] = ra1.z; As[s2][ac4 + 3][ar + 64] = ra1.w;
            asm volatile("cp.async.wait_group 0;\n");
        }
        __syncthreads();
    }
#pragma unroll
    for (int i = 0; i < 8; i++) {
        int m = m0 + ty * 8 + i;
        *(float4*)&C[(size_t)m * N + n0 + tx * 8] = *(float4*)&acc[i][0];
        *(float4*)&C[(size_t)m * N + n0 + tx * 8 + 4] = *(float4*)&acc[i][4];
    }
}

// ---------------- 1xTF32 tensor-core GEMM, 3-stage cp.async pipeline ---------
// A: [K][M] tf32 (pre-transposed), B: [K][N] tf32. Stage = A tile + B tile.
#define T1_STAGE_U32 (2 * 16 * 136)
template <bool RELU>
__global__ __launch_bounds__(256, 2) void gemm_tf1(
    const uint32_t* __restrict__ Ahi, const uint32_t* __restrict__ Bhi,
    float* __restrict__ C, int M, int N, int K,
    long sA, long sB, long sC, const float* __restrict__ bias) {
    extern __shared__ uint32_t smp[];
    Ahi += (size_t)blockIdx.z * sA;
    Bhi += (size_t)blockIdx.z * sB;
    C += (size_t)blockIdx.z * sC;
    int m0 = blockIdx.y * 128, n0 = blockIdx.x * 128;
    int tid = threadIdx.x, lane = tid & 31, w = tid >> 5;
    int wm = w & 1, wn = w >> 1;
    int g = lane >> 2, tig = lane & 3;
    float acc[4][4][4] = {};

    int crow = tid >> 4;            // 0..15
    int col0 = (tid & 15) * 4;      // 0..60
    uint32_t sbase = smem_u32(smp);
    const uint32_t STAGE_B = T1_STAGE_U32 * 4;  // 17408
    uint32_t offA = ((0 * 16 + crow) * 136 + col0) * 4;
    uint32_t offB = ((1 * 16 + crow) * 136 + col0) * 4;

    int nt = K / 16;
    // prologue: tiles 0,1 into stages 0,1
#pragma unroll
    for (int p = 0; p < 2; p++) {
        uint32_t dst = sbase + p * STAGE_B;
        const uint32_t* ga = &Ahi[(size_t)(p * 16 + crow) * M + m0 + col0];
        const uint32_t* gb = &Bhi[(size_t)(p * 16 + crow) * N + n0 + col0];
        cpasync16(dst + offA, ga);
        cpasync16(dst + offA + 256, ga + 64);
        cpasync16(dst + offB, gb);
        cpasync16(dst + offB + 256, gb + 64);
        asm volatile("cp.async.commit_group;\n");
    }
    asm volatile("cp.async.wait_group 1;\n");  // tile 0 landed
    __syncthreads();

    int sl = 2;  // stage for next load
    int sc = 0;  // stage to compute
    for (int t = 0; t < nt; t++) {
        if (t + 2 < nt) {
            uint32_t dst = sbase + sl * STAGE_B;
            const uint32_t* ga = &Ahi[(size_t)((t + 2) * 16 + crow) * M + m0 + col0];
            const uint32_t* gb = &Bhi[(size_t)((t + 2) * 16 + crow) * N + n0 + col0];
            cpasync16(dst + offA, ga);
            cpasync16(dst + offA + 256, ga + 64);
            cpasync16(dst + offB, gb);
            cpasync16(dst + offB + 256, gb + 64);
        }
        asm volatile("cp.async.commit_group;\n");  // real or empty group
        const uint32_t* As = smp + sc * T1_STAGE_U32;
        const uint32_t* Bs = As + 16 * 136;
#pragma unroll
        for (int kk = 0; kk < 16; kk += 8) {
            uint32_t af[4][4];
#pragma unroll
            for (int mi = 0; mi < 4; mi++) {
                int mb = wm * 64 + mi * 16 + g;
                af[mi][0] = As[(kk + tig) * 136 + mb];
                af[mi][1] = As[(kk + tig) * 136 + mb + 8];
                af[mi][2] = As[(kk + tig + 4) * 136 + mb];
                af[mi][3] = As[(kk + tig + 4) * 136 + mb + 8];
            }
#pragma unroll
            for (int ni = 0; ni < 4; ni++) {
                int nb = wn * 32 + ni * 8 + g;
                uint32_t bf[2];
                bf[0] = Bs[(kk + tig) * 136 + nb];
                bf[1] = Bs[(kk + tig + 4) * 136 + nb];
#pragma unroll
                for (int mi = 0; mi < 4; mi++) mma8(acc[mi][ni], af[mi], bf);
            }
        }
        asm volatile("cp.async.wait_group 1;\n");  // tile t+1 landed
        __syncthreads();
        sl = (sl == 2) ? 0 : sl + 1;
        sc = (sc == 2) ? 0 : sc + 1;
    }
#pragma unroll
    for (int mi = 0; mi < 4; mi++) {
        int m = m0 + wm * 64 + mi * 16 + g;
#pragma unroll
        for (int ni = 0; ni < 4; ni++) {
            int n = n0 + wn * 32 + ni * 8 + tig * 2;
            float b0 = bias ? bias[n] : 0.0f;
            float b1 = bias ? bias[n + 1] : 0.0f;
            float v0 = acc[mi][ni][0] + b0, v1 = acc[mi][ni][1] + b1;
            float v2 = acc[mi][ni][2] + b0, v3 = acc[mi][ni][3] + b1;
            if (RELU) {
                v0 = fmaxf(v0, 0.0f); v1 = fmaxf(v1, 0.0f);
                v2 = fmaxf(v2, 0.0f); v3 = fmaxf(v3, 0.0f);
            }
            *(float2*)&C[(size_t)m * N + n] = make_float2(v0, v1);
            *(float2*)&C[(size_t)(m + 8) * N + n] = make_float2(v2, v3);
        }
    }
}

// ---------------- fused attention, BQ=128 BK=64, 2 blocks/SM (FROZEN) --------
struct __align__(16) AttnSmem {
    float qs[64][132];
    uint32_t Ps[128][68];   // rows 0-63 alias ks during scores
    uint32_t vhi[64][72];
    uint32_t vlo[64][72];
    float sm_m[128];
    float sm_l[128];
    float sm_sc[128];
};

__global__ __launch_bounds__(256, 2) void attn_fused() {
    extern __shared__ char smraw[];
    AttnSmem* S = (AttnSmem*)smraw;
    float(*ks)[68] = (float(*)[68])S->Ps;
    int bh = blockIdx.y;
    int b = bh / HH, h = bh % HH;
    int q0 = blockIdx.x * 128;
    const float* qp = g_q + (size_t)b * TT * EE + h * FFDIM;
    const float* kp = g_k + (size_t)b * TT * EE + h * FFDIM;
    const float* vp = g_v + (size_t)b * TT * EE + h * FFDIM;
    float* op = g_zm + (size_t)b * TT * EE + h * FFDIM;

    int tid = threadIdx.x;
    int ty = tid >> 4, tx = tid & 15;
    int lane = tid & 31, w = tid >> 5;
    int wm = w >> 1, wn = w & 1;
    int g = lane >> 2, tig = lane & 3;
    int ar = tid >> 2;
    int ac4 = (tid & 3) * 4;

#pragma unroll
    for (int c0 = 0; c0 < 64; c0 += 16) {
#pragma unroll
        for (int ri = 0; ri < 2; ri++) {
            int r = ar + ri * 64;
            const float4 va = *(const float4*)&qp[(size_t)(q0 + r) * EE + c0 + ac4];
            S->qs[c0 + ac4 + 0][r] = va.x;
            S->qs[c0 + ac4 + 1][r] = va.y;
            S->qs[c0 + ac4 + 2][r] = va.z;
            S->qs[c0 + ac4 + 3][r] = va.w;
        }
    }
    if (tid < 128) {
        S->sm_m[tid] = -INFINITY;
        S->sm_l[tid] = 0.0f;
    }
    float acc[2][4][4] = {};
    __syncthreads();

    for (int k0 = 0; k0 < TT; k0 += 64) {
#pragma unroll
        for (int c0 = 0; c0 < 64; c0 += 16) {
            const float4 vb = *(const float4*)&kp[(size_t)(k0 + ar) * EE + c0 + ac4];
            ks[c0 + ac4 + 0][ar] = vb.x;
            ks[c0 + ac4 + 1][ar] = vb.y;
            ks[c0 + ac4 + 2][ar] = vb.z;
            ks[c0 + ac4 + 3][ar] = vb.w;
        }
        {
            int vr = tid >> 2;
            int vc = (tid & 3) * 16;
#pragma unroll
            for (int j = 0; j < 4; j++) {
                const float4 v = *(const float4*)&vp[(size_t)(k0 + vr) * EE + vc + j * 4];
                uint4 t, l;
                t.x = f2tf(v.x); t.y = f2tf(v.y); t.z = f2tf(v.z); t.w = f2tf(v.w);
                l.x = f2tf(v.x - __uint_as_float(t.x));
                l.y = f2tf(v.y - __uint_as_float(t.y));
                l.z = f2tf(v.z - __uint_as_float(t.z));
                l.w = f2tf(v.w - __uint_as_float(t.w));
                *(uint4*)&S->vhi[vr][vc + j * 4] = t;
                *(uint4*)&S->vlo[vr][vc + j * 4] = l;
            }
        }
        __syncthreads();

        float s[8][4] = {};
#pragma unroll
        for (int f = 0; f < 64; f++) {
            float a[8], bv[4];
            *(float4*)&a[0] = *(const float4*)&S->qs[f][ty * 8];
            *(float4*)&a[4] = *(const float4*)&S->qs[f][ty * 8 + 4];
            *(float4*)&bv[0] = *(const float4*)&ks[f][tx * 4];
#pragma unroll
            for (int i = 0; i < 8; i++)
#pragma unroll
                for (int j = 0; j < 4; j++) s[i][j] += a[i] * bv[j];
        }
#pragma unroll
        for (int i = 0; i < 8; i++) {
            int qg = q0 + ty * 8 + i;
#pragma unroll
            for (int j = 0; j < 4; j++) {
                int kg = k0 + tx * 4 + j;
                float m = (kg > qg) ? (1.0f - 1.0e9f) : 1.0f;
                s[i][j] = s[i][j] * m * 0.125f;
            }
        }
        float tm[8];
#pragma unroll
        for (int i = 0; i < 8; i++) {
            float v = fmaxf(fmaxf(s[i][0], s[i][1]), fmaxf(s[i][2], s[i][3]));
#pragma unroll
            for (int o = 8; o > 0; o >>= 1) v = fmaxf(v, __shfl_xor_sync(0xffffffffu, v, o));
            tm[i] = v;
        }
        if (tx == 0) {
#pragma unroll
            for (int i = 0; i < 8; i++) {
                int row = ty * 8 + i;
                float mo = S->sm_m[row];
                float mn = fmaxf(mo, tm[i]);
                S->sm_sc[row] = __expf(mo - mn);
                S->sm_m[row] = mn;
            }
        }
        __syncthreads();

        unsigned hm = (lane & 16) ? 0xffff0000u : 0x0000ffffu;
#pragma unroll
        for (int i = 0; i < 8; i++) {
            int row = ty * 8 + i;
            float mn = S->sm_m[row];
            if (tm[i] - mn > -104.0f) {
                float p0 = __expf(s[i][0] - mn);
                float p1 = __expf(s[i][1] - mn);
                float p2 = __expf(s[i][2] - mn);
                float p3 = __expf(s[i][3] - mn);
                float rs = p0 + p1 + p2 + p3;
                *(uint4*)&S->Ps[row][tx * 4] =
                    make_uint4(f2tf(p0), f2tf(p1), f2tf(p2), f2tf(p3));
#pragma unroll
                for (int o = 8; o > 0; o >>= 1) rs += __shfl_xor_sync(hm, rs, o);
                if (tx == 0) S->sm_l[row] = S->sm_l[row] * S->sm_sc[row] + rs;
            } else {
                *(uint4*)&S->Ps[row][tx * 4] = make_uint4(0, 0, 0, 0);
            }
        }
        __syncthreads();

#pragma unroll
        for (int mi = 0; mi < 2; mi++) {
            int row = wm * 32 + mi * 16 + g;
            float s0 = S->sm_sc[row], s1 = S->sm_sc[row + 8];
#pragma unroll
            for (int ni = 0; ni < 4; ni++) {
                acc[mi][ni][0] *= s0; acc[mi][ni][1] *= s0;
                acc[mi][ni][2] *= s1; acc[mi][ni][3] *= s1;
            }
        }
#pragma unroll
        for (int kk = 0; kk < 64; kk += 8) {
            uint32_t af[2][4];
#pragma unroll
            for (int mi = 0; mi < 2; mi++) {
                int mb = wm * 32 + mi * 16 + g;
                af[mi][0] = S->Ps[mb][kk + tig];
                af[mi][1] = S->Ps[mb + 8][kk + tig];
                af[mi][2] = S->Ps[mb][kk + tig + 4];
                af[mi][3] = S->Ps[mb + 8][kk + tig + 4];
            }
#pragma unroll
            for (int ni = 0; ni < 4; ni++) {
                int nb = wn * 32 + ni * 8 + g;
                uint32_t bf[2], bfl[2];
                bf[0] = S->vhi[kk + tig][nb];
                bf[1] = S->vhi[kk + tig + 4][nb];
                bfl[0] = S->vlo[kk + tig][nb];
                bfl[1] = S->vlo[kk + tig + 4][nb];
#pragma unroll
                for (int mi = 0; mi < 2; mi++) {
                    mma8(acc[mi][ni], af[mi], bfl);
                    mma8(acc[mi][ni], af[mi], bf);
                }
            }
        }
        __syncthreads();
    }
#pragma unroll
    for (int mi = 0; mi < 2; mi++) {
        int row = wm * 32 + mi * 16 + g;
        float i0 = 1.0f / S->sm_l[row];
        float i1 = 1.0f / S->sm_l[row + 8];
        int m = q0 + row;
#pragma unroll
        for (int ni = 0; ni < 4; ni++) {
            int n = wn * 32 + ni * 8 + tig * 2;
            *(float2*)&op[(size_t)m * EE + n] =
                make_float2(acc[mi][ni][0] * i0, acc[mi][ni][1] * i0);
            *(float2*)&op[(size_t)(m + 8) * EE + n] =
                make_float2(acc[mi][ni][2] * i1, acc[mi][ni][3] * i1);
        }
    }
}

// ---------------- LayerNorm over whole [T,E] plane per batch -----------------
__global__ __launch_bounds__(256) void ln_reduce(const float* __restrict__ in1,
                                                 const float* __restrict__ in2) {
    int b = blockIdx.y;
    const float* p1 = in1 + (size_t)b * LN_N;
    const float* p2 = in2 + (size_t)b * LN_N;
    const int chunk = (int)(LN_N / 64);
    size_t base = (size_t)blockIdx.x * chunk;
    double s = 0.0, sq = 0.0;
    for (int i = threadIdx.x * 4; i < chunk; i += 256 * 4) {
        float4 a = *(const float4*)&p1[base + i];
        float4 c = *(const float4*)&p2[base + i];
        float x0 = a.x + c.x, x1 = a.y + c.y, x2 = a.z + c.z, x3 = a.w + c.w;
        s += (double)x0 + (double)x1 + (double)x2 + (double)x3;
        sq += (double)x0 * x0 + (double)x1 * x1 + (double)x2 * x2 + (double)x3 * x3;
    }
    __shared__ double sh[256], shq[256];
    int tid = threadIdx.x;
    sh[tid] = s;
    shq[tid] = sq;
    __syncthreads();
    for (int o = 128; o > 0; o >>= 1) {
        if (tid < o) {
            sh[tid] += sh[tid + o];
            shq[tid] += shq[tid + o];
        }
        __syncthreads();
    }
    if (tid == 0) {
        g_part[(b * 64 + blockIdx.x) * 2] = sh[0];
        g_part[(b * 64 + blockIdx.x) * 2 + 1] = shq[0];
    }
}

__global__ void ln_finalize() {
    int b = blockIdx.x;
    int tid = threadIdx.x;
    __shared__ double sh[64], shq[64];
    sh[tid] = g_part[(b * 64 + tid) * 2];
    shq[tid] = g_part[(b * 64 + tid) * 2 + 1];
    __syncthreads();
    for (int o = 32; o > 0; o >>= 1) {
        if (tid < o) {
            sh[tid] += sh[tid + o];
            shq[tid] += shq[tid + o];
        }
        __syncthreads();
    }
    if (tid == 0) {
        double n = (double)LN_N;
        double mean = sh[0] / n;
        double var = shq[0] / n - mean * mean;
        g_stats[b * 2] = (float)mean;
        g_stats[b * 2 + 1] = (float)(1.0 / sqrt(var + 1e-5));
    }
}

__global__ __launch_bounds__(256) void ln_norm(const float* __restrict__ in1,
                                               const float* __restrict__ in2,
                                               const float* __restrict__ w,
                                               const float* __restrict__ bia,
                                               float* __restrict__ out) {
    size_t i = ((size_t)blockIdx.x * blockDim.x + threadIdx.x) * 4;
    if (i >= (size_t)BB * LN_N) return;
    int b = (int)(i / LN_N);
    size_t te = i % LN_N;
    float mean = g_stats[b * 2];
    float rstd = g_stats[b * 2 + 1];
    float4 a = *(const float4*)&in1[i];
    float4 c = *(const float4*)&in2[i];
    float4 ww = *(const float4*)&w[te];
    float4 bb = *(const float4*)&bia[te];
    float4 o;
    o.x = (a.x + c.x - mean) * rstd * ww.x + bb.x;
    o.y = (a.y + c.y - mean) * rstd * ww.y + bb.y;
    o.z = (a.z + c.z - mean) * rstd * ww.z + bb.z;
    o.w = (a.w + c.w - mean) * rstd * ww.w + bb.w;
    *(float4*)&out[i] = o;
}

// ---------------- launch -----------------------------------------------------
extern "C" void kernel_launch(void* const* d_in, const int* in_sizes, int n_in,
                              void* d_out, int out_size) {
    const float* x = (const float*)d_in[0];
    const float* q_w = (const float*)d_in[1];
    const float* k_w = (const float*)d_in[2];
    const float* v_w = (const float*)d_in[3];
    const float* fr_w = (const float*)d_in[4];
    const float* ff_w = (const float*)d_in[5];
    const float* ff_b = (const float*)d_in[6];
    const float* ln1_w = (const float*)d_in[7];
    const float* ln1_b = (const float*)d_in[8];
    const float* ln2_w = (const float*)d_in[9];
    const float* ln2_b = (const float*)d_in[10];
    float* out = (float*)d_out;

    float *p_wq, *p_wk, *p_q, *p_k, *p_v, *p_zm, *p_zf, *p_z1, *p_z2;
    uint32_t *p_wvhi, *p_wffhi, *p_frhi, *p_athi;
    cudaGetSymbolAddress((void**)&p_wq, g_wq);
    cudaGetSymbolAddress((void**)&p_wk, g_wk);
    cudaGetSymbolAddress((void**)&p_q, g_q);
    cudaGetSymbolAddress((void**)&p_k, g_k);
    cudaGetSymbolAddress((void**)&p_v, g_v);
    cudaGetSymbolAddress((void**)&p_zm, g_zm);
    cudaGetSymbolAddress((void**)&p_zf, g_zf);
    cudaGetSymbolAddress((void**)&p_z1, g_z1);
    cudaGetSymbolAddress((void**)&p_z2, g_z2);
    cudaGetSymbolAddress((void**)&p_wvhi, g_wvhi);
    cudaGetSymbolAddress((void**)&p_wffhi, g_wffhi);
    cudaGetSymbolAddress((void**)&p_frhi, g_frhi);
    cudaGetSymbolAddress((void**)&p_athi, g_athi);

    const size_t SMP = 3 * T1_STAGE_U32 * sizeof(uint32_t);  // 52224 B
    const size_t SMA = sizeof(AttnSmem);
    cudaFuncSetAttribute(attn_fused, cudaFuncAttributeMaxDynamicSharedMemorySize, (int)SMA);
    cudaFuncSetAttribute(gemm_tf1<false>, cudaFuncAttributeMaxDynamicSharedMemorySize, (int)SMP);
    cudaFuncSetAttribute(gemm_tf1<true>, cudaFuncAttributeMaxDynamicSharedMemorySize, (int)SMP);

    // 1) weight repacks
    repack_qkv<<<(EE * EE + 255) / 256, 256>>>(q_w, k_w, v_w);
    repack_ff<<<(EE * EE + 255) / 256, 256>>>(ff_w);
    split_fr<<<(BB * EE * EE + 255) / 256, 256>>>(fr_w);

    // 2) Q,K: exact fp32 sequential-k (one launch, grid.z=2)
    dim3 gqk(EE / 128, (BB * TT) / 128, 2);
    gemm_qk<<<gqk, 256>>>(x, p_wq, p_wk, p_q, p_k, BB * TT, EE, EE);

    // 3) V = x @ wv (1xTF32)
    dim3 gtx(EE / 32, (BB * TT) / 32, 1);
    transpose_tf<<<gtx, 256>>>(x, p_athi, BB * TT, EE);
    dim3 gv(EE / 128, (BB * TT) / 128, 1);
    gemm_tf1<false><<<gv, 256, SMP>>>(p_athi, p_wvhi, p_v,
                                      BB * TT, EE, EE, 0, 0, 0, nullptr);

    // 4) fused attention
    dim3 gat(TT / 128, BB * HH, 1);
    attn_fused<<<gat, 256, SMA>>>();

    // 5) zf[b] = zm[b] @ fr[b] (1xTF32, batched)
    dim3 gtz(EE / 32, TT / 32, BB);
    transpose_tf<<<gtz, 256>>>(p_zm, p_athi, TT, EE);
    dim3 gfr(EE / 128, TT / 128, BB);
    gemm_tf1<false><<<gfr, 256, SMP>>>(p_athi, p_frhi, p_zf,
                                       TT, EE, EE, (long)TT * EE, (long)EE * EE,
                                       (long)TT * EE, nullptr);

    // 6) LN1 over x + zf -> z1
    dim3 gred(64, BB, 1);
    ln_reduce<<<gred, 256>>>(x, p_zf);
    ln_finalize<<<BB, 64>>>();
    size_t total = (size_t)BB * LN_N;
    ln_norm<<<(unsigned)((total / 4 + 255) / 256), 256>>>(x, p_zf, ln1_w, ln1_b, p_z1);

    // 7) FFN: z2 = relu(z1 @ ff_w^T + ff_b) (1xTF32)
    transpose_tf<<<gtx, 256>>>(p_z1, p_athi, BB * TT, EE);
    gemm_tf1<true><<<gv, 256, SMP>>>(p_athi, p_wffhi, p_z2,
                                     BB * TT, EE, EE, 0, 0, 0, ff_b);

    // 8) LN2 over z1 + z2 -> out
    ln_reduce<<<gred, 256>>>(p_z1, p_z2);
    ln_finalize<<<BB, 64>>>();
    ln_norm<<<(unsigned)((total / 4 + 255) / 256), 256>>>(p_z1, p_z2, ln2_w, ln2_b, out);
}

// round 12
// speedup vs baseline: 2.5638x; 1.0624x over previous
#include <cuda_runtime.h>
#include <math.h>
#include <stdint.h>

#define BB 4
#define TT 1024
#define EE 1024
#define HH 16
#define FFDIM 64
#define LN_N ((size_t)TT * EE)

// ---------------- scratch (static device globals; no allocation) -------------
__device__ float g_wq[EE * EE];
__device__ float g_wk[EE * EE];
__device__ float g_q[BB * TT * EE];
__device__ float g_k[BB * TT * EE];
__device__ float g_v[BB * TT * EE];
__device__ float g_zm[BB * TT * EE];
__device__ float g_zf[BB * TT * EE];
__device__ float g_z1[BB * TT * EE];
__device__ float g_z2[BB * TT * EE];
__device__ double g_part[BB * 64 * 2];
__device__ float g_stats[BB * 2];
__device__ uint32_t g_wvhi[EE * EE];
__device__ uint32_t g_wffhi[EE * EE];
__device__ uint32_t g_frhi[BB * EE * EE];
__device__ uint32_t g_athi[BB * TT * EE];  // transposed activation [K][M]

// ---------------- helpers ----------------------------------------------------
__device__ __forceinline__ uint32_t f2tf(float x) {
    uint32_t r;
    asm("cvt.rna.tf32.f32 %0, %1;" : "=r"(r) : "f"(x));
    return r;
}

__device__ __forceinline__ void mma8(float c[4], const uint32_t a[4], const uint32_t b[2]) {
    asm volatile(
        "mma.sync.aligned.m16n8k8.row.col.f32.tf32.tf32.f32 "
        "{%0,%1,%2,%3}, {%4,%5,%6,%7}, {%8,%9}, {%0,%1,%2,%3};\n"
        : "+f"(c[0]), "+f"(c[1]), "+f"(c[2]), "+f"(c[3])
        : "r"(a[0]), "r"(a[1]), "r"(a[2]), "r"(a[3]), "r"(b[0]), "r"(b[1]));
}

__device__ __forceinline__ uint32_t smem_u32(const void* p) {
    return (uint32_t)__cvta_generic_to_shared(p);
}
__device__ __forceinline__ void cpasync16(uint32_t dst, const void* src) {
    asm volatile("cp.async.ca.shared.global [%0], [%1], 16;\n" ::"r"(dst), "l"(src));
}

// ---------------- merged weight repacks (one launch) -------------------------
// segment 0: qkv repack (EE*EE), segment 1: ff (EE*EE), segment 2: fr (BB*EE*EE)
__global__ void repack_all(const float* __restrict__ qw,
                           const float* __restrict__ kw,
                           const float* __restrict__ vw,
                           const float* __restrict__ ffw,
                           const float* __restrict__ frw) {
    int idx = blockIdx.x * blockDim.x + threadIdx.x;
    if (idx < EE * EE) {
        int e = idx / EE, n = idx % EE;
        int h = n >> 6, f = n & 63;
        int src = h * (EE * FFDIM) + e * FFDIM + f;
        g_wq[idx] = qw[src];
        g_wk[idx] = kw[src];
        g_wvhi[idx] = f2tf(vw[src]);
        g_wffhi[idx] = f2tf(ffw[n * EE + e]);
    }
    int idx2 = idx - EE * EE;
    if (idx2 >= 0 && idx2 < BB * EE * EE) g_frhi[idx2] = f2tf(frw[idx2]);
}

// ---------------- tiled transpose + tf32: [nb][M][K] -> [nb][K][M] -----------
__global__ __launch_bounds__(256) void transpose_tf(
    const float* __restrict__ in, uint32_t* __restrict__ ohi, int M, int K) {
    __shared__ float t[32][33];
    size_t bo = (size_t)blockIdx.z * M * K;
    in += bo; ohi += bo;
    int m0 = blockIdx.y * 32, k0 = blockIdx.x * 32;
    int tx = threadIdx.x & 31, ty = threadIdx.x >> 5;
#pragma unroll
    for (int i = ty; i < 32; i += 8) t[i][tx] = in[(size_t)(m0 + i) * K + k0 + tx];
    __syncthreads();
#pragma unroll
    for (int i = ty; i < 32; i += 8) {
        ohi[(size_t)(k0 + i) * M + m0 + tx] = f2tf(t[tx][i]);
    }
}

// ---------------- merged QKV GEMM ---------------------------------------------
// z=0: Q = x@wq (fp32 SIMT, FROZEN chain), z=1: K = x@wk (same),
// z=2: V = x@wv (1xTF32 tensor, 3-stage pipeline).
// V blocks fill the fp32 path's wave-2 scheduling bubble.
#define T1_STAGE_U32 (2 * 16 * 136)
__global__ __launch_bounds__(256, 2) void gemm_qkv(
    const float* __restrict__ A, const float* __restrict__ B0,
    const float* __restrict__ B1, float* __restrict__ C0, float* __restrict__ C1,
    const uint32_t* __restrict__ Ahi, const uint32_t* __restrict__ Bhi,
    float* __restrict__ CV, int M, int N, int K) {
    extern __shared__ uint32_t smp[];
    int m0 = blockIdx.y * 128, n0 = blockIdx.x * 128;
    int tid = threadIdx.x;

    if (blockIdx.z < 2) {
        // ----- fp32 SIMT path (bit-identical arithmetic; FROZEN) -----
        const float* Bm = blockIdx.z ? B1 : B0;
        float* C = blockIdx.z ? C1 : C0;
        float* Asf = (float*)smp;             // [2][16][132]
        float* Bsf = Asf + 2 * 16 * 132;      // [2][16][128]
        int ty = tid >> 4, tx = tid & 15;
        float acc[8][8] = {};
        int ar = tid >> 2;
        int ac4 = (tid & 3) * 4;
        int bk = tid >> 5;
        int bc4 = (tid & 31) * 4;

        uint32_t bd0[2], bd1[2];
        bd0[0] = smem_u32(&Bsf[0 * 2048 + bk * 128 + bc4]);
        bd0[1] = smem_u32(&Bsf[1 * 2048 + bk * 128 + bc4]);
        bd1[0] = smem_u32(&Bsf[0 * 2048 + (bk + 8) * 128 + bc4]);
        bd1[1] = smem_u32(&Bsf[1 * 2048 + (bk + 8) * 128 + bc4]);

        cpasync16(bd0[0], &Bm[(size_t)bk * N + n0 + bc4]);
        cpasync16(bd1[0], &Bm[(size_t)(bk + 8) * N + n0 + bc4]);
        asm volatile("cp.async.commit_group;\n");
        float4 ra0 = *(const float4*)&A[(size_t)(m0 + ar) * K + ac4];
        float4 ra1 = *(const float4*)&A[(size_t)(m0 + ar + 64) * K + ac4];
        Asf[(ac4 + 0) * 132 + ar] = ra0.x; Asf[(ac4 + 1) * 132 + ar] = ra0.y;
        Asf[(ac4 + 2) * 132 + ar] = ra0.z; Asf[(ac4 + 3) * 132 + ar] = ra0.w;
        Asf[(ac4 + 0) * 132 + ar + 64] = ra1.x; Asf[(ac4 + 1) * 132 + ar + 64] = ra1.y;
        Asf[(ac4 + 2) * 132 + ar + 64] = ra1.z; Asf[(ac4 + 3) * 132 + ar + 64] = ra1.w;
        asm volatile("cp.async.wait_group 0;\n");
        __syncthreads();

        int nt = K / 16;
        for (int t = 0; t < nt; t++) {
            int s = t & 1;
            if (t + 1 < nt) {
                int k0 = (t + 1) * 16;
                cpasync16(bd0[s ^ 1], &Bm[(size_t)(k0 + bk) * N + n0 + bc4]);
                cpasync16(bd1[s ^ 1], &Bm[(size_t)(k0 + bk + 8) * N + n0 + bc4]);
                asm volatile("cp.async.commit_group;\n");
                ra0 = *(const float4*)&A[(size_t)(m0 + ar) * K + k0 + ac4];
                ra1 = *(const float4*)&A[(size_t)(m0 + ar + 64) * K + k0 + ac4];
            }
            const float* Asc = Asf + s * 2112;
            const float* Bsc = Bsf + s * 2048;
#pragma unroll
            for (int k = 0; k < 16; k++) {
                float a[8], b[8];
                *(float4*)&a[0] = *(const float4*)&Asc[k * 132 + ty * 8];
                *(float4*)&a[4] = *(const float4*)&Asc[k * 132 + ty * 8 + 4];
                *(float4*)&b[0] = *(const float4*)&Bsc[k * 128 + tx * 8];
                *(float4*)&b[4] = *(const float4*)&Bsc[k * 128 + tx * 8 + 4];
#pragma unroll
                for (int i = 0; i < 8; i++)
#pragma unroll
                    for (int j = 0; j < 8; j++) acc[i][j] += a[i] * b[j];
            }
            if (t + 1 < nt) {
                int s2 = s ^ 1;
                float* Asn = Asf + s2 * 2112;
                Asn[(ac4 + 0) * 132 + ar] = ra0.x; Asn[(ac4 + 1) * 132 + ar] = ra0.y;
                Asn[(ac4 + 2) * 132 + ar] = ra0.z; Asn[(ac4 + 3) * 132 + ar] = ra0.w;
                Asn[(ac4 + 0) * 132 + ar + 64] = ra1.x; Asn[(ac4 + 1) * 132 + ar + 64] = ra1.y;
                Asn[(ac4 + 2) * 132 + ar + 64] = ra1.z; Asn[(ac4 + 3) * 132 + ar + 64] = ra1.w;
                asm volatile("cp.async.wait_group 0;\n");
            }
            __syncthreads();
        }
#pragma unroll
        for (int i = 0; i < 8; i++) {
            int m = m0 + ty * 8 + i;
            *(float4*)&C[(size_t)m * N + n0 + tx * 8] = *(float4*)&acc[i][0];
            *(float4*)&C[(size_t)m * N + n0 + tx * 8 + 4] = *(float4*)&acc[i][4];
        }
    } else {
        // ----- 1xTF32 tensor path (V projection) -----
        int lane = tid & 31, w = tid >> 5;
        int wm = w & 1, wn = w >> 1;
        int g = lane >> 2, tig = lane & 3;
        float acc[4][4][4] = {};
        int crow = tid >> 4;
        int col0 = (tid & 15) * 4;
        uint32_t sbase = smem_u32(smp);
        const uint32_t STAGE_B = T1_STAGE_U32 * 4;
        uint32_t offA = ((0 * 16 + crow) * 136 + col0) * 4;
        uint32_t offB = ((1 * 16 + crow) * 136 + col0) * 4;

        int nt = K / 16;
#pragma unroll
        for (int p = 0; p < 2; p++) {
            uint32_t dst = sbase + p * STAGE_B;
            const uint32_t* ga = &Ahi[(size_t)(p * 16 + crow) * M + m0 + col0];
            const uint32_t* gb = &Bhi[(size_t)(p * 16 + crow) * N + n0 + col0];
            cpasync16(dst + offA, ga);
            cpasync16(dst + offA + 256, ga + 64);
            cpasync16(dst + offB, gb);
            cpasync16(dst + offB + 256, gb + 64);
            asm volatile("cp.async.commit_group;\n");
        }
        asm volatile("cp.async.wait_group 1;\n");
        __syncthreads();

        int sl = 2, sc = 0;
        for (int t = 0; t < nt; t++) {
            if (t + 2 < nt) {
                uint32_t dst = sbase + sl * STAGE_B;
                const uint32_t* ga = &Ahi[(size_t)((t + 2) * 16 + crow) * M + m0 + col0];
                const uint32_t* gb = &Bhi[(size_t)((t + 2) * 16 + crow) * N + n0 + col0];
                cpasync16(dst + offA, ga);
                cpasync16(dst + offA + 256, ga + 64);
                cpasync16(dst + offB, gb);
                cpasync16(dst + offB + 256, gb + 64);
            }
            asm volatile("cp.async.commit_group;\n");
            const uint32_t* As = smp + sc * T1_STAGE_U32;
            const uint32_t* Bs = As + 16 * 136;
#pragma unroll
            for (int kk = 0; kk < 16; kk += 8) {
                uint32_t af[4][4];
#pragma unroll
                for (int mi = 0; mi < 4; mi++) {
                    int mb = wm * 64 + mi * 16 + g;
                    af[mi][0] = As[(kk + tig) * 136 + mb];
                    af[mi][1] = As[(kk + tig) * 136 + mb + 8];
                    af[mi][2] = As[(kk + tig + 4) * 136 + mb];
                    af[mi][3] = As[(kk + tig + 4) * 136 + mb + 8];
                }
#pragma unroll
                for (int ni = 0; ni < 4; ni++) {
                    int nb = wn * 32 + ni * 8 + g;
                    uint32_t bf[2];
                    bf[0] = Bs[(kk + tig) * 136 + nb];
                    bf[1] = Bs[(kk + tig + 4) * 136 + nb];
#pragma unroll
                    for (int mi = 0; mi < 4; mi++) mma8(acc[mi][ni], af[mi], bf);
                }
            }
            asm volatile("cp.async.wait_group 1;\n");
            __syncthreads();
            sl = (sl == 2) ? 0 : sl + 1;
            sc = (sc == 2) ? 0 : sc + 1;
        }
#pragma unroll
        for (int mi = 0; mi < 4; mi++) {
            int m = m0 + wm * 64 + mi * 16 + g;
#pragma unroll
            for (int ni = 0; ni < 4; ni++) {
                int n = n0 + wn * 32 + ni * 8 + tig * 2;
                *(float2*)&CV[(size_t)m * N + n] =
                    make_float2(acc[mi][ni][0], acc[mi][ni][1]);
                *(float2*)&CV[(size_t)(m + 8) * N + n] =
                    make_float2(acc[mi][ni][2], acc[mi][ni][3]);
            }
        }
    }
}

// ---------------- 1xTF32 tensor-core GEMM, 3-stage cp.async pipeline ---------
template <bool RELU>
__global__ __launch_bounds__(256, 2) void gemm_tf1(
    const uint32_t* __restrict__ Ahi, const uint32_t* __restrict__ Bhi,
    float* __restrict__ C, int M, int N, int K,
    long sA, long sB, long sC, const float* __restrict__ bias) {
    extern __shared__ uint32_t smp[];
    Ahi += (size_t)blockIdx.z * sA;
    Bhi += (size_t)blockIdx.z * sB;
    C += (size_t)blockIdx.z * sC;
    int m0 = blockIdx.y * 128, n0 = blockIdx.x * 128;
    int tid = threadIdx.x, lane = tid & 31, w = tid >> 5;
    int wm = w & 1, wn = w >> 1;
    int g = lane >> 2, tig = lane & 3;
    float acc[4][4][4] = {};

    int crow = tid >> 4;
    int col0 = (tid & 15) * 4;
    uint32_t sbase = smem_u32(smp);
    const uint32_t STAGE_B = T1_STAGE_U32 * 4;
    uint32_t offA = ((0 * 16 + crow) * 136 + col0) * 4;
    uint32_t offB = ((1 * 16 + crow) * 136 + col0) * 4;

    int nt = K / 16;
#pragma unroll
    for (int p = 0; p < 2; p++) {
        uint32_t dst = sbase + p * STAGE_B;
        const uint32_t* ga = &Ahi[(size_t)(p * 16 + crow) * M + m0 + col0];
        const uint32_t* gb = &Bhi[(size_t)(p * 16 + crow) * N + n0 + col0];
        cpasync16(dst + offA, ga);
        cpasync16(dst + offA + 256, ga + 64);
        cpasync16(dst + offB, gb);
        cpasync16(dst + offB + 256, gb + 64);
        asm volatile("cp.async.commit_group;\n");
    }
    asm volatile("cp.async.wait_group 1;\n");
    __syncthreads();

    int sl = 2, sc = 0;
    for (int t = 0; t < nt; t++) {
        if (t + 2 < nt) {
            uint32_t dst = sbase + sl * STAGE_B;
            const uint32_t* ga = &Ahi[(size_t)((t + 2) * 16 + crow) * M + m0 + col0];
            const uint32_t* gb = &Bhi[(size_t)((t + 2) * 16 + crow) * N + n0 + col0];
            cpasync16(dst + offA, ga);
            cpasync16(dst + offA + 256, ga + 64);
            cpasync16(dst + offB, gb);
            cpasync16(dst + offB + 256, gb + 64);
        }
        asm volatile("cp.async.commit_group;\n");
        const uint32_t* As = smp + sc * T1_STAGE_U32;
        const uint32_t* Bs = As + 16 * 136;
#pragma unroll
        for (int kk = 0; kk < 16; kk += 8) {
            uint32_t af[4][4];
#pragma unroll
            for (int mi = 0; mi < 4; mi++) {
                int mb = wm * 64 + mi * 16 + g;
                af[mi][0] = As[(kk + tig) * 136 + mb];
                af[mi][1] = As[(kk + tig) * 136 + mb + 8];
                af[mi][2] = As[(kk + tig + 4) * 136 + mb];
                af[mi][3] = As[(kk + tig + 4) * 136 + mb + 8];
            }
#pragma unroll
            for (int ni = 0; ni < 4; ni++) {
                int nb = wn * 32 + ni * 8 + g;
                uint32_t bf[2];
                bf[0] = Bs[(kk + tig) * 136 + nb];
                bf[1] = Bs[(kk + tig + 4) * 136 + nb];
#pragma unroll
                for (int mi = 0; mi < 4; mi++) mma8(acc[mi][ni], af[mi], bf);
            }
        }
        asm volatile("cp.async.wait_group 1;\n");
        __syncthreads();
        sl = (sl == 2) ? 0 : sl + 1;
        sc = (sc == 2) ? 0 : sc + 1;
    }
#pragma unroll
    for (int mi = 0; mi < 4; mi++) {
        int m = m0 + wm * 64 + mi * 16 + g;
#pragma unroll
        for (int ni = 0; ni < 4; ni++) {
            int n = n0 + wn * 32 + ni * 8 + tig * 2;
            float b0 = bias ? bias[n] : 0.0f;
            float b1 = bias ? bias[n + 1] : 0.0f;
            float v0 = acc[mi][ni][0] + b0, v1 = acc[mi][ni][1] + b1;
            float v2 = acc[mi][ni][2] + b0, v3 = acc[mi][ni][3] + b1;
            if (RELU) {
                v0 = fmaxf(v0, 0.0f); v1 = fmaxf(v1, 0.0f);
                v2 = fmaxf(v2, 0.0f); v3 = fmaxf(v3, 0.0f);
            }
            *(float2*)&C[(size_t)m * N + n] = make_float2(v0, v1);
            *(float2*)&C[(size_t)(m + 8) * N + n] = make_float2(v2, v3);
        }
    }
}

// ---------------- fused attention, BQ=128 BK=64, 2 blocks/SM (FROZEN) --------
struct __align__(16) AttnSmem {
    float qs[64][132];
    uint32_t Ps[128][68];
    uint32_t vhi[64][72];
    uint32_t vlo[64][72];
    float sm_m[128];
    float sm_l[128];
    float sm_sc[128];
};

__global__ __launch_bounds__(256, 2) void attn_fused() {
    extern __shared__ char smraw[];
    AttnSmem* S = (AttnSmem*)smraw;
    float(*ks)[68] = (float(*)[68])S->Ps;
    int bh = blockIdx.y;
    int b = bh / HH, h = bh % HH;
    int q0 = blockIdx.x * 128;
    const float* qp = g_q + (size_t)b * TT * EE + h * FFDIM;
    const float* kp = g_k + (size_t)b * TT * EE + h * FFDIM;
    const float* vp = g_v + (size_t)b * TT * EE + h * FFDIM;
    float* op = g_zm + (size_t)b * TT * EE + h * FFDIM;

    int tid = threadIdx.x;
    int ty = tid >> 4, tx = tid & 15;
    int lane = tid & 31, w = tid >> 5;
    int wm = w >> 1, wn = w & 1;
    int g = lane >> 2, tig = lane & 3;
    int ar = tid >> 2;
    int ac4 = (tid & 3) * 4;

#pragma unroll
    for (int c0 = 0; c0 < 64; c0 += 16) {
#pragma unroll
        for (int ri = 0; ri < 2; ri++) {
            int r = ar + ri * 64;
            const float4 va = *(const float4*)&qp[(size_t)(q0 + r) * EE + c0 + ac4];
            S->qs[c0 + ac4 + 0][r] = va.x;
            S->qs[c0 + ac4 + 1][r] = va.y;
            S->qs[c0 + ac4 + 2][r] = va.z;
            S->qs[c0 + ac4 + 3][r] = va.w;
        }
    }
    if (tid < 128) {
        S->sm_m[tid] = -INFINITY;
        S->sm_l[tid] = 0.0f;
    }
    float acc[2][4][4] = {};
    __syncthreads();

    for (int k0 = 0; k0 < TT; k0 += 64) {
#pragma unroll
        for (int c0 = 0; c0 < 64; c0 += 16) {
            const float4 vb = *(const float4*)&kp[(size_t)(k0 + ar) * EE + c0 + ac4];
            ks[c0 + ac4 + 0][ar] = vb.x;
            ks[c0 + ac4 + 1][ar] = vb.y;
            ks[c0 + ac4 + 2][ar] = vb.z;
            ks[c0 + ac4 + 3][ar] = vb.w;
        }
        {
            int vr = tid >> 2;
            int vc = (tid & 3) * 16;
#pragma unroll
            for (int j = 0; j < 4; j++) {
                const float4 v = *(const float4*)&vp[(size_t)(k0 + vr) * EE + vc + j * 4];
                uint4 t, l;
                t.x = f2tf(v.x); t.y = f2tf(v.y); t.z = f2tf(v.z); t.w = f2tf(v.w);
                l.x = f2tf(v.x - __uint_as_float(t.x));
                l.y = f2tf(v.y - __uint_as_float(t.y));
                l.z = f2tf(v.z - __uint_as_float(t.z));
                l.w = f2tf(v.w - __uint_as_float(t.w));
                *(uint4*)&S->vhi[vr][vc + j * 4] = t;
                *(uint4*)&S->vlo[vr][vc + j * 4] = l;
            }
        }
        __syncthreads();

        float s[8][4] = {};
#pragma unroll
        for (int f = 0; f < 64; f++) {
            float a[8], bv[4];
            *(float4*)&a[0] = *(const float4*)&S->qs[f][ty * 8];
            *(float4*)&a[4] = *(const float4*)&S->qs[f][ty * 8 + 4];
            *(float4*)&bv[0] = *(const float4*)&ks[f][tx * 4];
#pragma unroll
            for (int i = 0; i < 8; i++)
#pragma unroll
                for (int j = 0; j < 4; j++) s[i][j] += a[i] * bv[j];
        }
#pragma unroll
        for (int i = 0; i < 8; i++) {
            int qg = q0 + ty * 8 + i;
#pragma unroll
            for (int j = 0; j < 4; j++) {
                int kg = k0 + tx * 4 + j;
                float m = (kg > qg) ? (1.0f - 1.0e9f) : 1.0f;
                s[i][j] = s[i][j] * m * 0.125f;
            }
        }
        float tm[8];
#pragma unroll
        for (int i = 0; i < 8; i++) {
            float v = fmaxf(fmaxf(s[i][0], s[i][1]), fmaxf(s[i][2], s[i][3]));
#pragma unroll
            for (int o = 8; o > 0; o >>= 1) v = fmaxf(v, __shfl_xor_sync(0xffffffffu, v, o));
            tm[i] = v;
        }
        if (tx == 0) {
#pragma unroll
            for (int i = 0; i < 8; i++) {
                int row = ty * 8 + i;
                float mo = S->sm_m[row];
                float mn = fmaxf(mo, tm[i]);
                S->sm_sc[row] = __expf(mo - mn);
                S->sm_m[row] = mn;
            }
        }
        __syncthreads();

        unsigned hm = (lane & 16) ? 0xffff0000u : 0x0000ffffu;
#pragma unroll
        for (int i = 0; i < 8; i++) {
            int row = ty * 8 + i;
            float mn = S->sm_m[row];
            if (tm[i] - mn > -104.0f) {
                float p0 = __expf(s[i][0] - mn);
                float p1 = __expf(s[i][1] - mn);
                float p2 = __expf(s[i][2] - mn);
                float p3 = __expf(s[i][3] - mn);
                float rs = p0 + p1 + p2 + p3;
                *(uint4*)&S->Ps[row][tx * 4] =
                    make_uint4(f2tf(p0), f2tf(p1), f2tf(p2), f2tf(p3));
#pragma unroll
                for (int o = 8; o > 0; o >>= 1) rs += __shfl_xor_sync(hm, rs, o);
                if (tx == 0) S->sm_l[row] = S->sm_l[row] * S->sm_sc[row] + rs;
            } else {
                *(uint4*)&S->Ps[row][tx * 4] = make_uint4(0, 0, 0, 0);
            }
        }
        __syncthreads();

#pragma unroll
        for (int mi = 0; mi < 2; mi++) {
            int row = wm * 32 + mi * 16 + g;
            float s0 = S->sm_sc[row], s1 = S->sm_sc[row + 8];
#pragma unroll
            for (int ni = 0; ni < 4; ni++) {
                acc[mi][ni][0] *= s0; acc[mi][ni][1] *= s0;
                acc[mi][ni][2] *= s1; acc[mi][ni][3] *= s1;
            }
        }
#pragma unroll
        for (int kk = 0; kk < 64; kk += 8) {
            uint32_t af[2][4];
#pragma unroll
            for (int mi = 0; mi < 2; mi++) {
                int mb = wm * 32 + mi * 16 + g;
                af[mi][0] = S->Ps[mb][kk + tig];
                af[mi][1] = S->Ps[mb + 8][kk + tig];
                af[mi][2] = S->Ps[mb][kk + tig + 4];
                af[mi][3] = S->Ps[mb + 8][kk + tig + 4];
            }
#pragma unroll
            for (int ni = 0; ni < 4; ni++) {
                int nb = wn * 32 + ni * 8 + g;
                uint32_t bf[2], bfl[2];
                bf[0] = S->vhi[kk + tig][nb];
                bf[1] = S->vhi[kk + tig + 4][nb];
                bfl[0] = S->vlo[kk + tig][nb];
                bfl[1] = S->vlo[kk + tig + 4][nb];
#pragma unroll
                for (int mi = 0; mi < 2; mi++) {
                    mma8(acc[mi][ni], af[mi], bfl);
                    mma8(acc[mi][ni], af[mi], bf);
                }
            }
        }
        __syncthreads();
    }
#pragma unroll
    for (int mi = 0; mi < 2; mi++) {
        int row = wm * 32 + mi * 16 + g;
        float i0 = 1.0f / S->sm_l[row];
        float i1 = 1.0f / S->sm_l[row + 8];
        int m = q0 + row;
#pragma unroll
        for (int ni = 0; ni < 4; ni++) {
            int n = wn * 32 + ni * 8 + tig * 2;
            *(float2*)&op[(size_t)m * EE + n] =
                make_float2(acc[mi][ni][0] * i0, acc[mi][ni][1] * i0);
            *(float2*)&op[(size_t)(m + 8) * EE + n] =
                make_float2(acc[mi][ni][2] * i1, acc[mi][ni][3] * i1);
        }
    }
}

// ---------------- LayerNorm over whole [T,E] plane per batch -----------------
__global__ __launch_bounds__(256) void ln_reduce(const float* __restrict__ in1,
                                                 const float* __restrict__ in2) {
    int b = blockIdx.y;
    const float* p1 = in1 + (size_t)b * LN_N;
    const float* p2 = in2 + (size_t)b * LN_N;
    const int chunk = (int)(LN_N / 64);
    size_t base = (size_t)blockIdx.x * chunk;
    double s = 0.0, sq = 0.0;
    for (int i = threadIdx.x * 4; i < chunk; i += 256 * 4) {
        float4 a = *(const float4*)&p1[base + i];
        float4 c = *(const float4*)&p2[base + i];
        float x0 = a.x + c.x, x1 = a.y + c.y, x2 = a.z + c.z, x3 = a.w + c.w;
        s += (double)x0 + (double)x1 + (double)x2 + (double)x3;
        sq += (double)x0 * x0 + (double)x1 * x1 + (double)x2 * x2 + (double)x3 * x3;
    }
    __shared__ double sh[256], shq[256];
    int tid = threadIdx.x;
    sh[tid] = s;
    shq[tid] = sq;
    __syncthreads();
    for (int o = 128; o > 0; o >>= 1) {
        if (tid < o) {
            sh[tid] += sh[tid + o];
            shq[tid] += shq[tid + o];
        }
        __syncthreads();
    }
    if (tid == 0) {
        g_part[(b * 64 + blockIdx.x) * 2] = sh[0];
        g_part[(b * 64 + blockIdx.x) * 2 + 1] = shq[0];
    }
}

__global__ void ln_finalize() {
    int b = blockIdx.x;
    int tid = threadIdx.x;
    __shared__ double sh[64], shq[64];
    sh[tid] = g_part[(b * 64 + tid) * 2];
    shq[tid] = g_part[(b * 64 + tid) * 2 + 1];
    __syncthreads();
    for (int o = 32; o > 0; o >>= 1) {
        if (tid < o) {
            sh[tid] += sh[tid + o];
            shq[tid] += shq[tid + o];
        }
        __syncthreads();
    }
    if (tid == 0) {
        double n = (double)LN_N;
        double mean = sh[0] / n;
        double var = shq[0] / n - mean * mean;
        g_stats[b * 2] = (float)mean;
        g_stats[b * 2 + 1] = (float)(1.0 / sqrt(var + 1e-5));
    }
}

__global__ __launch_bounds__(256) void ln_norm(const float* __restrict__ in1,
                                               const float* __restrict__ in2,
                                               const float* __restrict__ w,
                                               const float* __restrict__ bia,
                                               float* __restrict__ out) {
    size_t i = ((size_t)blockIdx.x * blockDim.x + threadIdx.x) * 4;
    if (i >= (size_t)BB * LN_N) return;
    int b = (int)(i / LN_N);
    size_t te = i % LN_N;
    float mean = g_stats[b * 2];
    float rstd = g_stats[b * 2 + 1];
    float4 a = *(const float4*)&in1[i];
    float4 c = *(const float4*)&in2[i];
    float4 ww = *(const float4*)&w[te];
    float4 bb = *(const float4*)&bia[te];
    float4 o;
    o.x = (a.x + c.x - mean) * rstd * ww.x + bb.x;
    o.y = (a.y + c.y - mean) * rstd * ww.y + bb.y;
    o.z = (a.z + c.z - mean) * rstd * ww.z + bb.z;
    o.w = (a.w + c.w - mean) * rstd * ww.w + bb.w;
    *(float4*)&out[i] = o;
}

// ---------------- launch -----------------------------------------------------
extern "C" void kernel_launch(void* const* d_in, const int* in_sizes, int n_in,
                              void* d_out, int out_size) {
    const float* x = (const float*)d_in[0];
    const float* q_w = (const float*)d_in[1];
    const float* k_w = (const float*)d_in[2];
    const float* v_w = (const float*)d_in[3];
    const float* fr_w = (const float*)d_in[4];
    const float* ff_w = (const float*)d_in[5];
    const float* ff_b = (const float*)d_in[6];
    const float* ln1_w = (const float*)d_in[7];
    const float* ln1_b = (const float*)d_in[8];
    const float* ln2_w = (const float*)d_in[9];
    const float* ln2_b = (const float*)d_in[10];
    float* out = (float*)d_out;

    float *p_wq, *p_wk, *p_q, *p_k, *p_v, *p_zm, *p_zf, *p_z1, *p_z2;
    uint32_t *p_wvhi, *p_wffhi, *p_frhi, *p_athi;
    cudaGetSymbolAddress((void**)&p_wq, g_wq);
    cudaGetSymbolAddress((void**)&p_wk, g_wk);
    cudaGetSymbolAddress((void**)&p_q, g_q);
    cudaGetSymbolAddress((void**)&p_k, g_k);
    cudaGetSymbolAddress((void**)&p_v, g_v);
    cudaGetSymbolAddress((void**)&p_zm, g_zm);
    cudaGetSymbolAddress((void**)&p_zf, g_zf);
    cudaGetSymbolAddress((void**)&p_z1, g_z1);
    cudaGetSymbolAddress((void**)&p_z2, g_z2);
    cudaGetSymbolAddress((void**)&p_wvhi, g_wvhi);
    cudaGetSymbolAddress((void**)&p_wffhi, g_wffhi);
    cudaGetSymbolAddress((void**)&p_frhi, g_frhi);
    cudaGetSymbolAddress((void**)&p_athi, g_athi);

    const size_t SMP = 3 * T1_STAGE_U32 * sizeof(uint32_t);  // 52224 B
    const size_t SMA = sizeof(AttnSmem);
    cudaFuncSetAttribute(attn_fused, cudaFuncAttributeMaxDynamicSharedMemorySize, (int)SMA);
    cudaFuncSetAttribute(gemm_qkv, cudaFuncAttributeMaxDynamicSharedMemorySize, (int)SMP);
    cudaFuncSetAttribute(gemm_tf1<false>, cudaFuncAttributeMaxDynamicSharedMemorySize, (int)SMP);
    cudaFuncSetAttribute(gemm_tf1<true>, cudaFuncAttributeMaxDynamicSharedMemorySize, (int)SMP);

    // 1) merged weight repacks (qkv + ff + fr in one launch)
    int repack_total = EE * EE + BB * EE * EE;
    repack_all<<<(repack_total + 255) / 256, 256>>>(q_w, k_w, v_w, ff_w, fr_w);

    // 2) transpose x (feeds V path of merged kernel)
    dim3 gtx(EE / 32, (BB * TT) / 32, 1);
    transpose_tf<<<gtx, 256>>>(x, p_athi, BB * TT, EE);

    // 3) merged QKV: z=0,1 exact fp32 Q/K; z=2 tensor-core V fills the tail
    dim3 gqkv(EE / 128, (BB * TT) / 128, 3);
    gemm_qkv<<<gqkv, 256, SMP>>>(x, p_wq, p_wk, p_q, p_k,
                                 p_athi, p_wvhi, p_v, BB * TT, EE, EE);

    // 4) fused attention
    dim3 gat(TT / 128, BB * HH, 1);
    attn_fused<<<gat, 256, SMA>>>();

    // 5) zf[b] = zm[b] @ fr[b] (1xTF32, batched)
    dim3 gtz(EE / 32, TT / 32, BB);
    transpose_tf<<<gtz, 256>>>(p_zm, p_athi, TT, EE);
    dim3 gfr(EE / 128, TT / 128, BB);
    gemm_tf1<false><<<gfr, 256, SMP>>>(p_athi, p_frhi, p_zf,
                                       TT, EE, EE, (long)TT * EE, (long)EE * EE,
                                       (long)TT * EE, nullptr);

    // 6) LN1 over x + zf -> z1
    dim3 gred(64, BB, 1);
    ln_reduce<<<gred, 256>>>(x, p_zf);
    ln_finalize<<<BB, 64>>>();
    size_t total = (size_t)BB * LN_N;
    ln_norm<<<(unsigned)((total / 4 + 255) / 256), 256>>>(x, p_zf, ln1_w, ln1_b, p_z1);

    // 7) FFN: z2 = relu(z1 @ ff_w^T + ff_b) (1xTF32)
    transpose_tf<<<gtx, 256>>>(p_z1, p_athi, BB * TT, EE);
    dim3 gv(EE / 128, (BB * TT) / 128, 1);
    gemm_tf1<true><<<gv, 256, SMP>>>(p_athi, p_wffhi, p_z2,
                                     BB * TT, EE, EE, 0, 0, 0, ff_b);

    // 8) LN2 over z1 + z2 -> out
    ln_reduce<<<gred, 256>>>(p_z1, p_z2);
    ln_finalize<<<BB, 64>>>();
    ln_norm<<<(unsigned)((total / 4 + 255) / 256), 256>>>(p_z1, p_z2, ln2_w, ln2_b, out);
}